// round 2
// baseline (speedup 1.0000x reference)
#include <cuda_runtime.h>
#include <cuda_bf16.h>

// Problem dims
#define BB 1024
#define TT 60
#define VV 9
#define HH 512
#define LL 3
#define ZZ 128
#define BH (BB*HH)            // 524288
#define G4 (4*HH)             // 2048

// Device scratch (static allocation is the sanctioned path)
__device__ float g_emb[BB*HH];          // embed[scenario[b]]
__device__ float g_prev[BB*VV];         // prev_out
__device__ float g_embW0[BB*G4];        // emb @ Wih0[9:,:] + bih0 + bhh0
__device__ float g_h[2*LL*BH];          // ping-pong h per layer
__device__ float g_c[LL*BH];            // c per layer (in-place)
__device__ float g_trendh[BB*HH];
__device__ float g_trend[BB*TT*VV];     // [B, T*V]
__device__ float g_hidden[BB*HH];

// ---------------- fast activations ----------------
__device__ __forceinline__ float fsigmoid(float x) {
    return __fdividef(1.0f, 1.0f + __expf(-x));
}
__device__ __forceinline__ float ftanh(float x) {
    x = fminf(fmaxf(x, -15.0f), 15.0f);
    float e = __expf(2.0f * x);
    return (e - 1.0f) * __fdividef(1.0f, e + 1.0f);
}

// ---------------- generic fp32 GEMM ----------------
// C[M,N] = A[M,K] @ W[K,N] (+bias +bias2), tiles 64x64, BK=16, 256 thr, 4x4 microtile
#define A_PLAIN 0
#define A_ZCOND 1
#define EPI_PLAIN 0
#define EPI_LEAKY 1
#define EPI_SCATTER 2

template<int AMODE, int EPI>
__global__ __launch_bounds__(256)
void gemm_kernel(const float* __restrict__ A, int lda,
                 const float* __restrict__ Az, const float* __restrict__ Ae,
                 const float* __restrict__ W, int N, int K,
                 const float* __restrict__ bias, const float* __restrict__ bias2,
                 float* __restrict__ C0, float* __restrict__ C1)
{
    __shared__ float As[16][65];
    __shared__ float Ws[16][64];

    const int tid = threadIdx.x;
    const int tx = tid & 15, ty = tid >> 4;
    const int row0 = blockIdx.x * 64;
    const int col0 = blockIdx.y * 64;

    const int ar = tid >> 2;          // 0..63
    const int ak = (tid & 3) * 4;     // 0,4,8,12
    const int wk = tid >> 4;          // 0..15
    const int wn = (tid & 15) * 4;    // 0..60

    float acc[4][4];
    #pragma unroll
    for (int m = 0; m < 4; m++)
        #pragma unroll
        for (int n = 0; n < 4; n++) acc[m][n] = 0.0f;

    for (int k0 = 0; k0 < K; k0 += 16) {
        // A tile
        const int arow = row0 + ar;
        if (AMODE == A_ZCOND) {
            #pragma unroll
            for (int j = 0; j < 4; j++) {
                int kx = k0 + ak + j;
                float v = (kx < ZZ) ? Az[arow * ZZ + kx] : Ae[arow * HH + (kx - ZZ)];
                As[ak + j][ar] = v;
            }
        } else {
            float4 av = *reinterpret_cast<const float4*>(&A[arow * lda + k0 + ak]);
            As[ak + 0][ar] = av.x; As[ak + 1][ar] = av.y;
            As[ak + 2][ar] = av.z; As[ak + 3][ar] = av.w;
        }
        // W tile (guard for N=540 tail)
        {
            int wcol = col0 + wn;
            if (wcol + 3 < N) {
                float4 wv = *reinterpret_cast<const float4*>(&W[(k0 + wk) * N + wcol]);
                Ws[wk][wn + 0] = wv.x; Ws[wk][wn + 1] = wv.y;
                Ws[wk][wn + 2] = wv.z; Ws[wk][wn + 3] = wv.w;
            } else {
                #pragma unroll
                for (int j = 0; j < 4; j++)
                    Ws[wk][wn + j] = (wcol + j < N) ? W[(k0 + wk) * N + wcol + j] : 0.0f;
            }
        }
        __syncthreads();
        #pragma unroll
        for (int kk = 0; kk < 16; kk++) {
            float a[4];
            #pragma unroll
            for (int m = 0; m < 4; m++) a[m] = As[kk][ty * 4 + m];
            float4 wv = *reinterpret_cast<const float4*>(&Ws[kk][tx * 4]);
            float w[4] = {wv.x, wv.y, wv.z, wv.w};
            #pragma unroll
            for (int m = 0; m < 4; m++)
                #pragma unroll
                for (int n = 0; n < 4; n++) acc[m][n] += a[m] * w[n];
        }
        __syncthreads();
    }

    #pragma unroll
    for (int m = 0; m < 4; m++) {
        int row = row0 + ty * 4 + m;
        #pragma unroll
        for (int n = 0; n < 4; n++) {
            int col = col0 + tx * 4 + n;
            if (col >= N) continue;
            float v = acc[m][n];
            if (bias)  v += bias[col];
            if (bias2) v += bias2[col];
            if (EPI == EPI_LEAKY) v = (v > 0.0f) ? v : 0.2f * v;
            if (EPI == EPI_SCATTER) {
                // col in [0,3072): l*1024 + sel*512 + hh  -> h0/c0
                int l = col >> 10, rem = col & 1023, sel = rem >> 9, hh = rem & 511;
                float* dst = sel ? C1 : C0;
                dst[l * BH + row * HH + hh] = v;
            } else {
                C0[row * N + col] = v;
            }
        }
    }
}

// ---------------- fused LSTM gates + cell ----------------
// Block computes [64 rows] x [64 h-cols] for all 4 gates (cols g*512 + nh),
// then does the cell update in-register. c updated in place; h ping-ponged.
template<bool LAYER0>
__global__ __launch_bounds__(256)
void lstm_gate_kernel(const float* __restrict__ Xin, const float* __restrict__ Wih,
                      const float* __restrict__ Hin, const float* __restrict__ Whh,
                      const float* __restrict__ embW0,
                      const float* __restrict__ bih, const float* __restrict__ bhh,
                      const float* __restrict__ prev, const float* __restrict__ Wih0full,
                      float* __restrict__ Hout, float* __restrict__ C)
{
    __shared__ float As[16][65];       // 4160 B
    __shared__ float Ws[4][16][64];    // 16 KB

    const int tid = threadIdx.x;
    const int tx = tid & 15, ty = tid >> 4;
    const int row0 = blockIdx.x * 64;
    const int col0 = blockIdx.y * 64;   // h-space column

    const int ar = tid >> 2;
    const int ak = (tid & 3) * 4;
    const int wk = tid >> 4;
    const int wn = (tid & 15) * 4;

    float acc[4][4][4];  // [gate][m][n]
    #pragma unroll
    for (int g = 0; g < 4; g++)
        #pragma unroll
        for (int m = 0; m < 4; m++)
            #pragma unroll
            for (int n = 0; n < 4; n++) acc[g][m][n] = 0.0f;

    const int NSEG = LAYER0 ? 1 : 2;
    for (int seg = 0; seg < NSEG; seg++) {
        const float* Ap = LAYER0 ? Hin : (seg == 0 ? Xin : Hin);
        const float* Wp = LAYER0 ? Whh : (seg == 0 ? Wih : Whh);
        for (int k0 = 0; k0 < HH; k0 += 16) {
            float4 av = *reinterpret_cast<const float4*>(&Ap[(row0 + ar) * HH + k0 + ak]);
            As[ak + 0][ar] = av.x; As[ak + 1][ar] = av.y;
            As[ak + 2][ar] = av.z; As[ak + 3][ar] = av.w;
            #pragma unroll
            for (int g = 0; g < 4; g++) {
                float4 wv = *reinterpret_cast<const float4*>(
                    &Wp[(k0 + wk) * G4 + g * HH + col0 + wn]);
                Ws[g][wk][wn + 0] = wv.x; Ws[g][wk][wn + 1] = wv.y;
                Ws[g][wk][wn + 2] = wv.z; Ws[g][wk][wn + 3] = wv.w;
            }
            __syncthreads();
            #pragma unroll
            for (int kk = 0; kk < 16; kk++) {
                float a[4];
                #pragma unroll
                for (int m = 0; m < 4; m++) a[m] = As[kk][ty * 4 + m];
                #pragma unroll
                for (int g = 0; g < 4; g++) {
                    float4 wv = *reinterpret_cast<const float4*>(&Ws[g][kk][tx * 4]);
                    float w[4] = {wv.x, wv.y, wv.z, wv.w};
                    #pragma unroll
                    for (int m = 0; m < 4; m++)
                        #pragma unroll
                        for (int n = 0; n < 4; n++) acc[g][m][n] += a[m] * w[n];
                }
            }
            __syncthreads();
        }
    }

    if (LAYER0) {
        // prev_out (9 cols) @ Wih0[0:9,:] contribution, staged through smem.
        float* Asf = &As[0][0];  // 1040 floats >= 576
        for (int lin = tid; lin < 64 * VV; lin += 256) {
            int r = lin / VV, k = lin - VV * r;
            Asf[lin] = prev[(row0 + r) * VV + k];
        }
        for (int lin = tid; lin < 4 * VV * 16; lin += 256) {  // 576 float4 groups
            int g = lin / (VV * 16);
            int rem = lin - g * (VV * 16);
            int k = rem / 16, n4 = rem - 16 * k;
            float4 wv = *reinterpret_cast<const float4*>(
                &Wih0full[k * G4 + g * HH + col0 + n4 * 4]);
            *reinterpret_cast<float4*>(&Ws[g][k][n4 * 4]) = wv;
        }
        __syncthreads();
        #pragma unroll
        for (int m = 0; m < 4; m++) {
            #pragma unroll
            for (int k = 0; k < VV; k++) {
                float p = Asf[(ty * 4 + m) * VV + k];
                #pragma unroll
                for (int g = 0; g < 4; g++)
                    #pragma unroll
                    for (int n = 0; n < 4; n++)
                        acc[g][m][n] += p * Ws[g][k][tx * 4 + n];
            }
        }
    }

    // Cell update
    #pragma unroll
    for (int m = 0; m < 4; m++) {
        int row = row0 + ty * 4 + m;
        #pragma unroll
        for (int n = 0; n < 4; n++) {
            int nh = col0 + tx * 4 + n;
            int idx = row * HH + nh;
            float gi = acc[0][m][n], gf = acc[1][m][n];
            float gg = acc[2][m][n], go = acc[3][m][n];
            if (LAYER0) {
                const float* e = embW0 + row * G4 + nh;
                gi += e[0]; gf += e[HH]; gg += e[2 * HH]; go += e[3 * HH];
            } else {
                gi += bih[nh]          + bhh[nh];
                gf += bih[HH + nh]     + bhh[HH + nh];
                gg += bih[2 * HH + nh] + bhh[2 * HH + nh];
                go += bih[3 * HH + nh] + bhh[3 * HH + nh];
            }
            float c_old = C[idx];
            float i_s = fsigmoid(gi);
            float f_s = fsigmoid(gf);
            float g_t = ftanh(gg);
            float o_s = fsigmoid(go);
            float c_new = f_s * c_old + i_s * g_t;
            C[idx] = c_new;
            Hout[idx] = o_s * ftanh(c_new);
        }
    }
}

// ---------------- prep: gather emb, zero prev ----------------
__global__ void prep_kernel(const float* __restrict__ embed, const int* __restrict__ scen)
{
    int idx = blockIdx.x * blockDim.x + threadIdx.x;
    if (idx < BB * HH) {
        int b = idx >> 9, j = idx & (HH - 1);
        g_emb[idx] = embed[scen[b] * HH + j];
    }
    if (idx < BB * VV) g_prev[idx] = 0.0f;
}

// ---------------- out2 + trend add ----------------
__global__ void out2_kernel(const float* __restrict__ hidden, const float* __restrict__ W2,
                            const float* __restrict__ b2, const float* __restrict__ trend,
                            int t, float* __restrict__ out, float* __restrict__ prev)
{
    int b = blockIdx.x;
    int w = threadIdx.x >> 5;     // 0..8 (blockDim = 288)
    int lane = threadIdx.x & 31;
    const float* hrow = hidden + b * HH;
    float s = 0.0f;
    #pragma unroll
    for (int k = lane; k < HH; k += 32) s += hrow[k] * W2[k * VV + w];
    #pragma unroll
    for (int off = 16; off; off >>= 1) s += __shfl_down_sync(0xffffffffu, s, off);
    if (lane == 0) {
        float o = s + b2[w] + trend[b * (TT * VV) + t * VV + w];
        out[b * (TT * VV) + t * VV + w] = o;
        prev[b * VV + w] = o;
    }
}

extern "C" void kernel_launch(void* const* d_in, const int* in_sizes, int n_in,
                              void* d_out, int out_size)
{
    (void)in_sizes; (void)n_in; (void)out_size;
    const float* z      = (const float*)d_in[0];
    const int*   scen   = (const int*)  d_in[1];
    const float* embed  = (const float*)d_in[2];
    const float* fcW    = (const float*)d_in[3];
    const float* fcb    = (const float*)d_in[4];
    const float* Wih[LL], *Whh[LL], *bih[LL], *bhh[LL];
    for (int l = 0; l < LL; l++) {
        Wih[l] = (const float*)d_in[5 + 4 * l];
        Whh[l] = (const float*)d_in[6 + 4 * l];
        bih[l] = (const float*)d_in[7 + 4 * l];
        bhh[l] = (const float*)d_in[8 + 4 * l];
    }
    const float* out1_W = (const float*)d_in[17];
    const float* out1_b = (const float*)d_in[18];
    const float* out2_W = (const float*)d_in[19];
    const float* out2_b = (const float*)d_in[20];
    const float* tr1_W  = (const float*)d_in[21];
    const float* tr1_b  = (const float*)d_in[22];
    const float* tr2_W  = (const float*)d_in[23];
    const float* tr2_b  = (const float*)d_in[24];
    float* out = (float*)d_out;

    float *p_emb, *p_prev, *p_embW0, *p_h, *p_c, *p_trendh, *p_trend, *p_hidden;
    cudaGetSymbolAddress((void**)&p_emb,    g_emb);
    cudaGetSymbolAddress((void**)&p_prev,   g_prev);
    cudaGetSymbolAddress((void**)&p_embW0,  g_embW0);
    cudaGetSymbolAddress((void**)&p_h,      g_h);
    cudaGetSymbolAddress((void**)&p_c,      g_c);
    cudaGetSymbolAddress((void**)&p_trendh, g_trendh);
    cudaGetSymbolAddress((void**)&p_trend,  g_trend);
    cudaGetSymbolAddress((void**)&p_hidden, g_hidden);

    // prep: gather emb, zero prev
    prep_kernel<<<(BB * HH + 255) / 256, 256>>>(embed, scen);

    // h0/c0 init: [B,640] @ [640,3072] -> scatter into g_h[buf0], g_c
    gemm_kernel<A_ZCOND, EPI_SCATTER><<<dim3(16, 48), 256>>>(
        nullptr, 0, z, p_emb, fcW, 3072, ZZ + HH, fcb, nullptr, p_h, p_c);

    // trend hidden: leaky([B,640] @ [640,512])
    gemm_kernel<A_ZCOND, EPI_LEAKY><<<dim3(16, 8), 256>>>(
        nullptr, 0, z, p_emb, tr1_W, HH, ZZ + HH, tr1_b, nullptr, p_trendh, nullptr);

    // trend: [B,512] @ [512,540]
    gemm_kernel<A_PLAIN, EPI_PLAIN><<<dim3(16, 9), 256>>>(
        p_trendh, HH, nullptr, nullptr, tr2_W, TT * VV, HH, tr2_b, nullptr, p_trend, nullptr);

    // embW0: emb @ Wih0[9:,:] + bih0 + bhh0 (time-invariant layer-0 input term)
    gemm_kernel<A_PLAIN, EPI_PLAIN><<<dim3(16, 32), 256>>>(
        p_emb, HH, nullptr, nullptr, Wih[0] + VV * G4, G4, HH, bih[0], bhh[0], p_embW0, nullptr);

    for (int t = 0; t < TT; t++) {
        int p = t & 1;
        float* hi0 = p_h + (p * LL + 0) * BH;
        float* hi1 = p_h + (p * LL + 1) * BH;
        float* hi2 = p_h + (p * LL + 2) * BH;
        float* ho0 = p_h + ((1 - p) * LL + 0) * BH;
        float* ho1 = p_h + ((1 - p) * LL + 1) * BH;
        float* ho2 = p_h + ((1 - p) * LL + 2) * BH;

        lstm_gate_kernel<true><<<dim3(16, 8), 256>>>(
            nullptr, nullptr, hi0, Whh[0], p_embW0, nullptr, nullptr,
            p_prev, Wih[0], ho0, p_c + 0 * BH);
        lstm_gate_kernel<false><<<dim3(16, 8), 256>>>(
            ho0, Wih[1], hi1, Whh[1], nullptr, bih[1], bhh[1],
            nullptr, nullptr, ho1, p_c + 1 * BH);
        lstm_gate_kernel<false><<<dim3(16, 8), 256>>>(
            ho1, Wih[2], hi2, Whh[2], nullptr, bih[2], bhh[2],
            nullptr, nullptr, ho2, p_c + 2 * BH);

        gemm_kernel<A_PLAIN, EPI_LEAKY><<<dim3(16, 8), 256>>>(
            ho2, HH, nullptr, nullptr, out1_W, HH, HH, out1_b, nullptr, p_hidden, nullptr);

        out2_kernel<<<BB, 288>>>(p_hidden, out2_W, out2_b, p_trend, t, out, p_prev);
    }
}

// round 3
// speedup vs baseline: 1.0035x; 1.0035x over previous
#include <cuda_runtime.h>
#include <cuda_bf16.h>

// Problem dims
#define BB 1024
#define TT 60
#define VV 9
#define HH 512
#define LL 3
#define ZZ 128
#define BH (BB*HH)            // 524288
#define G4 (4*HH)             // 2048

// Device scratch (static allocation is the sanctioned path)
__device__ float g_emb[BB*HH];          // embed[scenario[b]]
__device__ float g_prev[BB*VV];         // prev_out
__device__ float g_embW0[BB*G4];        // emb @ Wih0[9:,:] + bih0 + bhh0
__device__ float g_h[2*LL*BH];          // ping-pong h per layer
__device__ float g_c[LL*BH];            // c per layer (in-place)
__device__ float g_trendh[BB*HH];
__device__ float g_trend[BB*TT*VV];     // [B, T*V]
__device__ float g_hidden[BB*HH];

// ---------------- fast activations ----------------
__device__ __forceinline__ float fsigmoid(float x) {
    return __fdividef(1.0f, 1.0f + __expf(-x));
}
__device__ __forceinline__ float ftanh(float x) {
    x = fminf(fmaxf(x, -15.0f), 15.0f);
    float e = __expf(2.0f * x);
    return (e - 1.0f) * __fdividef(1.0f, e + 1.0f);
}

// ---------------- generic fp32 GEMM ----------------
// C[M,N] = A[M,K] @ W[K,N] (+bias +bias2), tiles 64x64, BK=16, 256 thr, 4x4 microtile
#define A_PLAIN 0
#define A_ZCOND 1
#define EPI_PLAIN 0
#define EPI_LEAKY 1
#define EPI_SCATTER 2

template<int AMODE, int EPI>
__global__ __launch_bounds__(256)
void gemm_kernel(const float* __restrict__ A, int lda,
                 const float* __restrict__ Az, const float* __restrict__ Ae,
                 const float* __restrict__ W, int N, int K,
                 const float* __restrict__ bias, const float* __restrict__ bias2,
                 float* __restrict__ C0, float* __restrict__ C1)
{
    __shared__ float As[16][65];
    __shared__ float Ws[16][64];

    const int tid = threadIdx.x;
    const int tx = tid & 15, ty = tid >> 4;
    const int row0 = blockIdx.x * 64;
    const int col0 = blockIdx.y * 64;

    const int ar = tid >> 2;          // 0..63
    const int ak = (tid & 3) * 4;     // 0,4,8,12
    const int wk = tid >> 4;          // 0..15
    const int wn = (tid & 15) * 4;    // 0..60

    float acc[4][4];
    #pragma unroll
    for (int m = 0; m < 4; m++)
        #pragma unroll
        for (int n = 0; n < 4; n++) acc[m][n] = 0.0f;

    for (int k0 = 0; k0 < K; k0 += 16) {
        // A tile
        const int arow = row0 + ar;
        if (AMODE == A_ZCOND) {
            #pragma unroll
            for (int j = 0; j < 4; j++) {
                int kx = k0 + ak + j;
                float v = (kx < ZZ) ? Az[arow * ZZ + kx] : Ae[arow * HH + (kx - ZZ)];
                As[ak + j][ar] = v;
            }
        } else {
            float4 av = *reinterpret_cast<const float4*>(&A[arow * lda + k0 + ak]);
            As[ak + 0][ar] = av.x; As[ak + 1][ar] = av.y;
            As[ak + 2][ar] = av.z; As[ak + 3][ar] = av.w;
        }
        // W tile (guard for N=540 tail)
        {
            int wcol = col0 + wn;
            if (wcol + 3 < N) {
                float4 wv = *reinterpret_cast<const float4*>(&W[(k0 + wk) * N + wcol]);
                Ws[wk][wn + 0] = wv.x; Ws[wk][wn + 1] = wv.y;
                Ws[wk][wn + 2] = wv.z; Ws[wk][wn + 3] = wv.w;
            } else {
                #pragma unroll
                for (int j = 0; j < 4; j++)
                    Ws[wk][wn + j] = (wcol + j < N) ? W[(k0 + wk) * N + wcol + j] : 0.0f;
            }
        }
        __syncthreads();
        #pragma unroll
        for (int kk = 0; kk < 16; kk++) {
            float a[4];
            #pragma unroll
            for (int m = 0; m < 4; m++) a[m] = As[kk][ty * 4 + m];
            float4 wv = *reinterpret_cast<const float4*>(&Ws[kk][tx * 4]);
            float w[4] = {wv.x, wv.y, wv.z, wv.w};
            #pragma unroll
            for (int m = 0; m < 4; m++)
                #pragma unroll
                for (int n = 0; n < 4; n++) acc[m][n] += a[m] * w[n];
        }
        __syncthreads();
    }

    #pragma unroll
    for (int m = 0; m < 4; m++) {
        int row = row0 + ty * 4 + m;
        #pragma unroll
        for (int n = 0; n < 4; n++) {
            int col = col0 + tx * 4 + n;
            if (col >= N) continue;
            float v = acc[m][n];
            if (bias)  v += bias[col];
            if (bias2) v += bias2[col];
            if (EPI == EPI_LEAKY) v = (v > 0.0f) ? v : 0.2f * v;
            if (EPI == EPI_SCATTER) {
                // col in [0,3072): l*1024 + sel*512 + hh  -> h0/c0
                int l = col >> 10, rem = col & 1023, sel = rem >> 9, hh = rem & 511;
                float* dst = sel ? C1 : C0;
                dst[l * BH + row * HH + hh] = v;
            } else {
                C0[row * N + col] = v;
            }
        }
    }
}

// ---------------- fused LSTM gates + cell ----------------
// Block computes [64 rows] x [64 h-cols] for all 4 gates (cols g*512 + nh),
// then does the cell update in-register. c updated in place; h ping-ponged.
template<bool LAYER0>
__global__ __launch_bounds__(256)
void lstm_gate_kernel(const float* __restrict__ Xin, const float* __restrict__ Wih,
                      const float* __restrict__ Hin, const float* __restrict__ Whh,
                      const float* __restrict__ embW0,
                      const float* __restrict__ bih, const float* __restrict__ bhh,
                      const float* __restrict__ prev, const float* __restrict__ Wih0full,
                      float* __restrict__ Hout, float* __restrict__ C)
{
    __shared__ float As[16][65];       // 4160 B
    __shared__ float Ws[4][16][64];    // 16 KB

    const int tid = threadIdx.x;
    const int tx = tid & 15, ty = tid >> 4;
    const int row0 = blockIdx.x * 64;
    const int col0 = blockIdx.y * 64;   // h-space column

    const int ar = tid >> 2;
    const int ak = (tid & 3) * 4;
    const int wk = tid >> 4;
    const int wn = (tid & 15) * 4;

    float acc[4][4][4];  // [gate][m][n]
    #pragma unroll
    for (int g = 0; g < 4; g++)
        #pragma unroll
        for (int m = 0; m < 4; m++)
            #pragma unroll
            for (int n = 0; n < 4; n++) acc[g][m][n] = 0.0f;

    const int NSEG = LAYER0 ? 1 : 2;
    for (int seg = 0; seg < NSEG; seg++) {
        const float* Ap = LAYER0 ? Hin : (seg == 0 ? Xin : Hin);
        const float* Wp = LAYER0 ? Whh : (seg == 0 ? Wih : Whh);
        for (int k0 = 0; k0 < HH; k0 += 16) {
            float4 av = *reinterpret_cast<const float4*>(&Ap[(row0 + ar) * HH + k0 + ak]);
            As[ak + 0][ar] = av.x; As[ak + 1][ar] = av.y;
            As[ak + 2][ar] = av.z; As[ak + 3][ar] = av.w;
            #pragma unroll
            for (int g = 0; g < 4; g++) {
                float4 wv = *reinterpret_cast<const float4*>(
                    &Wp[(k0 + wk) * G4 + g * HH + col0 + wn]);
                Ws[g][wk][wn + 0] = wv.x; Ws[g][wk][wn + 1] = wv.y;
                Ws[g][wk][wn + 2] = wv.z; Ws[g][wk][wn + 3] = wv.w;
            }
            __syncthreads();
            #pragma unroll
            for (int kk = 0; kk < 16; kk++) {
                float a[4];
                #pragma unroll
                for (int m = 0; m < 4; m++) a[m] = As[kk][ty * 4 + m];
                #pragma unroll
                for (int g = 0; g < 4; g++) {
                    float4 wv = *reinterpret_cast<const float4*>(&Ws[g][kk][tx * 4]);
                    float w[4] = {wv.x, wv.y, wv.z, wv.w};
                    #pragma unroll
                    for (int m = 0; m < 4; m++)
                        #pragma unroll
                        for (int n = 0; n < 4; n++) acc[g][m][n] += a[m] * w[n];
                }
            }
            __syncthreads();
        }
    }

    if (LAYER0) {
        // prev_out (9 cols) @ Wih0[0:9,:] contribution, staged through smem.
        float* Asf = &As[0][0];  // 1040 floats >= 576
        for (int lin = tid; lin < 64 * VV; lin += 256) {
            int r = lin / VV, k = lin - VV * r;
            Asf[lin] = prev[(row0 + r) * VV + k];
        }
        for (int lin = tid; lin < 4 * VV * 16; lin += 256) {  // 576 float4 groups
            int g = lin / (VV * 16);
            int rem = lin - g * (VV * 16);
            int k = rem / 16, n4 = rem - 16 * k;
            float4 wv = *reinterpret_cast<const float4*>(
                &Wih0full[k * G4 + g * HH + col0 + n4 * 4]);
            *reinterpret_cast<float4*>(&Ws[g][k][n4 * 4]) = wv;
        }
        __syncthreads();
        #pragma unroll
        for (int m = 0; m < 4; m++) {
            #pragma unroll
            for (int k = 0; k < VV; k++) {
                float p = Asf[(ty * 4 + m) * VV + k];
                #pragma unroll
                for (int g = 0; g < 4; g++)
                    #pragma unroll
                    for (int n = 0; n < 4; n++)
                        acc[g][m][n] += p * Ws[g][k][tx * 4 + n];
            }
        }
    }

    // Cell update
    #pragma unroll
    for (int m = 0; m < 4; m++) {
        int row = row0 + ty * 4 + m;
        #pragma unroll
        for (int n = 0; n < 4; n++) {
            int nh = col0 + tx * 4 + n;
            int idx = row * HH + nh;
            float gi = acc[0][m][n], gf = acc[1][m][n];
            float gg = acc[2][m][n], go = acc[3][m][n];
            if (LAYER0) {
                const float* e = embW0 + row * G4 + nh;
                gi += e[0]; gf += e[HH]; gg += e[2 * HH]; go += e[3 * HH];
            } else {
                gi += bih[nh]          + bhh[nh];
                gf += bih[HH + nh]     + bhh[HH + nh];
                gg += bih[2 * HH + nh] + bhh[2 * HH + nh];
                go += bih[3 * HH + nh] + bhh[3 * HH + nh];
            }
            float c_old = C[idx];
            float i_s = fsigmoid(gi);
            float f_s = fsigmoid(gf);
            float g_t = ftanh(gg);
            float o_s = fsigmoid(go);
            float c_new = f_s * c_old + i_s * g_t;
            C[idx] = c_new;
            Hout[idx] = o_s * ftanh(c_new);
        }
    }
}

// ---------------- prep: gather emb, zero prev ----------------
__global__ void prep_kernel(const float* __restrict__ embed, const int* __restrict__ scen)
{
    int idx = blockIdx.x * blockDim.x + threadIdx.x;
    if (idx < BB * HH) {
        int b = idx >> 9, j = idx & (HH - 1);
        g_emb[idx] = embed[scen[b] * HH + j];
    }
    if (idx < BB * VV) g_prev[idx] = 0.0f;
}

// ---------------- out2 + trend add ----------------
__global__ void out2_kernel(const float* __restrict__ hidden, const float* __restrict__ W2,
                            const float* __restrict__ b2, const float* __restrict__ trend,
                            int t, float* __restrict__ out, float* __restrict__ prev)
{
    int b = blockIdx.x;
    int w = threadIdx.x >> 5;     // 0..8 (blockDim = 288)
    int lane = threadIdx.x & 31;
    const float* hrow = hidden + b * HH;
    float s = 0.0f;
    #pragma unroll
    for (int k = lane; k < HH; k += 32) s += hrow[k] * W2[k * VV + w];
    #pragma unroll
    for (int off = 16; off; off >>= 1) s += __shfl_down_sync(0xffffffffu, s, off);
    if (lane == 0) {
        float o = s + b2[w] + trend[b * (TT * VV) + t * VV + w];
        out[b * (TT * VV) + t * VV + w] = o;
        prev[b * VV + w] = o;
    }
}

extern "C" void kernel_launch(void* const* d_in, const int* in_sizes, int n_in,
                              void* d_out, int out_size)
{
    (void)in_sizes; (void)n_in; (void)out_size;
    const float* z      = (const float*)d_in[0];
    const int*   scen   = (const int*)  d_in[1];
    const float* embed  = (const float*)d_in[2];
    const float* fcW    = (const float*)d_in[3];
    const float* fcb    = (const float*)d_in[4];
    const float* Wih[LL], *Whh[LL], *bih[LL], *bhh[LL];
    for (int l = 0; l < LL; l++) {
        Wih[l] = (const float*)d_in[5 + 4 * l];
        Whh[l] = (const float*)d_in[6 + 4 * l];
        bih[l] = (const float*)d_in[7 + 4 * l];
        bhh[l] = (const float*)d_in[8 + 4 * l];
    }
    const float* out1_W = (const float*)d_in[17];
    const float* out1_b = (const float*)d_in[18];
    const float* out2_W = (const float*)d_in[19];
    const float* out2_b = (const float*)d_in[20];
    const float* tr1_W  = (const float*)d_in[21];
    const float* tr1_b  = (const float*)d_in[22];
    const float* tr2_W  = (const float*)d_in[23];
    const float* tr2_b  = (const float*)d_in[24];
    float* out = (float*)d_out;

    float *p_emb, *p_prev, *p_embW0, *p_h, *p_c, *p_trendh, *p_trend, *p_hidden;
    cudaGetSymbolAddress((void**)&p_emb,    g_emb);
    cudaGetSymbolAddress((void**)&p_prev,   g_prev);
    cudaGetSymbolAddress((void**)&p_embW0,  g_embW0);
    cudaGetSymbolAddress((void**)&p_h,      g_h);
    cudaGetSymbolAddress((void**)&p_c,      g_c);
    cudaGetSymbolAddress((void**)&p_trendh, g_trendh);
    cudaGetSymbolAddress((void**)&p_trend,  g_trend);
    cudaGetSymbolAddress((void**)&p_hidden, g_hidden);

    // prep: gather emb, zero prev
    prep_kernel<<<(BB * HH + 255) / 256, 256>>>(embed, scen);

    // h0/c0 init: [B,640] @ [640,3072] -> scatter into g_h[buf0], g_c
    gemm_kernel<A_ZCOND, EPI_SCATTER><<<dim3(16, 48), 256>>>(
        nullptr, 0, z, p_emb, fcW, 3072, ZZ + HH, fcb, nullptr, p_h, p_c);

    // trend hidden: leaky([B,640] @ [640,512])
    gemm_kernel<A_ZCOND, EPI_LEAKY><<<dim3(16, 8), 256>>>(
        nullptr, 0, z, p_emb, tr1_W, HH, ZZ + HH, tr1_b, nullptr, p_trendh, nullptr);

    // trend: [B,512] @ [512,540]
    gemm_kernel<A_PLAIN, EPI_PLAIN><<<dim3(16, 9), 256>>>(
        p_trendh, HH, nullptr, nullptr, tr2_W, TT * VV, HH, tr2_b, nullptr, p_trend, nullptr);

    // embW0: emb @ Wih0[9:,:] + bih0 + bhh0 (time-invariant layer-0 input term)
    gemm_kernel<A_PLAIN, EPI_PLAIN><<<dim3(16, 32), 256>>>(
        p_emb, HH, nullptr, nullptr, Wih[0] + VV * G4, G4, HH, bih[0], bhh[0], p_embW0, nullptr);

    for (int t = 0; t < TT; t++) {
        int p = t & 1;
        float* hi0 = p_h + (p * LL + 0) * BH;
        float* hi1 = p_h + (p * LL + 1) * BH;
        float* hi2 = p_h + (p * LL + 2) * BH;
        float* ho0 = p_h + ((1 - p) * LL + 0) * BH;
        float* ho1 = p_h + ((1 - p) * LL + 1) * BH;
        float* ho2 = p_h + ((1 - p) * LL + 2) * BH;

        lstm_gate_kernel<true><<<dim3(16, 8), 256>>>(
            nullptr, nullptr, hi0, Whh[0], p_embW0, nullptr, nullptr,
            p_prev, Wih[0], ho0, p_c + 0 * BH);
        lstm_gate_kernel<false><<<dim3(16, 8), 256>>>(
            ho0, Wih[1], hi1, Whh[1], nullptr, bih[1], bhh[1],
            nullptr, nullptr, ho1, p_c + 1 * BH);
        lstm_gate_kernel<false><<<dim3(16, 8), 256>>>(
            ho1, Wih[2], hi2, Whh[2], nullptr, bih[2], bhh[2],
            nullptr, nullptr, ho2, p_c + 2 * BH);

        gemm_kernel<A_PLAIN, EPI_LEAKY><<<dim3(16, 8), 256>>>(
            ho2, HH, nullptr, nullptr, out1_W, HH, HH, out1_b, nullptr, p_hidden, nullptr);

        out2_kernel<<<BB, 288>>>(p_hidden, out2_W, out2_b, p_trend, t, out, p_prev);
    }
}

// round 7
// speedup vs baseline: 1.5044x; 1.4992x over previous
#include <cuda_runtime.h>
#include <cuda_bf16.h>
#include <cstdint>
typedef __nv_bfloat16 bf16;

#define BB 1024
#define TT 60
#define VV 9
#define HH 512
#define LL 3
#define ZZ 128
#define ZH 640
#define G4 2048
#define BH (BB*HH)

// scratch
__device__ float g_c[LL*BH];
__device__ bf16  g_hhi[LL*BH];
__device__ bf16  g_hlo[LL*BH];
__device__ bf16  g_prevh[BB*64];
__device__ bf16  g_prevl[BB*64];
__device__ bf16  g_zchi[BB*ZH];
__device__ bf16  g_zclo[BB*ZH];
__device__ float g_embW0[BB*G4];
__device__ float g_bias[LL*G4];
__device__ float g_hidden[BB*HH];
__device__ float g_trendh[BB*HH];
__device__ float g_trend[BB*TT*VV];
// transposed split weights [Nperm, Kpad]
__device__ bf16 g_fcW_h[3072*ZH], g_fcW_l[3072*ZH];
__device__ bf16 g_tr1_h[HH*ZH],  g_tr1_l[HH*ZH];
__device__ bf16 g_w0b_h[G4*HH],  g_w0b_l[G4*HH];
__device__ bf16 g_w0t_h[G4*64],  g_w0t_l[G4*64];
__device__ bf16 g_whh_h[LL*G4*HH], g_whh_l[LL*G4*HH];
__device__ bf16 g_wih_h[2*G4*HH],  g_wih_l[2*G4*HH];
__device__ bf16 g_o1_h[HH*HH],   g_o1_l[HH*HH];

__device__ __forceinline__ float fsigmoid(float x){ return __fdividef(1.0f,1.0f+__expf(-x)); }
__device__ __forceinline__ float ftanh(float x){
    x = fminf(fmaxf(x,-15.0f),15.0f);
    float e = __expf(2.0f*x);
    return (e-1.0f)*__fdividef(1.0f,e+1.0f);
}
__device__ __forceinline__ uint32_t smem_u32(const void* p){
    uint32_t r;
    asm("{ .reg .u64 t; cvta.to.shared.u64 t, %1; cvt.u32.u64 %0, t; }" : "=r"(r) : "l"(p));
    return r;
}
__device__ __forceinline__ void cp16(uint32_t s, const bf16* g){
    asm volatile("cp.async.cg.shared.global [%0], [%1], 16;" :: "r"(s), "l"(g) : "memory");
}
__device__ __forceinline__ void ldsm4(uint32_t* r, uint32_t a){
    asm volatile("ldmatrix.sync.aligned.m8n8.x4.shared.b16 {%0,%1,%2,%3}, [%4];"
        : "=r"(r[0]),"=r"(r[1]),"=r"(r[2]),"=r"(r[3]) : "r"(a));
}
__device__ __forceinline__ void mma16816(float* d, const uint32_t* a, uint32_t b0, uint32_t b1){
    asm volatile("mma.sync.aligned.m16n8k16.row.col.f32.bf16.bf16.f32 "
        "{%0,%1,%2,%3}, {%4,%5,%6,%7}, {%8,%9}, {%0,%1,%2,%3};"
        : "+f"(d[0]),"+f"(d[1]),"+f"(d[2]),"+f"(d[3])
        : "r"(a[0]),"r"(a[1]),"r"(a[2]),"r"(a[3]), "r"(b0),"r"(b1));
}

// ---- HMMA GEMM: CTA tile 128x128, BK=32, 3-term bf16 split, up to 2 K-segments ----
// EPI: 0 store(+bias opt), 1 bias+leaky, 2 init-scatter(bias), 3 fused LSTM cell
// smem: A0@0 A1@10240 B0@20480 B1@30720 (128 rows x 40 bf16, 80B rows), out fp32 @40960
#define OUT_OFF 40960
#define SMEM_TOTAL (40960 + 128*132*4)

template<int EPI>
__global__ void __launch_bounds__(256)
gemm_mma(const bf16* __restrict__ Ah0, const bf16* __restrict__ Al0, int lda0, int k0len,
         const bf16* __restrict__ Bh0, const bf16* __restrict__ Bl0,
         const bf16* __restrict__ Ah1, const bf16* __restrict__ Al1, int lda1, int k1len,
         const bf16* __restrict__ Bh1, const bf16* __restrict__ Bl1,
         int nseg, float* __restrict__ C, int ldc, const float* __restrict__ bias,
         const float* __restrict__ embAdd, int layer)
{
    extern __shared__ __align__(128) uint8_t smem[];
    float* outs = (float*)(smem + OUT_OFF);
    const uint32_t sb = smem_u32(smem);
    const int tid = threadIdx.x, wid = tid >> 5, lane = tid & 31;
    const int m0 = blockIdx.x * 128, n0 = blockIdx.y * 128;

    const int kb0 = k0len >> 5;
    const int nch0 = 3 * kb0;
    const int kb1 = (nseg > 1) ? (k1len >> 5) : 0;
    const int total = nch0 + 3 * kb1;

    float acc[4][4][4];
    #pragma unroll
    for (int mt = 0; mt < 4; mt++)
        #pragma unroll
        for (int nt = 0; nt < 4; nt++)
            #pragma unroll
            for (int i = 0; i < 4; i++) acc[mt][nt][i] = 0.0f;

    const int warpM = (wid & 1) * 64, warpN = (wid >> 1) * 32;
    const uint32_t aoff = (uint32_t)((lane & 15)*80 + (lane >> 4)*16);
    const uint32_t boff = (uint32_t)((lane & 7)*80 + ((lane >> 3) & 1)*16 + (lane >> 4)*640);

    // chunk c -> stage s load
    auto issue = [&](int c, int s){
        int cc = c; const bf16 *Ap, *Bp; int lda, klen, koff;
        if (cc < nch0) {
            const int term = cc / kb0; koff = (cc - term*kb0) << 5;
            Ap = (term == 2) ? Al0 : Ah0; Bp = (term == 1) ? Bl0 : Bh0;
            lda = lda0; klen = k0len;
        } else {
            cc -= nch0;
            const int term = cc / kb1; koff = (cc - term*kb1) << 5;
            Ap = (term == 2) ? Al1 : Ah1; Bp = (term == 1) ? Bl1 : Bh1;
            lda = lda1; klen = k1len;
        }
        const uint32_t sA = sb + s*10240;
        const uint32_t sB = sb + 20480 + s*10240;
        #pragma unroll
        for (int i = 0; i < 2; i++) {
            const int li = tid + i*256;       // 0..511
            const int r = li >> 2, c16 = li & 3;
            cp16(sA + r*80 + c16*16, Ap + (m0 + r)*lda + koff + c16*8);
            cp16(sB + r*80 + c16*16, Bp + (n0 + r)*klen + koff + c16*8);
        }
        asm volatile("cp.async.commit_group;" ::: "memory");
    };
    auto compute = [&](int s){
        const uint32_t sA = sb + s*10240 + warpM*80;
        const uint32_t sB = sb + 20480 + s*10240 + warpN*80;
        #pragma unroll
        for (int ks = 0; ks < 2; ks++) {
            uint32_t af[4][4], bfr[2][4];
            #pragma unroll
            for (int mt = 0; mt < 4; mt++) ldsm4(af[mt], sA + mt*1280 + ks*32 + aoff);
            #pragma unroll
            for (int np = 0; np < 2; np++) ldsm4(bfr[np], sB + np*1280 + ks*32 + boff);
            #pragma unroll
            for (int mt = 0; mt < 4; mt++)
                #pragma unroll
                for (int nt = 0; nt < 4; nt++)
                    mma16816(acc[mt][nt], af[mt], bfr[nt>>1][(nt&1)*2], bfr[nt>>1][(nt&1)*2+1]);
        }
    };

    issue(0, 0);
    for (int c = 0; c < total; c++) {
        if (c + 1 < total) {
            issue(c + 1, (c + 1) & 1);
            asm volatile("cp.async.wait_group 1;" ::: "memory");
        } else {
            asm volatile("cp.async.wait_group 0;" ::: "memory");
        }
        __syncthreads();
        compute(c & 1);
        __syncthreads();
    }

    // dump accs to smem [128][132]
    #pragma unroll
    for (int mt = 0; mt < 4; mt++)
        #pragma unroll
        for (int nt = 0; nt < 4; nt++) {
            const int r = warpM + mt*16 + (lane >> 2);
            const int cN = warpN + nt*8 + (lane & 3)*2;
            *reinterpret_cast<float2*>(&outs[r*132 + cN]) =
                make_float2(acc[mt][nt][0], acc[mt][nt][1]);
            *reinterpret_cast<float2*>(&outs[(r+8)*132 + cN]) =
                make_float2(acc[mt][nt][2], acc[mt][nt][3]);
        }
    __syncthreads();

    if (EPI == 3) {
        const int q = tid & 31, rl0 = tid >> 5;
        #pragma unroll 4
        for (int i = 0; i < 16; i++) {
            const int rloc = rl0 + 8*i;
            const int row = m0 + rloc;
            float4 g4 = *reinterpret_cast<const float4*>(&outs[rloc*132 + 4*q]);
            float4 bb = *reinterpret_cast<const float4*>(&bias[n0 + 4*q]);
            float gi = g4.x + bb.x, gf = g4.y + bb.y, gg = g4.z + bb.z, go = g4.w + bb.w;
            if (embAdd) {
                float4 e = *reinterpret_cast<const float4*>(&embAdd[row*G4 + n0 + 4*q]);
                gi += e.x; gf += e.y; gg += e.z; go += e.w;
            }
            const int nh = (n0 >> 2) + q;
            const int ci = layer*BH + row*HH + nh;
            const float cn = fsigmoid(gf)*g_c[ci] + fsigmoid(gi)*ftanh(gg);
            g_c[ci] = cn;
            const float h = fsigmoid(go)*ftanh(cn);
            const bf16 hh = __float2bfloat16(h);
            g_hhi[ci] = hh;
            g_hlo[ci] = __float2bfloat16(h - __bfloat162float(hh));
        }
    } else {
        #pragma unroll 4
        for (int i = 0; i < 64; i++) {
            const int idx = tid + i*256;
            const int rloc = idx >> 7, col = idx & 127;
            const int row = m0 + rloc, cg = n0 + col;
            float v = outs[rloc*132 + col];
            if (EPI == 0) {
                if (bias) v += bias[cg];
                C[row*ldc + cg] = v;
            } else if (EPI == 1) {
                v += bias[cg];
                v = (v > 0.0f) ? v : 0.2f*v;
                C[row*ldc + cg] = v;
            } else {
                v += bias[cg];
                const int l = cg >> 10, rem = cg & 1023, sel = rem >> 9, hh2 = rem & 511;
                const int di = l*BH + row*HH + hh2;
                if (sel) g_c[di] = v;
                else {
                    const bf16 h16 = __float2bfloat16(v);
                    g_hhi[di] = h16;
                    g_hlo[di] = __float2bfloat16(v - __bfloat162float(h16));
                }
            }
        }
    }
}

// ---- transpose + split (+optional gate-interleave perm, zero-pad K) ----
template<int PERM>
__global__ void convsplit(const float* __restrict__ W, int K, int Kpad, int N,
                          bf16* __restrict__ Th, bf16* __restrict__ Tl)
{
    __shared__ float tile[32][33];
    const int k0 = blockIdx.x*32, n0 = blockIdx.y*32;
    const int tx = threadIdx.x, ty = threadIdx.y;
    for (int i = ty; i < 32; i += 8) {
        const int k = k0+i, n = n0+tx;
        tile[i][tx] = (k < K && n < N) ? W[k*N + n] : 0.0f;
    }
    __syncthreads();
    for (int i = ty; i < 32; i += 8) {
        const int n = n0+i, k = k0+tx;
        if (n < N && k < Kpad) {
            const float v = tile[tx][i];
            const int np = PERM ? ((n & 511)*4 + (n >> 9)) : n;
            const bf16 h = __float2bfloat16(v);
            Th[np*Kpad + k] = h;
            Tl[np*Kpad + k] = __float2bfloat16(v - __bfloat162float(h));
        }
    }
}

// ---- prep: z_cond split, prev zero, permuted bias sums ----
__global__ void prep_kernel(const float* __restrict__ z, const int* __restrict__ scen,
                            const float* __restrict__ embed,
                            const float* b0a, const float* b0b,
                            const float* b1a, const float* b1b,
                            const float* b2a, const float* b2b)
{
    const int idx = blockIdx.x*blockDim.x + threadIdx.x;
    if (idx < BB*ZH) {
        const int b = idx / ZH, j = idx - b*ZH;
        const float v = (j < ZZ) ? z[b*ZZ + j] : embed[scen[b]*HH + (j - ZZ)];
        const bf16 h = __float2bfloat16(v);
        g_zchi[idx] = h;
        g_zclo[idx] = __float2bfloat16(v - __bfloat162float(h));
    }
    if (idx < BB*64) { g_prevh[idx] = __float2bfloat16(0.0f); g_prevl[idx] = __float2bfloat16(0.0f); }
    if (idx < LL*G4) {
        const int l = idx >> 11, n = idx & 2047;
        const float s = (l == 0) ? b0a[n]+b0b[n] : (l == 1) ? b1a[n]+b1b[n] : b2a[n]+b2b[n];
        const int np = (n & 511)*4 + (n >> 9);
        g_bias[l*G4 + np] = s;
    }
}

// ---- one-time fp32 GEMM (trend2, N=540) ----
__global__ void __launch_bounds__(256)
gemm32_kernel(const float* __restrict__ A, const float* __restrict__ W,
              int N, int K, const float* __restrict__ bias, float* __restrict__ C)
{
    __shared__ float As[16][65];
    __shared__ float Ws[16][64];
    const int tid = threadIdx.x, tx = tid & 15, ty = tid >> 4;
    const int row0 = blockIdx.x*64, col0 = blockIdx.y*64;
    const int ar = tid >> 2, ak = (tid & 3)*4, wk = tid >> 4, wn = (tid & 15)*4;
    float acc[4][4];
    #pragma unroll
    for (int m = 0; m < 4; m++) { acc[m][0]=acc[m][1]=acc[m][2]=acc[m][3]=0.0f; }
    for (int k0 = 0; k0 < K; k0 += 16) {
        float4 av = *reinterpret_cast<const float4*>(&A[(row0+ar)*K + k0 + ak]);
        As[ak+0][ar]=av.x; As[ak+1][ar]=av.y; As[ak+2][ar]=av.z; As[ak+3][ar]=av.w;
        const int wcol = col0 + wn;
        #pragma unroll
        for (int j = 0; j < 4; j++)
            Ws[wk][wn+j] = (wcol+j < N) ? W[(k0+wk)*N + wcol + j] : 0.0f;
        __syncthreads();
        #pragma unroll
        for (int kk = 0; kk < 16; kk++) {
            float a[4];
            #pragma unroll
            for (int m = 0; m < 4; m++) a[m] = As[kk][ty*4+m];
            #pragma unroll
            for (int m = 0; m < 4; m++)
                #pragma unroll
                for (int n = 0; n < 4; n++) acc[m][n] += a[m]*Ws[kk][tx*4+n];
        }
        __syncthreads();
    }
    #pragma unroll
    for (int m = 0; m < 4; m++) {
        const int row = row0 + ty*4 + m;
        #pragma unroll
        for (int n = 0; n < 4; n++) {
            const int col = col0 + tx*4 + n;
            if (col < N) C[row*N + col] = acc[m][n] + bias[col];
        }
    }
}

// ---- out2 + trend add + prev split ----
__global__ void out2_kernel(const float* __restrict__ W2, const float* __restrict__ b2,
                            int t, float* __restrict__ out)
{
    const int b = blockIdx.x;
    const int w = threadIdx.x >> 5, lane = threadIdx.x & 31;
    const float* hrow = g_hidden + b*HH;
    float s = 0.0f;
    #pragma unroll
    for (int k = lane; k < HH; k += 32) s += hrow[k]*W2[k*VV + w];
    #pragma unroll
    for (int off = 16; off; off >>= 1) s += __shfl_down_sync(0xffffffffu, s, off);
    if (lane == 0) {
        const float o = s + b2[w] + g_trend[b*(TT*VV) + t*VV + w];
        out[b*(TT*VV) + t*VV + w] = o;
        const bf16 h = __float2bfloat16(o);
        g_prevh[b*64 + w] = h;
        g_prevl[b*64 + w] = __float2bfloat16(o - __bfloat162float(h));
    }
}

extern "C" void kernel_launch(void* const* d_in, const int* in_sizes, int n_in,
                              void* d_out, int out_size)
{
    (void)in_sizes; (void)n_in; (void)out_size;
    const float* z     = (const float*)d_in[0];
    const int*   scen  = (const int*)  d_in[1];
    const float* embed = (const float*)d_in[2];
    const float* fcW   = (const float*)d_in[3];
    const float* fcb   = (const float*)d_in[4];
    const float* Wih[LL], *Whh[LL], *bih[LL], *bhh[LL];
    for (int l = 0; l < LL; l++) {
        Wih[l] = (const float*)d_in[5+4*l];  Whh[l] = (const float*)d_in[6+4*l];
        bih[l] = (const float*)d_in[7+4*l];  bhh[l] = (const float*)d_in[8+4*l];
    }
    const float* out1_W = (const float*)d_in[17];
    const float* out1_b = (const float*)d_in[18];
    const float* out2_W = (const float*)d_in[19];
    const float* out2_b = (const float*)d_in[20];
    const float* tr1_W  = (const float*)d_in[21];
    const float* tr1_b  = (const float*)d_in[22];
    const float* tr2_W  = (const float*)d_in[23];
    const float* tr2_b  = (const float*)d_in[24];
    float* out = (float*)d_out;

    cudaFuncSetAttribute(gemm_mma<0>, cudaFuncAttributeMaxDynamicSharedMemorySize, SMEM_TOTAL);
    cudaFuncSetAttribute(gemm_mma<1>, cudaFuncAttributeMaxDynamicSharedMemorySize, SMEM_TOTAL);
    cudaFuncSetAttribute(gemm_mma<2>, cudaFuncAttributeMaxDynamicSharedMemorySize, SMEM_TOTAL);
    cudaFuncSetAttribute(gemm_mma<3>, cudaFuncAttributeMaxDynamicSharedMemorySize, SMEM_TOTAL);

    bf16 *p_zchi,*p_zclo,*p_hhi,*p_hlo,*p_prevh,*p_prevl;
    bf16 *p_fcWh,*p_fcWl,*p_tr1h,*p_tr1l,*p_w0bh,*p_w0bl,*p_w0th,*p_w0tl;
    bf16 *p_whhh,*p_whhl,*p_wihh,*p_wihl,*p_o1h,*p_o1l;
    float *p_embW0,*p_bias,*p_hidden,*p_trendh,*p_trend;
    cudaGetSymbolAddress((void**)&p_zchi, g_zchi);   cudaGetSymbolAddress((void**)&p_zclo, g_zclo);
    cudaGetSymbolAddress((void**)&p_hhi,  g_hhi);    cudaGetSymbolAddress((void**)&p_hlo,  g_hlo);
    cudaGetSymbolAddress((void**)&p_prevh,g_prevh);  cudaGetSymbolAddress((void**)&p_prevl,g_prevl);
    cudaGetSymbolAddress((void**)&p_fcWh, g_fcW_h);  cudaGetSymbolAddress((void**)&p_fcWl, g_fcW_l);
    cudaGetSymbolAddress((void**)&p_tr1h, g_tr1_h);  cudaGetSymbolAddress((void**)&p_tr1l, g_tr1_l);
    cudaGetSymbolAddress((void**)&p_w0bh, g_w0b_h);  cudaGetSymbolAddress((void**)&p_w0bl, g_w0b_l);
    cudaGetSymbolAddress((void**)&p_w0th, g_w0t_h);  cudaGetSymbolAddress((void**)&p_w0tl, g_w0t_l);
    cudaGetSymbolAddress((void**)&p_whhh, g_whh_h);  cudaGetSymbolAddress((void**)&p_whhl, g_whh_l);
    cudaGetSymbolAddress((void**)&p_wihh, g_wih_h);  cudaGetSymbolAddress((void**)&p_wihl, g_wih_l);
    cudaGetSymbolAddress((void**)&p_o1h,  g_o1_h);   cudaGetSymbolAddress((void**)&p_o1l,  g_o1_l);
    cudaGetSymbolAddress((void**)&p_embW0,g_embW0);  cudaGetSymbolAddress((void**)&p_bias, g_bias);
    cudaGetSymbolAddress((void**)&p_hidden,g_hidden);
    cudaGetSymbolAddress((void**)&p_trendh,g_trendh); cudaGetSymbolAddress((void**)&p_trend, g_trend);

    const dim3 cblk(32, 8);
    convsplit<0><<<dim3(20,96), cblk>>>(fcW, ZH, ZH, 3072, p_fcWh, p_fcWl);
    convsplit<0><<<dim3(20,16), cblk>>>(tr1_W, ZH, ZH, HH, p_tr1h, p_tr1l);
    convsplit<1><<<dim3(16,64), cblk>>>(Wih[0] + VV*G4, HH, HH, G4, p_w0bh, p_w0bl);
    convsplit<1><<<dim3(2,64),  cblk>>>(Wih[0], VV, 64, G4, p_w0th, p_w0tl);
    for (int l = 0; l < LL; l++)
        convsplit<1><<<dim3(16,64), cblk>>>(Whh[l], HH, HH, G4, p_whhh + l*G4*HH, p_whhl + l*G4*HH);
    for (int l = 1; l < LL; l++)
        convsplit<1><<<dim3(16,64), cblk>>>(Wih[l], HH, HH, G4, p_wihh + (l-1)*G4*HH, p_wihl + (l-1)*G4*HH);
    convsplit<0><<<dim3(16,16), cblk>>>(out1_W, HH, HH, HH, p_o1h, p_o1l);

    prep_kernel<<<(BB*ZH + 255)/256, 256>>>(z, scen, embed,
        bih[0], bhh[0], bih[1], bhh[1], bih[2], bhh[2]);

    // h0/c0 init scatter (N=3072)
    gemm_mma<2><<<dim3(8,24), 256, SMEM_TOTAL>>>(
        p_zchi, p_zclo, ZH, ZH, p_fcWh, p_fcWl,
        nullptr, nullptr, 0, 0, nullptr, nullptr, 1, nullptr, 0, fcb, nullptr, 0);
    // trend hidden (leaky, N=512)
    gemm_mma<1><<<dim3(8,4), 256, SMEM_TOTAL>>>(
        p_zchi, p_zclo, ZH, ZH, p_tr1h, p_tr1l,
        nullptr, nullptr, 0, 0, nullptr, nullptr, 1, p_trendh, HH, tr1_b, nullptr, 0);
    // trend2 (fp32, one-time)
    gemm32_kernel<<<dim3(16,9), 256>>>(p_trendh, tr2_W, TT*VV, HH, tr2_b, p_trend);
    // embW0 = emb @ Wih0[9:,:]  (permuted cols, N=2048)
    gemm_mma<0><<<dim3(8,16), 256, SMEM_TOTAL>>>(
        p_zchi + ZZ, p_zclo + ZZ, ZH, HH, p_w0bh, p_w0bl,
        nullptr, nullptr, 0, 0, nullptr, nullptr, 1, p_embW0, G4, nullptr, nullptr, 0);

    for (int t = 0; t < TT; t++) {
        // L0: h0@Whh0 + prev@W0top, fused cell
        gemm_mma<3><<<dim3(8,16), 256, SMEM_TOTAL>>>(
            p_hhi, p_hlo, HH, HH, p_whhh, p_whhl,
            p_prevh, p_prevl, 64, 64, p_w0th, p_w0tl,
            2, nullptr, 0, p_bias, p_embW0, 0);
        // L1: h0@Wih1 + h1@Whh1, fused cell
        gemm_mma<3><<<dim3(8,16), 256, SMEM_TOTAL>>>(
            p_hhi, p_hlo, HH, HH, p_wihh, p_wihl,
            p_hhi + BH, p_hlo + BH, HH, HH, p_whhh + G4*HH, p_whhl + G4*HH,
            2, nullptr, 0, p_bias + G4, nullptr, 1);
        // L2
        gemm_mma<3><<<dim3(8,16), 256, SMEM_TOTAL>>>(
            p_hhi + BH, p_hlo + BH, HH, HH, p_wihh + G4*HH, p_wihl + G4*HH,
            p_hhi + 2*BH, p_hlo + 2*BH, HH, HH, p_whhh + 2*G4*HH, p_whhl + 2*G4*HH,
            2, nullptr, 0, p_bias + 2*G4, nullptr, 2);
        // out1 (leaky, N=512)
        gemm_mma<1><<<dim3(8,4), 256, SMEM_TOTAL>>>(
            p_hhi + 2*BH, p_hlo + 2*BH, HH, HH, p_o1h, p_o1l,
            nullptr, nullptr, 0, 0, nullptr, nullptr, 1, p_hidden, HH, out1_b, nullptr, 0);
        // out2 + trend + prev
        out2_kernel<<<BB, 288>>>(out2_W, out2_b, t, out);
    }
}

// round 11
// speedup vs baseline: 1.5491x; 1.0297x over previous
#include <cuda_runtime.h>
#include <cuda_bf16.h>
#include <cstdint>
typedef __nv_bfloat16 bf16;

#define BB 1024
#define TT 60
#define VV 9
#define HH 512
#define LL 3
#define ZZ 128
#define ZH 640
#define G4 2048
#define BH (BB*HH)

// scratch
__device__ float g_c[LL*BH];
__device__ bf16  g_hhi[LL*BH];
__device__ bf16  g_hlo[LL*BH];
__device__ bf16  g_prevh[BB*64];
__device__ bf16  g_prevl[BB*64];
__device__ bf16  g_zchi[BB*ZH];
__device__ bf16  g_zclo[BB*ZH];
__device__ float g_embW0[BB*G4];
__device__ float g_bias[LL*G4];
__device__ float g_hidden[BB*HH];
__device__ float g_trendh[BB*HH];
__device__ float g_trend[BB*TT*VV];
// transposed split weights [Nperm, Kpad]
__device__ bf16 g_fcW_h[3072*ZH], g_fcW_l[3072*ZH];
__device__ bf16 g_tr1_h[HH*ZH],  g_tr1_l[HH*ZH];
__device__ bf16 g_w0b_h[G4*HH],  g_w0b_l[G4*HH];
__device__ bf16 g_w0t_h[G4*64],  g_w0t_l[G4*64];
__device__ bf16 g_whh_h[LL*G4*HH], g_whh_l[LL*G4*HH];
__device__ bf16 g_wih_h[2*G4*HH],  g_wih_l[2*G4*HH];
__device__ bf16 g_o1_h[HH*HH],   g_o1_l[HH*HH];

__device__ __forceinline__ float fsigmoid(float x){ return __fdividef(1.0f,1.0f+__expf(-x)); }
__device__ __forceinline__ float ftanh(float x){
    x = fminf(fmaxf(x,-15.0f),15.0f);
    float e = __expf(2.0f*x);
    return (e-1.0f)*__fdividef(1.0f,e+1.0f);
}
__device__ __forceinline__ uint32_t smem_u32(const void* p){
    uint32_t r;
    asm("{ .reg .u64 t; cvta.to.shared.u64 t, %1; cvt.u32.u64 %0, t; }" : "=r"(r) : "l"(p));
    return r;
}
__device__ __forceinline__ void cp16(uint32_t s, const bf16* g){
    asm volatile("cp.async.cg.shared.global [%0], [%1], 16;" :: "r"(s), "l"(g) : "memory");
}
__device__ __forceinline__ void ldsm4(uint32_t* r, uint32_t a){
    asm volatile("ldmatrix.sync.aligned.m8n8.x4.shared.b16 {%0,%1,%2,%3}, [%4];"
        : "=r"(r[0]),"=r"(r[1]),"=r"(r[2]),"=r"(r[3]) : "r"(a));
}
__device__ __forceinline__ void mma16816(float* d, const uint32_t* a, uint32_t b0, uint32_t b1){
    asm volatile("mma.sync.aligned.m16n8k16.row.col.f32.bf16.bf16.f32 "
        "{%0,%1,%2,%3}, {%4,%5,%6,%7}, {%8,%9}, {%0,%1,%2,%3};"
        : "+f"(d[0]),"+f"(d[1]),"+f"(d[2]),"+f"(d[3])
        : "r"(a[0]),"r"(a[1]),"r"(a[2]),"r"(a[3]), "r"(b0),"r"(b1));
}

// ---- HMMA GEMM v2.1: CTA 128x128, 512 thr (16 warps, 32x32 warp tile), BK=64,
// 3-stage cp.async, 1 barrier/chunk, fragment-direct epilogue.
// EPI: 0 store(+bias opt), 1 bias+leaky, 2 init-scatter(bias), 3 fused LSTM cell
#define STAGE_B 36864           // A(128x144B) + B(128x144B)
#define SMEM_TOTAL (3*STAGE_B)  // 110592

template<int EPI>
__global__ void __launch_bounds__(512)
gemm_mma(const bf16* __restrict__ Ah0, const bf16* __restrict__ Al0, int lda0, int k0len,
         const bf16* __restrict__ Bh0, const bf16* __restrict__ Bl0,
         const bf16* __restrict__ Ah1, const bf16* __restrict__ Al1, int lda1, int k1len,
         const bf16* __restrict__ Bh1, const bf16* __restrict__ Bl1,
         int nseg, float* __restrict__ C, int ldc, const float* __restrict__ bias,
         const float* __restrict__ embAdd, int layer)
{
    extern __shared__ __align__(128) uint8_t smem[];
    const uint32_t sb = smem_u32(smem);
    const int tid = threadIdx.x, wid = tid >> 5, lane = tid & 31;
    const int m0 = blockIdx.x * 128, n0 = blockIdx.y * 128;

    const int kb0 = k0len >> 6;
    const int nch0 = 3 * kb0;
    const int kb1 = (nseg > 1) ? (k1len >> 6) : 0;
    const int total = nch0 + 3 * kb1;

    float acc[2][4][4];
    #pragma unroll
    for (int mt = 0; mt < 2; mt++)
        #pragma unroll
        for (int nt = 0; nt < 4; nt++)
            #pragma unroll
            for (int i = 0; i < 4; i++) acc[mt][nt][i] = 0.0f;

    const int warpM = (wid & 3) * 32, warpN = (wid >> 2) * 32;
    const uint32_t aoff = (uint32_t)((lane & 15)*144 + (lane >> 4)*16);
    // lane-group stride for B = 8 rows * 144B = 1152 (16-row stride belongs to np, not lanes)
    const uint32_t boff = (uint32_t)((lane & 7)*144 + ((lane >> 3) & 1)*16 + (lane >> 4)*1152);

    auto issue = [&](int c, int s){
        int cc = c; const bf16 *Ap, *Bp; int lda, klen, koff;
        if (cc < nch0) {
            const int term = cc / kb0; koff = (cc - term*kb0) << 6;
            Ap = (term == 2) ? Al0 : Ah0; Bp = (term == 1) ? Bl0 : Bh0;
            lda = lda0; klen = k0len;
        } else {
            cc -= nch0;
            const int term = cc / kb1; koff = (cc - term*kb1) << 6;
            Ap = (term == 2) ? Al1 : Ah1; Bp = (term == 1) ? Bl1 : Bh1;
            lda = lda1; klen = k1len;
        }
        const uint32_t sA = sb + s*STAGE_B;
        const uint32_t sB = sA + 18432;
        #pragma unroll
        for (int i = 0; i < 2; i++) {
            const int li = tid + i*512;      // 0..1023
            const int r = li >> 3, c16 = li & 7;
            cp16(sA + r*144 + c16*16, Ap + (m0 + r)*lda + koff + c16*8);
            cp16(sB + r*144 + c16*16, Bp + (n0 + r)*klen + koff + c16*8);
        }
        asm volatile("cp.async.commit_group;" ::: "memory");
    };
    auto compute = [&](int s){
        const uint32_t sA = sb + s*STAGE_B + warpM*144;
        const uint32_t sB = sb + s*STAGE_B + 18432 + warpN*144;
        #pragma unroll
        for (int ks = 0; ks < 4; ks++) {
            uint32_t af[2][4], bfr[2][4];
            #pragma unroll
            for (int mt = 0; mt < 2; mt++) ldsm4(af[mt], sA + mt*2304 + ks*32 + aoff);
            #pragma unroll
            for (int np = 0; np < 2; np++) ldsm4(bfr[np], sB + np*2304 + ks*32 + boff);
            #pragma unroll
            for (int mt = 0; mt < 2; mt++)
                #pragma unroll
                for (int nt = 0; nt < 4; nt++)
                    mma16816(acc[mt][nt], af[mt], bfr[nt>>1][(nt&1)*2], bfr[nt>>1][(nt&1)*2+1]);
        }
    };

    issue(0, 0);
    issue(1, 1);
    for (int c = 0; c < total; c++) {
        if (c + 1 < total) asm volatile("cp.async.wait_group 1;" ::: "memory");
        else               asm volatile("cp.async.wait_group 0;" ::: "memory");
        __syncthreads();
        compute(c % 3);
        if (c + 2 < total) issue(c + 2, (c + 2) % 3);
    }

    if (EPI == 3) {
        #pragma unroll
        for (int mt = 0; mt < 2; mt++) {
            const int row = m0 + warpM + mt*16 + (lane >> 2) + ((lane & 1) ? 8 : 0);
            #pragma unroll
            for (int nt = 0; nt < 4; nt++) {
                const float d0 = acc[mt][nt][0], d1 = acc[mt][nt][1];
                const float d2 = acc[mt][nt][2], d3 = acc[mt][nt][3];
                const float e0 = __shfl_xor_sync(0xffffffffu, d0, 1);
                const float e1 = __shfl_xor_sync(0xffffffffu, d1, 1);
                const float e2 = __shfl_xor_sync(0xffffffffu, d2, 1);
                const float e3 = __shfl_xor_sync(0xffffffffu, d3, 1);
                float q0, q1, q2, q3;
                if (lane & 1) { q0 = e2; q1 = e3; q2 = d2; q3 = d3; }
                else          { q0 = d0; q1 = d1; q2 = e0; q3 = e1; }
                const int qb = n0 + warpN + nt*8 + ((lane & 3) >> 1)*4;
                const int nh = qb >> 2;
                float4 bb = *reinterpret_cast<const float4*>(&bias[qb]);
                float gi = q0 + bb.x, gf = q1 + bb.y, gg = q2 + bb.z, go = q3 + bb.w;
                if (embAdd) {
                    float4 e = *reinterpret_cast<const float4*>(&embAdd[row*G4 + qb]);
                    gi += e.x; gf += e.y; gg += e.z; go += e.w;
                }
                const int ci = layer*BH + row*HH + nh;
                const float cn = fsigmoid(gf)*g_c[ci] + fsigmoid(gi)*ftanh(gg);
                g_c[ci] = cn;
                const float h = fsigmoid(go)*ftanh(cn);
                const bf16 hh = __float2bfloat16(h);
                g_hhi[ci] = hh;
                g_hlo[ci] = __float2bfloat16(h - __bfloat162float(hh));
            }
        }
    } else {
        #pragma unroll
        for (int mt = 0; mt < 2; mt++) {
            #pragma unroll
            for (int nt = 0; nt < 4; nt++) {
                const int row = m0 + warpM + mt*16 + (lane >> 2);
                const int col = n0 + warpN + nt*8 + (lane & 3)*2;
                const float v0 = acc[mt][nt][0], v1 = acc[mt][nt][1];
                const float v2 = acc[mt][nt][2], v3 = acc[mt][nt][3];
                #pragma unroll
                for (int hrow = 0; hrow < 2; hrow++) {
                    const int r = row + hrow*8;
                    float a = hrow ? v2 : v0, b = hrow ? v3 : v1;
                    if (EPI == 0) {
                        if (bias) { a += bias[col]; b += bias[col+1]; }
                        *reinterpret_cast<float2*>(&C[r*ldc + col]) = make_float2(a, b);
                    } else if (EPI == 1) {
                        a += bias[col];   a = (a > 0.0f) ? a : 0.2f*a;
                        b += bias[col+1]; b = (b > 0.0f) ? b : 0.2f*b;
                        *reinterpret_cast<float2*>(&C[r*ldc + col]) = make_float2(a, b);
                    } else {
                        a += bias[col]; b += bias[col+1];
                        const int l = col >> 10, rem = col & 1023, sel = rem >> 9, hh2 = rem & 511;
                        const int di = l*BH + r*HH + hh2;
                        if (sel) {
                            *reinterpret_cast<float2*>(&g_c[di]) = make_float2(a, b);
                        } else {
                            const bf16 ah = __float2bfloat16(a);
                            const bf16 bh = __float2bfloat16(b);
                            g_hhi[di]   = ah;
                            g_hhi[di+1] = bh;
                            g_hlo[di]   = __float2bfloat16(a - __bfloat162float(ah));
                            g_hlo[di+1] = __float2bfloat16(b - __bfloat162float(bh));
                        }
                    }
                }
            }
        }
    }
}

// ---- transpose + split (+optional gate-interleave perm, zero-pad K) ----
template<int PERM>
__global__ void convsplit(const float* __restrict__ W, int K, int Kpad, int N,
                          bf16* __restrict__ Th, bf16* __restrict__ Tl)
{
    __shared__ float tile[32][33];
    const int k0 = blockIdx.x*32, n0 = blockIdx.y*32;
    const int tx = threadIdx.x, ty = threadIdx.y;
    for (int i = ty; i < 32; i += 8) {
        const int k = k0+i, n = n0+tx;
        tile[i][tx] = (k < K && n < N) ? W[k*N + n] : 0.0f;
    }
    __syncthreads();
    for (int i = ty; i < 32; i += 8) {
        const int n = n0+i, k = k0+tx;
        if (n < N && k < Kpad) {
            const float v = tile[tx][i];
            const int np = PERM ? ((n & 511)*4 + (n >> 9)) : n;
            const bf16 h = __float2bfloat16(v);
            Th[np*Kpad + k] = h;
            Tl[np*Kpad + k] = __float2bfloat16(v - __bfloat162float(h));
        }
    }
}

// ---- prep: z_cond split, prev zero, permuted bias sums ----
__global__ void prep_kernel(const float* __restrict__ z, const int* __restrict__ scen,
                            const float* __restrict__ embed,
                            const float* b0a, const float* b0b,
                            const float* b1a, const float* b1b,
                            const float* b2a, const float* b2b)
{
    const int idx = blockIdx.x*blockDim.x + threadIdx.x;
    if (idx < BB*ZH) {
        const int b = idx / ZH, j = idx - b*ZH;
        const float v = (j < ZZ) ? z[b*ZZ + j] : embed[scen[b]*HH + (j - ZZ)];
        const bf16 h = __float2bfloat16(v);
        g_zchi[idx] = h;
        g_zclo[idx] = __float2bfloat16(v - __bfloat162float(h));
    }
    if (idx < BB*64) { g_prevh[idx] = __float2bfloat16(0.0f); g_prevl[idx] = __float2bfloat16(0.0f); }
    if (idx < LL*G4) {
        const int l = idx >> 11, n = idx & 2047;
        const float s = (l == 0) ? b0a[n]+b0b[n] : (l == 1) ? b1a[n]+b1b[n] : b2a[n]+b2b[n];
        const int np = (n & 511)*4 + (n >> 9);
        g_bias[l*G4 + np] = s;
    }
}

// ---- one-time fp32 GEMM (trend2, N=540) ----
__global__ void __launch_bounds__(256)
gemm32_kernel(const float* __restrict__ A, const float* __restrict__ W,
              int N, int K, const float* __restrict__ bias, float* __restrict__ C)
{
    __shared__ float As[16][65];
    __shared__ float Ws[16][64];
    const int tid = threadIdx.x, tx = tid & 15, ty = tid >> 4;
    const int row0 = blockIdx.x*64, col0 = blockIdx.y*64;
    const int ar = tid >> 2, ak = (tid & 3)*4, wk = tid >> 4, wn = (tid & 15)*4;
    float acc[4][4];
    #pragma unroll
    for (int m = 0; m < 4; m++) { acc[m][0]=acc[m][1]=acc[m][2]=acc[m][3]=0.0f; }
    for (int k0 = 0; k0 < K; k0 += 16) {
        float4 av = *reinterpret_cast<const float4*>(&A[(row0+ar)*K + k0 + ak]);
        As[ak+0][ar]=av.x; As[ak+1][ar]=av.y; As[ak+2][ar]=av.z; As[ak+3][ar]=av.w;
        const int wcol = col0 + wn;
        #pragma unroll
        for (int j = 0; j < 4; j++)
            Ws[wk][wn+j] = (wcol+j < N) ? W[(k0+wk)*N + wcol + j] : 0.0f;
        __syncthreads();
        #pragma unroll
        for (int kk = 0; kk < 16; kk++) {
            float a[4];
            #pragma unroll
            for (int m = 0; m < 4; m++) a[m] = As[kk][ty*4+m];
            #pragma unroll
            for (int m = 0; m < 4; m++)
                #pragma unroll
                for (int n = 0; n < 4; n++) acc[m][n] += a[m]*Ws[kk][tx*4+n];
        }
        __syncthreads();
    }
    #pragma unroll
    for (int m = 0; m < 4; m++) {
        const int row = row0 + ty*4 + m;
        #pragma unroll
        for (int n = 0; n < 4; n++) {
            const int col = col0 + tx*4 + n;
            if (col < N) C[row*N + col] = acc[m][n] + bias[col];
        }
    }
}

// ---- out2 + trend add + prev split ----
__global__ void out2_kernel(const float* __restrict__ W2, const float* __restrict__ b2,
                            int t, float* __restrict__ out)
{
    const int b = blockIdx.x;
    const int w = threadIdx.x >> 5, lane = threadIdx.x & 31;
    const float* hrow = g_hidden + b*HH;
    float s = 0.0f;
    #pragma unroll
    for (int k = lane; k < HH; k += 32) s += hrow[k]*W2[k*VV + w];
    #pragma unroll
    for (int off = 16; off; off >>= 1) s += __shfl_down_sync(0xffffffffu, s, off);
    if (lane == 0) {
        const float o = s + b2[w] + g_trend[b*(TT*VV) + t*VV + w];
        out[b*(TT*VV) + t*VV + w] = o;
        const bf16 h = __float2bfloat16(o);
        g_prevh[b*64 + w] = h;
        g_prevl[b*64 + w] = __float2bfloat16(o - __bfloat162float(h));
    }
}

extern "C" void kernel_launch(void* const* d_in, const int* in_sizes, int n_in,
                              void* d_out, int out_size)
{
    (void)in_sizes; (void)n_in; (void)out_size;
    const float* z     = (const float*)d_in[0];
    const int*   scen  = (const int*)  d_in[1];
    const float* embed = (const float*)d_in[2];
    const float* fcW   = (const float*)d_in[3];
    const float* fcb   = (const float*)d_in[4];
    const float* Wih[LL], *Whh[LL], *bih[LL], *bhh[LL];
    for (int l = 0; l < LL; l++) {
        Wih[l] = (const float*)d_in[5+4*l];  Whh[l] = (const float*)d_in[6+4*l];
        bih[l] = (const float*)d_in[7+4*l];  bhh[l] = (const float*)d_in[8+4*l];
    }
    const float* out1_W = (const float*)d_in[17];
    const float* out1_b = (const float*)d_in[18];
    const float* out2_W = (const float*)d_in[19];
    const float* out2_b = (const float*)d_in[20];
    const float* tr1_W  = (const float*)d_in[21];
    const float* tr1_b  = (const float*)d_in[22];
    const float* tr2_W  = (const float*)d_in[23];
    const float* tr2_b  = (const float*)d_in[24];
    float* out = (float*)d_out;

    cudaFuncSetAttribute(gemm_mma<0>, cudaFuncAttributeMaxDynamicSharedMemorySize, SMEM_TOTAL);
    cudaFuncSetAttribute(gemm_mma<1>, cudaFuncAttributeMaxDynamicSharedMemorySize, SMEM_TOTAL);
    cudaFuncSetAttribute(gemm_mma<2>, cudaFuncAttributeMaxDynamicSharedMemorySize, SMEM_TOTAL);
    cudaFuncSetAttribute(gemm_mma<3>, cudaFuncAttributeMaxDynamicSharedMemorySize, SMEM_TOTAL);

    bf16 *p_zchi,*p_zclo,*p_hhi,*p_hlo,*p_prevh,*p_prevl;
    bf16 *p_fcWh,*p_fcWl,*p_tr1h,*p_tr1l,*p_w0bh,*p_w0bl,*p_w0th,*p_w0tl;
    bf16 *p_whhh,*p_whhl,*p_wihh,*p_wihl,*p_o1h,*p_o1l;
    float *p_embW0,*p_bias,*p_hidden,*p_trendh,*p_trend;
    cudaGetSymbolAddress((void**)&p_zchi, g_zchi);   cudaGetSymbolAddress((void**)&p_zclo, g_zclo);
    cudaGetSymbolAddress((void**)&p_hhi,  g_hhi);    cudaGetSymbolAddress((void**)&p_hlo,  g_hlo);
    cudaGetSymbolAddress((void**)&p_prevh,g_prevh);  cudaGetSymbolAddress((void**)&p_prevl,g_prevl);
    cudaGetSymbolAddress((void**)&p_fcWh, g_fcW_h);  cudaGetSymbolAddress((void**)&p_fcWl, g_fcW_l);
    cudaGetSymbolAddress((void**)&p_tr1h, g_tr1_h);  cudaGetSymbolAddress((void**)&p_tr1l, g_tr1_l);
    cudaGetSymbolAddress((void**)&p_w0bh, g_w0b_h);  cudaGetSymbolAddress((void**)&p_w0bl, g_w0b_l);
    cudaGetSymbolAddress((void**)&p_w0th, g_w0t_h);  cudaGetSymbolAddress((void**)&p_w0tl, g_w0t_l);
    cudaGetSymbolAddress((void**)&p_whhh, g_whh_h);  cudaGetSymbolAddress((void**)&p_whhl, g_whh_l);
    cudaGetSymbolAddress((void**)&p_wihh, g_wih_h);  cudaGetSymbolAddress((void**)&p_wihl, g_wih_l);
    cudaGetSymbolAddress((void**)&p_o1h,  g_o1_h);   cudaGetSymbolAddress((void**)&p_o1l,  g_o1_l);
    cudaGetSymbolAddress((void**)&p_embW0,g_embW0);  cudaGetSymbolAddress((void**)&p_bias, g_bias);
    cudaGetSymbolAddress((void**)&p_hidden,g_hidden);
    cudaGetSymbolAddress((void**)&p_trendh,g_trendh); cudaGetSymbolAddress((void**)&p_trend, g_trend);

    const dim3 cblk(32, 8);
    convsplit<0><<<dim3(20,96), cblk>>>(fcW, ZH, ZH, 3072, p_fcWh, p_fcWl);
    convsplit<0><<<dim3(20,16), cblk>>>(tr1_W, ZH, ZH, HH, p_tr1h, p_tr1l);
    convsplit<1><<<dim3(16,64), cblk>>>(Wih[0] + VV*G4, HH, HH, G4, p_w0bh, p_w0bl);
    convsplit<1><<<dim3(2,64),  cblk>>>(Wih[0], VV, 64, G4, p_w0th, p_w0tl);
    for (int l = 0; l < LL; l++)
        convsplit<1><<<dim3(16,64), cblk>>>(Whh[l], HH, HH, G4, p_whhh + l*G4*HH, p_whhl + l*G4*HH);
    for (int l = 1; l < LL; l++)
        convsplit<1><<<dim3(16,64), cblk>>>(Wih[l], HH, HH, G4, p_wihh + (l-1)*G4*HH, p_wihl + (l-1)*G4*HH);
    convsplit<0><<<dim3(16,16), cblk>>>(out1_W, HH, HH, HH, p_o1h, p_o1l);

    prep_kernel<<<(BB*ZH + 255)/256, 256>>>(z, scen, embed,
        bih[0], bhh[0], bih[1], bhh[1], bih[2], bhh[2]);

    // h0/c0 init scatter (N=3072)
    gemm_mma<2><<<dim3(8,24), 512, SMEM_TOTAL>>>(
        p_zchi, p_zclo, ZH, ZH, p_fcWh, p_fcWl,
        nullptr, nullptr, 0, 0, nullptr, nullptr, 1, nullptr, 0, fcb, nullptr, 0);
    // trend hidden (leaky, N=512)
    gemm_mma<1><<<dim3(8,4), 512, SMEM_TOTAL>>>(
        p_zchi, p_zclo, ZH, ZH, p_tr1h, p_tr1l,
        nullptr, nullptr, 0, 0, nullptr, nullptr, 1, p_trendh, HH, tr1_b, nullptr, 0);
    // trend2 (fp32, one-time)
    gemm32_kernel<<<dim3(16,9), 256>>>(p_trendh, tr2_W, TT*VV, HH, tr2_b, p_trend);
    // embW0 = emb @ Wih0[9:,:]  (permuted cols, N=2048)
    gemm_mma<0><<<dim3(8,16), 512, SMEM_TOTAL>>>(
        p_zchi + ZZ, p_zclo + ZZ, ZH, HH, p_w0bh, p_w0bl,
        nullptr, nullptr, 0, 0, nullptr, nullptr, 1, p_embW0, G4, nullptr, nullptr, 0);

    for (int t = 0; t < TT; t++) {
        // L0: h0@Whh0 + prev@W0top, fused cell
        gemm_mma<3><<<dim3(8,16), 512, SMEM_TOTAL>>>(
            p_hhi, p_hlo, HH, HH, p_whhh, p_whhl,
            p_prevh, p_prevl, 64, 64, p_w0th, p_w0tl,
            2, nullptr, 0, p_bias, p_embW0, 0);
        // L1: h0@Wih1 + h1@Whh1, fused cell
        gemm_mma<3><<<dim3(8,16), 512, SMEM_TOTAL>>>(
            p_hhi, p_hlo, HH, HH, p_wihh, p_wihl,
            p_hhi + BH, p_hlo + BH, HH, HH, p_whhh + G4*HH, p_whhl + G4*HH,
            2, nullptr, 0, p_bias + G4, nullptr, 1);
        // L2
        gemm_mma<3><<<dim3(8,16), 512, SMEM_TOTAL>>>(
            p_hhi + BH, p_hlo + BH, HH, HH, p_wihh + G4*HH, p_wihl + G4*HH,
            p_hhi + 2*BH, p_hlo + 2*BH, HH, HH, p_whhh + 2*G4*HH, p_whhl + 2*G4*HH,
            2, nullptr, 0, p_bias + 2*G4, nullptr, 2);
        // out1 (leaky, N=512)
        gemm_mma<1><<<dim3(8,4), 512, SMEM_TOTAL>>>(
            p_hhi + 2*BH, p_hlo + 2*BH, HH, HH, p_o1h, p_o1l,
            nullptr, nullptr, 0, 0, nullptr, nullptr, 1, p_hidden, HH, out1_b, nullptr, 0);
        // out2 + trend + prev
        out2_kernel<<<BB, 288>>>(out2_W, out2_b, t, out);
    }
}

// round 14
// speedup vs baseline: 1.6979x; 1.0960x over previous
#include <cuda_runtime.h>
#include <cuda_bf16.h>
#include <cstdint>
typedef __nv_bfloat16 bf16;

#define BB 1024
#define TT 60
#define VV 9
#define HH 512
#define LL 3
#define ZZ 128
#define ZH 640
#define G4 2048
#define BH (BB*HH)

// scratch
__device__ float g_c[LL*BH];
__device__ bf16  g_hhi[2*LL*BH];        // ping-pong h (hi part)
__device__ bf16  g_hlo[2*LL*BH];
__device__ bf16  g_prevh[BB*64];
__device__ bf16  g_prevl[BB*64];
__device__ bf16  g_zchi[BB*ZH];
__device__ bf16  g_zclo[BB*ZH];
__device__ float g_embW0[BB*G4];
__device__ float g_bias[LL*G4];
__device__ float g_part[4*BB*HH];       // out1 split-K partials
__device__ float g_trendh[BB*HH];
__device__ float g_trend[BB*TT*VV];
// grid barrier state
__device__ unsigned g_count;
__device__ volatile unsigned g_gen;
// transposed split weights [Nperm, Kpad]
__device__ bf16 g_fcW_h[3072*ZH], g_fcW_l[3072*ZH];
__device__ bf16 g_tr1_h[HH*ZH],  g_tr1_l[HH*ZH];
__device__ bf16 g_w0b_h[G4*HH],  g_w0b_l[G4*HH];
__device__ bf16 g_w0t_h[G4*64],  g_w0t_l[G4*64];
__device__ bf16 g_whh_h[LL*G4*HH], g_whh_l[LL*G4*HH];
__device__ bf16 g_wih_h[2*G4*HH],  g_wih_l[2*G4*HH];
__device__ bf16 g_o1_h[HH*HH],   g_o1_l[HH*HH];

__device__ __forceinline__ float fsigmoid(float x){ return __fdividef(1.0f,1.0f+__expf(-x)); }
__device__ __forceinline__ float ftanh(float x){
    x = fminf(fmaxf(x,-15.0f),15.0f);
    float e = __expf(2.0f*x);
    return (e-1.0f)*__fdividef(1.0f,e+1.0f);
}
__device__ __forceinline__ uint32_t smem_u32(const void* p){
    uint32_t r;
    asm("{ .reg .u64 t; cvta.to.shared.u64 t, %1; cvt.u32.u64 %0, t; }" : "=r"(r) : "l"(p));
    return r;
}
__device__ __forceinline__ void cp16(uint32_t s, const bf16* g){
    asm volatile("cp.async.cg.shared.global [%0], [%1], 16;" :: "r"(s), "l"(g) : "memory");
}
__device__ __forceinline__ void ldsm4(uint32_t* r, uint32_t a){
    asm volatile("ldmatrix.sync.aligned.m8n8.x4.shared.b16 {%0,%1,%2,%3}, [%4];"
        : "=r"(r[0]),"=r"(r[1]),"=r"(r[2]),"=r"(r[3]) : "r"(a));
}
__device__ __forceinline__ void mma16816(float* d, const uint32_t* a, uint32_t b0, uint32_t b1){
    asm volatile("mma.sync.aligned.m16n8k16.row.col.f32.bf16.bf16.f32 "
        "{%0,%1,%2,%3}, {%4,%5,%6,%7}, {%8,%9}, {%0,%1,%2,%3};"
        : "+f"(d[0]),"+f"(d[1]),"+f"(d[2]),"+f"(d[3])
        : "r"(a[0]),"r"(a[1]),"r"(a[2]),"r"(a[3]), "r"(b0),"r"(b1));
}

#define STAGE_B 36864
#define SMEM_TOTAL (3*STAGE_B)  // 110592

// grid barrier: all 128 CTAs resident (1/SM). threadfence = gpu scope -> L1D flushed.
__device__ __forceinline__ void gridbar(int tid){
    __syncthreads();
    __threadfence();
    if (tid == 0){
        unsigned old = g_gen;
        if (atomicAdd(&g_count, 1u) == 127u){
            g_count = 0;
            __threadfence();
            g_gen = old + 1u;
        } else {
            while (g_gen == old) __nanosleep(64);
        }
    }
    __syncthreads();
}

// ---- GEMM phase: 128x128 tile, 512 thr, BK=64, 3-stage cp.async, 3-term split ----
// EPI 0: plain store to C. EPI 3: fused LSTM cell (gate-interleaved cols).
template<int EPI>
__device__ __noinline__ void gemm_phase(
    uint8_t* smem, uint32_t sb, int tid, int m0, int n0,
    const bf16* Ah0, const bf16* Al0, int lda0, int klen0, int koff0, int kb0,
    const bf16* Bh0, const bf16* Bl0,
    const bf16* Ah1, const bf16* Al1, int lda1, int klen1, int kb1,
    const bf16* Bh1, const bf16* Bl1,
    float* C, int ldc, const float* bias, const float* embAdd,
    float* cbase, bf16* hhi_out, bf16* hlo_out)
{
    const int wid = tid >> 5, lane = tid & 31;
    const int nch0 = 3*kb0;
    const int total = nch0 + 3*kb1;

    float acc[2][4][4];
    #pragma unroll
    for (int mt = 0; mt < 2; mt++)
        #pragma unroll
        for (int nt = 0; nt < 4; nt++)
            #pragma unroll
            for (int i = 0; i < 4; i++) acc[mt][nt][i] = 0.0f;

    const int warpM = (wid & 3) * 32, warpN = (wid >> 2) * 32;
    const uint32_t aoff = (uint32_t)((lane & 15)*144 + (lane >> 4)*16);
    const uint32_t boff = (uint32_t)((lane & 7)*144 + ((lane >> 3) & 1)*16 + (lane >> 4)*1152);

    auto issue = [&](int c, int s){
        int cc = c; const bf16 *Ap, *Bp; int lda, klen, koff;
        if (cc < nch0) {
            const int term = cc / kb0; koff = koff0 + ((cc - term*kb0) << 6);
            Ap = (term == 2) ? Al0 : Ah0; Bp = (term == 1) ? Bl0 : Bh0;
            lda = lda0; klen = klen0;
        } else {
            cc -= nch0;
            const int term = cc / kb1; koff = (cc - term*kb1) << 6;
            Ap = (term == 2) ? Al1 : Ah1; Bp = (term == 1) ? Bl1 : Bh1;
            lda = lda1; klen = klen1;
        }
        const uint32_t sA = sb + s*STAGE_B;
        const uint32_t sB = sA + 18432;
        #pragma unroll
        for (int i = 0; i < 2; i++) {
            const int li = tid + i*512;
            const int r = li >> 3, c16 = li & 7;
            cp16(sA + r*144 + c16*16, Ap + (m0 + r)*lda + koff + c16*8);
            cp16(sB + r*144 + c16*16, Bp + (n0 + r)*klen + koff + c16*8);
        }
        asm volatile("cp.async.commit_group;" ::: "memory");
    };
    auto compute = [&](int s){
        const uint32_t sA = sb + s*STAGE_B + warpM*144;
        const uint32_t sB = sb + s*STAGE_B + 18432 + warpN*144;
        #pragma unroll
        for (int ks = 0; ks < 4; ks++) {
            uint32_t af[2][4], bfr[2][4];
            #pragma unroll
            for (int mt = 0; mt < 2; mt++) ldsm4(af[mt], sA + mt*2304 + ks*32 + aoff);
            #pragma unroll
            for (int np = 0; np < 2; np++) ldsm4(bfr[np], sB + np*2304 + ks*32 + boff);
            #pragma unroll
            for (int mt = 0; mt < 2; mt++)
                #pragma unroll
                for (int nt = 0; nt < 4; nt++)
                    mma16816(acc[mt][nt], af[mt], bfr[nt>>1][(nt&1)*2], bfr[nt>>1][(nt&1)*2+1]);
        }
    };

    issue(0, 0);
    issue(1, 1);
    for (int c = 0; c < total; c++) {
        if (c + 1 < total) asm volatile("cp.async.wait_group 1;" ::: "memory");
        else               asm volatile("cp.async.wait_group 0;" ::: "memory");
        __syncthreads();
        compute(c % 3);
        if (c + 2 < total) issue(c + 2, (c + 2) % 3);
    }
    __syncthreads();

    if (EPI == 3) {
        #pragma unroll
        for (int mt = 0; mt < 2; mt++) {
            const int row = m0 + warpM + mt*16 + (lane >> 2) + ((lane & 1) ? 8 : 0);
            #pragma unroll
            for (int nt = 0; nt < 4; nt++) {
                const float d0 = acc[mt][nt][0], d1 = acc[mt][nt][1];
                const float d2 = acc[mt][nt][2], d3 = acc[mt][nt][3];
                const float e0 = __shfl_xor_sync(0xffffffffu, d0, 1);
                const float e1 = __shfl_xor_sync(0xffffffffu, d1, 1);
                const float e2 = __shfl_xor_sync(0xffffffffu, d2, 1);
                const float e3 = __shfl_xor_sync(0xffffffffu, d3, 1);
                float q0, q1, q2, q3;
                if (lane & 1) { q0 = e2; q1 = e3; q2 = d2; q3 = d3; }
                else          { q0 = d0; q1 = d1; q2 = e0; q3 = e1; }
                const int qb = n0 + warpN + nt*8 + ((lane & 3) >> 1)*4;
                const int nh = qb >> 2;
                float4 bb = *reinterpret_cast<const float4*>(&bias[qb]);
                float gi = q0 + bb.x, gf = q1 + bb.y, gg = q2 + bb.z, go = q3 + bb.w;
                if (embAdd) {
                    float4 e = *reinterpret_cast<const float4*>(&embAdd[row*G4 + qb]);
                    gi += e.x; gf += e.y; gg += e.z; go += e.w;
                }
                const int ci = row*HH + nh;
                const float cn = fsigmoid(gf)*cbase[ci] + fsigmoid(gi)*ftanh(gg);
                cbase[ci] = cn;
                const float h = fsigmoid(go)*ftanh(cn);
                const bf16 hh = __float2bfloat16(h);
                hhi_out[ci] = hh;
                hlo_out[ci] = __float2bfloat16(h - __bfloat162float(hh));
            }
        }
    } else {
        #pragma unroll
        for (int mt = 0; mt < 2; mt++) {
            #pragma unroll
            for (int nt = 0; nt < 4; nt++) {
                const int row = m0 + warpM + mt*16 + (lane >> 2);
                const int col = n0 + warpN + nt*8 + (lane & 3)*2;
                *reinterpret_cast<float2*>(&C[row*ldc + col]) =
                    make_float2(acc[mt][nt][0], acc[mt][nt][1]);
                *reinterpret_cast<float2*>(&C[(row+8)*ldc + col]) =
                    make_float2(acc[mt][nt][2], acc[mt][nt][3]);
            }
        }
    }
}

// ---- persistent kernel: all 60 steps, 128 CTAs ----
__global__ void __launch_bounds__(512) step_kernel(
    const float* __restrict__ out1_b, const float* __restrict__ W2,
    const float* __restrict__ b2, float* __restrict__ out)
{
    extern __shared__ __align__(128) uint8_t smem[];
    const uint32_t sb = smem_u32(smem);
    const int tid = threadIdx.x;
    const int cta = blockIdx.x;           // 0..127
    const int gm = (cta & 7) * 128;       // gate gemm tile map (8 x 16)
    const int gn = (cta >> 3) * 128;
    const int o1slice = cta & 3;          // out1: 8M x 4N x 4 K-slices
    const int o1n = ((cta >> 2) & 3) * 128;
    const int o1m = (cta >> 4) * 128;

    for (int t = 0; t < TT; t++) {
        const int p = t & 1, q = p ^ 1;
        const bf16 *hip = g_hhi + p*(LL*BH), *lop = g_hlo + p*(LL*BH);
        bf16 *hiq = g_hhi + q*(LL*BH), *loq = g_hlo + q*(LL*BH);

        // L0: h0(p)@Whh0 (K=512) + prev@W0t (K=64), fused cell -> h0(q)
        gemm_phase<3>(smem, sb, tid, gm, gn,
            hip, lop, HH, HH, 0, 8, g_whh_h, g_whh_l,
            g_prevh, g_prevl, 64, 64, 1, g_w0t_h, g_w0t_l,
            nullptr, 0, g_bias, g_embW0, g_c, hiq, loq);
        gridbar(tid);
        // L1: h0(q)@Wih1 + h1(p)@Whh1
        gemm_phase<3>(smem, sb, tid, gm, gn,
            hiq, loq, HH, HH, 0, 8, g_wih_h, g_wih_l,
            hip + BH, lop + BH, HH, HH, 8, g_whh_h + G4*HH, g_whh_l + G4*HH,
            nullptr, 0, g_bias + G4, nullptr, g_c + BH, hiq + BH, loq + BH);
        gridbar(tid);
        // L2
        gemm_phase<3>(smem, sb, tid, gm, gn,
            hiq + BH, loq + BH, HH, HH, 0, 8, g_wih_h + G4*HH, g_wih_l + G4*HH,
            hip + 2*BH, lop + 2*BH, HH, HH, 8, g_whh_h + 2*G4*HH, g_whh_l + 2*G4*HH,
            nullptr, 0, g_bias + 2*G4, nullptr, g_c + 2*BH, hiq + 2*BH, loq + 2*BH);
        gridbar(tid);
        // out1 split-K partial (no bias/leaky yet)
        gemm_phase<0>(smem, sb, tid, o1m, o1n,
            hiq + 2*BH, loq + 2*BH, HH, HH, o1slice*128, 2, g_o1_h, g_o1_l,
            nullptr, nullptr, 0, 0, 0, nullptr, nullptr,
            g_part + o1slice*(BB*HH), HH, nullptr, nullptr, nullptr, nullptr, nullptr);
        gridbar(tid);
        // out2: combine partials + bias + leaky, dot with W2, add trend, emit prev
        {
            float* hid = reinterpret_cast<float*>(smem);   // 8 rows x 512 = 16KB
            const int rbase = cta * 8;
            #pragma unroll
            for (int i = 0; i < 8; i++) {
                const int e = tid + i*512;
                const int rl = e >> 9, k = e & 511;
                const int gi = (rbase + rl)*HH + k;
                float v = g_part[gi] + g_part[BB*HH + gi]
                        + g_part[2*BB*HH + gi] + g_part[3*BB*HH + gi] + out1_b[k];
                hid[e] = (v > 0.0f) ? v : 0.2f*v;
            }
            __syncthreads();
            const int wid = tid >> 5, lane = tid & 31;
            for (int task = wid; task < 72; task += 16) {
                const int rl = task / 9, w = task - rl*9;
                const float* hrow = hid + rl*512;
                float s = 0.0f;
                #pragma unroll
                for (int k = lane; k < HH; k += 32) s += hrow[k]*W2[k*VV + w];
                #pragma unroll
                for (int off = 16; off; off >>= 1) s += __shfl_down_sync(0xffffffffu, s, off);
                if (lane == 0) {
                    const int b = rbase + rl;
                    const float o = s + b2[w] + g_trend[b*(TT*VV) + t*VV + w];
                    out[b*(TT*VV) + t*VV + w] = o;
                    const bf16 h = __float2bfloat16(o);
                    g_prevh[b*64 + w] = h;
                    g_prevl[b*64 + w] = __float2bfloat16(o - __bfloat162float(h));
                }
            }
        }
        gridbar(tid);
    }
}

// ---- one-time init GEMM (HMMA, EPI: 0 store+bias, 1 bias+leaky, 2 init-scatter) ----
template<int EPI>
__global__ void __launch_bounds__(512)
gemm_init(const bf16* __restrict__ Ah0, const bf16* __restrict__ Al0, int lda0, int k0len,
          const bf16* __restrict__ Bh0, const bf16* __restrict__ Bl0,
          float* __restrict__ C, int ldc, const float* __restrict__ bias)
{
    extern __shared__ __align__(128) uint8_t smem[];
    const uint32_t sb = smem_u32(smem);
    const int tid = threadIdx.x, wid = tid >> 5, lane = tid & 31;
    const int m0 = blockIdx.x * 128, n0 = blockIdx.y * 128;
    const int kb0 = k0len >> 6, total = 3*kb0;

    float acc[2][4][4];
    #pragma unroll
    for (int mt = 0; mt < 2; mt++)
        #pragma unroll
        for (int nt = 0; nt < 4; nt++)
            #pragma unroll
            for (int i = 0; i < 4; i++) acc[mt][nt][i] = 0.0f;

    const int warpM = (wid & 3) * 32, warpN = (wid >> 2) * 32;
    const uint32_t aoff = (uint32_t)((lane & 15)*144 + (lane >> 4)*16);
    const uint32_t boff = (uint32_t)((lane & 7)*144 + ((lane >> 3) & 1)*16 + (lane >> 4)*1152);

    auto issue = [&](int c, int s){
        const int term = c / kb0, koff = (c - term*kb0) << 6;
        const bf16* Ap = (term == 2) ? Al0 : Ah0;
        const bf16* Bp = (term == 1) ? Bl0 : Bh0;
        const uint32_t sA = sb + s*STAGE_B, sB = sA + 18432;
        #pragma unroll
        for (int i = 0; i < 2; i++) {
            const int li = tid + i*512, r = li >> 3, c16 = li & 7;
            cp16(sA + r*144 + c16*16, Ap + (m0 + r)*lda0 + koff + c16*8);
            cp16(sB + r*144 + c16*16, Bp + (n0 + r)*k0len + koff + c16*8);
        }
        asm volatile("cp.async.commit_group;" ::: "memory");
    };
    issue(0, 0);
    issue(1, 1);
    for (int c = 0; c < total; c++) {
        if (c + 1 < total) asm volatile("cp.async.wait_group 1;" ::: "memory");
        else               asm volatile("cp.async.wait_group 0;" ::: "memory");
        __syncthreads();
        {
            const int s = c % 3;
            const uint32_t sA = sb + s*STAGE_B + warpM*144;
            const uint32_t sB = sb + s*STAGE_B + 18432 + warpN*144;
            #pragma unroll
            for (int ks = 0; ks < 4; ks++) {
                uint32_t af[2][4], bfr[2][4];
                #pragma unroll
                for (int mt = 0; mt < 2; mt++) ldsm4(af[mt], sA + mt*2304 + ks*32 + aoff);
                #pragma unroll
                for (int np = 0; np < 2; np++) ldsm4(bfr[np], sB + np*2304 + ks*32 + boff);
                #pragma unroll
                for (int mt = 0; mt < 2; mt++)
                    #pragma unroll
                    for (int nt = 0; nt < 4; nt++)
                        mma16816(acc[mt][nt], af[mt], bfr[nt>>1][(nt&1)*2], bfr[nt>>1][(nt&1)*2+1]);
            }
        }
        if (c + 2 < total) issue(c + 2, (c + 2) % 3);
    }

    #pragma unroll
    for (int mt = 0; mt < 2; mt++) {
        #pragma unroll
        for (int nt = 0; nt < 4; nt++) {
            const int row = m0 + warpM + mt*16 + (lane >> 2);
            const int col = n0 + warpN + nt*8 + (lane & 3)*2;
            #pragma unroll
            for (int hrow = 0; hrow < 2; hrow++) {
                const int r = row + hrow*8;
                float a = hrow ? acc[mt][nt][2] : acc[mt][nt][0];
                float b = hrow ? acc[mt][nt][3] : acc[mt][nt][1];
                if (EPI == 0) {
                    if (bias) { a += bias[col]; b += bias[col+1]; }
                    *reinterpret_cast<float2*>(&C[r*ldc + col]) = make_float2(a, b);
                } else if (EPI == 1) {
                    a += bias[col];   a = (a > 0.0f) ? a : 0.2f*a;
                    b += bias[col+1]; b = (b > 0.0f) ? b : 0.2f*b;
                    *reinterpret_cast<float2*>(&C[r*ldc + col]) = make_float2(a, b);
                } else {
                    a += bias[col]; b += bias[col+1];
                    const int l = col >> 10, rem = col & 1023, sel = rem >> 9, hh2 = rem & 511;
                    const int di = l*BH + r*HH + hh2;
                    if (sel) {
                        *reinterpret_cast<float2*>(&g_c[di]) = make_float2(a, b);
                    } else {
                        const bf16 ah = __float2bfloat16(a);
                        const bf16 bh = __float2bfloat16(b);
                        g_hhi[di]   = ah;  g_hhi[di+1] = bh;
                        g_hlo[di]   = __float2bfloat16(a - __bfloat162float(ah));
                        g_hlo[di+1] = __float2bfloat16(b - __bfloat162float(bh));
                    }
                }
            }
        }
    }
}

// ---- transpose + split (+optional gate-interleave perm, zero-pad K) ----
template<int PERM>
__global__ void convsplit(const float* __restrict__ W, int K, int Kpad, int N,
                          bf16* __restrict__ Th, bf16* __restrict__ Tl)
{
    __shared__ float tile[32][33];
    const int k0 = blockIdx.x*32, n0 = blockIdx.y*32;
    const int tx = threadIdx.x, ty = threadIdx.y;
    for (int i = ty; i < 32; i += 8) {
        const int k = k0+i, n = n0+tx;
        tile[i][tx] = (k < K && n < N) ? W[k*N + n] : 0.0f;
    }
    __syncthreads();
    for (int i = ty; i < 32; i += 8) {
        const int n = n0+i, k = k0+tx;
        if (n < N && k < Kpad) {
            const float v = tile[tx][i];
            const int np = PERM ? ((n & 511)*4 + (n >> 9)) : n;
            const bf16 h = __float2bfloat16(v);
            Th[np*Kpad + k] = h;
            Tl[np*Kpad + k] = __float2bfloat16(v - __bfloat162float(h));
        }
    }
}

// ---- prep: z_cond split, prev zero, permuted bias sums ----
__global__ void prep_kernel(const float* __restrict__ z, const int* __restrict__ scen,
                            const float* __restrict__ embed,
                            const float* b0a, const float* b0b,
                            const float* b1a, const float* b1b,
                            const float* b2a, const float* b2b)
{
    const int idx = blockIdx.x*blockDim.x + threadIdx.x;
    if (idx < BB*ZH) {
        const int b = idx / ZH, j = idx - b*ZH;
        const float v = (j < ZZ) ? z[b*ZZ + j] : embed[scen[b]*HH + (j - ZZ)];
        const bf16 h = __float2bfloat16(v);
        g_zchi[idx] = h;
        g_zclo[idx] = __float2bfloat16(v - __bfloat162float(h));
    }
    if (idx < BB*64) { g_prevh[idx] = __float2bfloat16(0.0f); g_prevl[idx] = __float2bfloat16(0.0f); }
    if (idx < LL*G4) {
        const int l = idx >> 11, n = idx & 2047;
        const float s = (l == 0) ? b0a[n]+b0b[n] : (l == 1) ? b1a[n]+b1b[n] : b2a[n]+b2b[n];
        const int np = (n & 511)*4 + (n >> 9);
        g_bias[l*G4 + np] = s;
    }
}

// ---- one-time fp32 GEMM (trend2, N=540) ----
__global__ void __launch_bounds__(256)
gemm32_kernel(const float* __restrict__ A, const float* __restrict__ W,
              int N, int K, const float* __restrict__ bias, float* __restrict__ C)
{
    __shared__ float As[16][65];
    __shared__ float Ws[16][64];
    const int tid = threadIdx.x, tx = tid & 15, ty = tid >> 4;
    const int row0 = blockIdx.x*64, col0 = blockIdx.y*64;
    const int ar = tid >> 2, ak = (tid & 3)*4, wk = tid >> 4, wn = (tid & 15)*4;
    float acc[4][4];
    #pragma unroll
    for (int m = 0; m < 4; m++) { acc[m][0]=acc[m][1]=acc[m][2]=acc[m][3]=0.0f; }
    for (int k0 = 0; k0 < K; k0 += 16) {
        float4 av = *reinterpret_cast<const float4*>(&A[(row0+ar)*K + k0 + ak]);
        As[ak+0][ar]=av.x; As[ak+1][ar]=av.y; As[ak+2][ar]=av.z; As[ak+3][ar]=av.w;
        const int wcol = col0 + wn;
        #pragma unroll
        for (int j = 0; j < 4; j++)
            Ws[wk][wn+j] = (wcol+j < N) ? W[(k0+wk)*N + wcol + j] : 0.0f;
        __syncthreads();
        #pragma unroll
        for (int kk = 0; kk < 16; kk++) {
            float a[4];
            #pragma unroll
            for (int m = 0; m < 4; m++) a[m] = As[kk][ty*4+m];
            #pragma unroll
            for (int m = 0; m < 4; m++)
                #pragma unroll
                for (int n = 0; n < 4; n++) acc[m][n] += a[m]*Ws[kk][tx*4+n];
        }
        __syncthreads();
    }
    #pragma unroll
    for (int m = 0; m < 4; m++) {
        const int row = row0 + ty*4 + m;
        #pragma unroll
        for (int n = 0; n < 4; n++) {
            const int col = col0 + tx*4 + n;
            if (col < N) C[row*N + col] = acc[m][n] + bias[col];
        }
    }
}

extern "C" void kernel_launch(void* const* d_in, const int* in_sizes, int n_in,
                              void* d_out, int out_size)
{
    (void)in_sizes; (void)n_in; (void)out_size;
    const float* z     = (const float*)d_in[0];
    const int*   scen  = (const int*)  d_in[1];
    const float* embed = (const float*)d_in[2];
    const float* fcW   = (const float*)d_in[3];
    const float* fcb   = (const float*)d_in[4];
    const float* Wih[LL], *Whh[LL], *bih[LL], *bhh[LL];
    for (int l = 0; l < LL; l++) {
        Wih[l] = (const float*)d_in[5+4*l];  Whh[l] = (const float*)d_in[6+4*l];
        bih[l] = (const float*)d_in[7+4*l];  bhh[l] = (const float*)d_in[8+4*l];
    }
    const float* out1_W = (const float*)d_in[17];
    const float* out1_b = (const float*)d_in[18];
    const float* out2_W = (const float*)d_in[19];
    const float* out2_b = (const float*)d_in[20];
    const float* tr1_W  = (const float*)d_in[21];
    const float* tr1_b  = (const float*)d_in[22];
    const float* tr2_W  = (const float*)d_in[23];
    const float* tr2_b  = (const float*)d_in[24];
    float* out = (float*)d_out;

    cudaFuncSetAttribute(gemm_init<0>, cudaFuncAttributeMaxDynamicSharedMemorySize, SMEM_TOTAL);
    cudaFuncSetAttribute(gemm_init<1>, cudaFuncAttributeMaxDynamicSharedMemorySize, SMEM_TOTAL);
    cudaFuncSetAttribute(gemm_init<2>, cudaFuncAttributeMaxDynamicSharedMemorySize, SMEM_TOTAL);
    cudaFuncSetAttribute(step_kernel,  cudaFuncAttributeMaxDynamicSharedMemorySize, SMEM_TOTAL);

    bf16 *p_zchi,*p_zclo,*p_fcWh,*p_fcWl,*p_tr1h,*p_tr1l,*p_w0bh,*p_w0bl,*p_w0th,*p_w0tl;
    bf16 *p_whhh,*p_whhl,*p_wihh,*p_wihl,*p_o1h,*p_o1l;
    float *p_embW0,*p_trendh,*p_trend;
    cudaGetSymbolAddress((void**)&p_zchi, g_zchi);   cudaGetSymbolAddress((void**)&p_zclo, g_zclo);
    cudaGetSymbolAddress((void**)&p_fcWh, g_fcW_h);  cudaGetSymbolAddress((void**)&p_fcWl, g_fcW_l);
    cudaGetSymbolAddress((void**)&p_tr1h, g_tr1_h);  cudaGetSymbolAddress((void**)&p_tr1l, g_tr1_l);
    cudaGetSymbolAddress((void**)&p_w0bh, g_w0b_h);  cudaGetSymbolAddress((void**)&p_w0bl, g_w0b_l);
    cudaGetSymbolAddress((void**)&p_w0th, g_w0t_h);  cudaGetSymbolAddress((void**)&p_w0tl, g_w0t_l);
    cudaGetSymbolAddress((void**)&p_whhh, g_whh_h);  cudaGetSymbolAddress((void**)&p_whhl, g_whh_l);
    cudaGetSymbolAddress((void**)&p_wihh, g_wih_h);  cudaGetSymbolAddress((void**)&p_wihl, g_wih_l);
    cudaGetSymbolAddress((void**)&p_o1h,  g_o1_h);   cudaGetSymbolAddress((void**)&p_o1l,  g_o1_l);
    cudaGetSymbolAddress((void**)&p_embW0,g_embW0);
    cudaGetSymbolAddress((void**)&p_trendh,g_trendh); cudaGetSymbolAddress((void**)&p_trend, g_trend);

    const dim3 cblk(32, 8);
    convsplit<0><<<dim3(20,96), cblk>>>(fcW, ZH, ZH, 3072, p_fcWh, p_fcWl);
    convsplit<0><<<dim3(20,16), cblk>>>(tr1_W, ZH, ZH, HH, p_tr1h, p_tr1l);
    convsplit<1><<<dim3(16,64), cblk>>>(Wih[0] + VV*G4, HH, HH, G4, p_w0bh, p_w0bl);
    convsplit<1><<<dim3(2,64),  cblk>>>(Wih[0], VV, 64, G4, p_w0th, p_w0tl);
    for (int l = 0; l < LL; l++)
        convsplit<1><<<dim3(16,64), cblk>>>(Whh[l], HH, HH, G4, p_whhh + l*G4*HH, p_whhl + l*G4*HH);
    for (int l = 1; l < LL; l++)
        convsplit<1><<<dim3(16,64), cblk>>>(Wih[l], HH, HH, G4, p_wihh + (l-1)*G4*HH, p_wihl + (l-1)*G4*HH);
    convsplit<0><<<dim3(16,16), cblk>>>(out1_W, HH, HH, HH, p_o1h, p_o1l);

    prep_kernel<<<(BB*ZH + 255)/256, 256>>>(z, scen, embed,
        bih[0], bhh[0], bih[1], bhh[1], bih[2], bhh[2]);

    // h0/c0 init scatter (N=3072) -> h buf0 / c
    gemm_init<2><<<dim3(8,24), 512, SMEM_TOTAL>>>(
        p_zchi, p_zclo, ZH, ZH, p_fcWh, p_fcWl, nullptr, 0, fcb);
    // trend hidden (leaky, N=512)
    gemm_init<1><<<dim3(8,4), 512, SMEM_TOTAL>>>(
        p_zchi, p_zclo, ZH, ZH, p_tr1h, p_tr1l, p_trendh, HH, tr1_b);
    // trend2 (fp32, one-time)
    gemm32_kernel<<<dim3(16,9), 256>>>(p_trendh, tr2_W, TT*VV, HH, tr2_b, p_trend);
    // embW0 = emb @ Wih0[9:,:] (permuted cols, N=2048)
    gemm_init<0><<<dim3(8,16), 512, SMEM_TOTAL>>>(
        p_zchi + ZZ, p_zclo + ZZ, ZH, HH, p_w0bh, p_w0bl, p_embW0, G4, nullptr);

    // persistent time loop: one launch, 128 CTAs (all resident), software grid barrier
    step_kernel<<<128, 512, SMEM_TOTAL>>>(out1_b, out2_W, out2_b, out);
}

// round 15
// speedup vs baseline: 1.8890x; 1.1126x over previous
#include <cuda_runtime.h>
#include <cuda_bf16.h>
#include <cstdint>
typedef __nv_bfloat16 bf16;

#define BB 1024
#define TT 60
#define VV 9
#define HH 512
#define LL 3
#define ZZ 128
#define ZH 640
#define G4 2048
#define BH (BB*HH)

// scratch
__device__ float g_c[LL*BH];
__device__ bf16  g_hhi[2*LL*BH];        // ping-pong h (hi part)
__device__ bf16  g_hlo[2*LL*BH];
__device__ bf16  g_prevh[BB*64];
__device__ bf16  g_prevl[BB*64];
__device__ bf16  g_zchi[BB*ZH];
__device__ bf16  g_zclo[BB*ZH];
__device__ float g_embW0[BB*G4];
__device__ float g_bias[LL*G4];
__device__ float g_part[4*BB*HH];       // out1 split-K partials
__device__ float g_trendh[BB*HH];
__device__ float g_trend[BB*TT*VV];
// grid barrier state
__device__ unsigned g_count;
__device__ volatile unsigned g_gen;
// transposed split weights [Nperm, Kpad]
__device__ bf16 g_fcW_h[3072*ZH], g_fcW_l[3072*ZH];
__device__ bf16 g_tr1_h[HH*ZH],  g_tr1_l[HH*ZH];
__device__ bf16 g_w0b_h[G4*HH],  g_w0b_l[G4*HH];
__device__ bf16 g_w0t_h[G4*64],  g_w0t_l[G4*64];
__device__ bf16 g_whh_h[LL*G4*HH], g_whh_l[LL*G4*HH];
__device__ bf16 g_wih_h[2*G4*HH],  g_wih_l[2*G4*HH];
__device__ bf16 g_o1_h[HH*HH],   g_o1_l[HH*HH];

__device__ __forceinline__ float fsigmoid(float x){ return __fdividef(1.0f,1.0f+__expf(-x)); }
__device__ __forceinline__ float ftanh(float x){
    x = fminf(fmaxf(x,-15.0f),15.0f);
    float e = __expf(2.0f*x);
    return (e-1.0f)*__fdividef(1.0f,e+1.0f);
}
__device__ __forceinline__ uint32_t smem_u32(const void* p){
    uint32_t r;
    asm("{ .reg .u64 t; cvta.to.shared.u64 t, %1; cvt.u32.u64 %0, t; }" : "=r"(r) : "l"(p));
    return r;
}
__device__ __forceinline__ void cp16(uint32_t s, const bf16* g){
    asm volatile("cp.async.cg.shared.global [%0], [%1], 16;" :: "r"(s), "l"(g) : "memory");
}
__device__ __forceinline__ void ldsm4(uint32_t* r, uint32_t a){
    asm volatile("ldmatrix.sync.aligned.m8n8.x4.shared.b16 {%0,%1,%2,%3}, [%4];"
        : "=r"(r[0]),"=r"(r[1]),"=r"(r[2]),"=r"(r[3]) : "r"(a));
}
__device__ __forceinline__ void mma16816(float* d, const uint32_t* a, uint32_t b0, uint32_t b1){
    asm volatile("mma.sync.aligned.m16n8k16.row.col.f32.bf16.bf16.f32 "
        "{%0,%1,%2,%3}, {%4,%5,%6,%7}, {%8,%9}, {%0,%1,%2,%3};"
        : "+f"(d[0]),"+f"(d[1]),"+f"(d[2]),"+f"(d[3])
        : "r"(a[0]),"r"(a[1]),"r"(a[2]),"r"(a[3]), "r"(b0),"r"(b1));
}

#define STAGE_B 36864
#define SMEM_TOTAL (3*STAGE_B)  // 110592

// grid barrier: all 128 CTAs resident (1/SM). threadfence = gpu scope.
__device__ __forceinline__ void gridbar(int tid){
    __syncthreads();
    __threadfence();
    if (tid == 0){
        unsigned old = g_gen;
        if (atomicAdd(&g_count, 1u) == 127u){
            g_count = 0;
            __threadfence();
            g_gen = old + 1u;
        } else {
            while (g_gen == old) __nanosleep(64);
        }
    }
    __syncthreads();
}

// ---- GEMM phase: 128x128 tile, 512 thr, BK=64, 3-stage cp.async, 3-term split ----
// EPI 0: plain store to C. EPI 3: fused LSTM cell (gate-interleaved cols).
template<int EPI>
__device__ __noinline__ void gemm_phase(
    uint8_t* smem, uint32_t sb, int tid, int m0, int n0,
    const bf16* Ah0, const bf16* Al0, int lda0, int klen0, int koff0, int kb0,
    const bf16* Bh0, const bf16* Bl0,
    const bf16* Ah1, const bf16* Al1, int lda1, int klen1, int kb1,
    const bf16* Bh1, const bf16* Bl1,
    float* C, int ldc, const float* bias, const float* embAdd,
    float* cbase, bf16* hhi_out, bf16* hlo_out)
{
    const int wid = tid >> 5, lane = tid & 31;
    const int nch0 = 3*kb0;
    const int total = nch0 + 3*kb1;

    float acc[2][4][4];
    #pragma unroll
    for (int mt = 0; mt < 2; mt++)
        #pragma unroll
        for (int nt = 0; nt < 4; nt++)
            #pragma unroll
            for (int i = 0; i < 4; i++) acc[mt][nt][i] = 0.0f;

    const int warpM = (wid & 3) * 32, warpN = (wid >> 2) * 32;
    const uint32_t aoff = (uint32_t)((lane & 15)*144 + (lane >> 4)*16);
    const uint32_t boff = (uint32_t)((lane & 7)*144 + ((lane >> 3) & 1)*16 + (lane >> 4)*1152);

    auto issue = [&](int c, int s){
        int cc = c; const bf16 *Ap, *Bp; int lda, klen, koff;
        if (cc < nch0) {
            const int term = cc / kb0; koff = koff0 + ((cc - term*kb0) << 6);
            Ap = (term == 2) ? Al0 : Ah0; Bp = (term == 1) ? Bl0 : Bh0;
            lda = lda0; klen = klen0;
        } else {
            cc -= nch0;
            const int term = cc / kb1; koff = (cc - term*kb1) << 6;
            Ap = (term == 2) ? Al1 : Ah1; Bp = (term == 1) ? Bl1 : Bh1;
            lda = lda1; klen = klen1;
        }
        const uint32_t sA = sb + s*STAGE_B;
        const uint32_t sB = sA + 18432;
        #pragma unroll
        for (int i = 0; i < 2; i++) {
            const int li = tid + i*512;
            const int r = li >> 3, c16 = li & 7;
            cp16(sA + r*144 + c16*16, Ap + (m0 + r)*lda + koff + c16*8);
            cp16(sB + r*144 + c16*16, Bp + (n0 + r)*klen + koff + c16*8);
        }
        asm volatile("cp.async.commit_group;" ::: "memory");
    };
    auto compute = [&](int s){
        const uint32_t sA = sb + s*STAGE_B + warpM*144;
        const uint32_t sB = sb + s*STAGE_B + 18432 + warpN*144;
        #pragma unroll
        for (int ks = 0; ks < 4; ks++) {
            uint32_t af[2][4], bfr[2][4];
            #pragma unroll
            for (int mt = 0; mt < 2; mt++) ldsm4(af[mt], sA + mt*2304 + ks*32 + aoff);
            #pragma unroll
            for (int np = 0; np < 2; np++) ldsm4(bfr[np], sB + np*2304 + ks*32 + boff);
            #pragma unroll
            for (int mt = 0; mt < 2; mt++)
                #pragma unroll
                for (int nt = 0; nt < 4; nt++)
                    mma16816(acc[mt][nt], af[mt], bfr[nt>>1][(nt&1)*2], bfr[nt>>1][(nt&1)*2+1]);
        }
    };

    issue(0, 0);
    issue(1, 1);
    for (int c = 0; c < total; c++) {
        if (c + 1 < total) asm volatile("cp.async.wait_group 1;" ::: "memory");
        else               asm volatile("cp.async.wait_group 0;" ::: "memory");
        __syncthreads();
        compute(c % 3);
        if (c + 2 < total) issue(c + 2, (c + 2) % 3);
    }
    __syncthreads();

    if (EPI == 3) {
        #pragma unroll
        for (int mt = 0; mt < 2; mt++) {
            const int row = m0 + warpM + mt*16 + (lane >> 2) + ((lane & 1) ? 8 : 0);
            #pragma unroll
            for (int nt = 0; nt < 4; nt++) {
                const float d0 = acc[mt][nt][0], d1 = acc[mt][nt][1];
                const float d2 = acc[mt][nt][2], d3 = acc[mt][nt][3];
                const float e0 = __shfl_xor_sync(0xffffffffu, d0, 1);
                const float e1 = __shfl_xor_sync(0xffffffffu, d1, 1);
                const float e2 = __shfl_xor_sync(0xffffffffu, d2, 1);
                const float e3 = __shfl_xor_sync(0xffffffffu, d3, 1);
                float q0, q1, q2, q3;
                if (lane & 1) { q0 = e2; q1 = e3; q2 = d2; q3 = d3; }
                else          { q0 = d0; q1 = d1; q2 = e0; q3 = e1; }
                const int qb = n0 + warpN + nt*8 + ((lane & 3) >> 1)*4;
                const int nh = qb >> 2;
                float4 bb = *reinterpret_cast<const float4*>(&bias[qb]);
                float gi = q0 + bb.x, gf = q1 + bb.y, gg = q2 + bb.z, go = q3 + bb.w;
                if (embAdd) {
                    float4 e = *reinterpret_cast<const float4*>(&embAdd[row*G4 + qb]);
                    gi += e.x; gf += e.y; gg += e.z; go += e.w;
                }
                const int ci = row*HH + nh;
                const float cn = fsigmoid(gf)*cbase[ci] + fsigmoid(gi)*ftanh(gg);
                cbase[ci] = cn;
                const float h = fsigmoid(go)*ftanh(cn);
                const bf16 hh = __float2bfloat16(h);
                hhi_out[ci] = hh;
                hlo_out[ci] = __float2bfloat16(h - __bfloat162float(hh));
            }
        }
    } else {
        #pragma unroll
        for (int mt = 0; mt < 2; mt++) {
            #pragma unroll
            for (int nt = 0; nt < 4; nt++) {
                const int row = m0 + warpM + mt*16 + (lane >> 2);
                const int col = n0 + warpN + nt*8 + (lane & 3)*2;
                *reinterpret_cast<float2*>(&C[row*ldc + col]) =
                    make_float2(acc[mt][nt][0], acc[mt][nt][1]);
                *reinterpret_cast<float2*>(&C[(row+8)*ldc + col]) =
                    make_float2(acc[mt][nt][2], acc[mt][nt][3]);
            }
        }
    }
}

// ---- persistent kernel: embW0 + all 60 steps, 128 CTAs ----
__global__ void __launch_bounds__(512) step_kernel(
    const float* __restrict__ out1_b, const float* __restrict__ W2,
    const float* __restrict__ b2, float* __restrict__ out)
{
    extern __shared__ __align__(128) uint8_t smem[];
    const uint32_t sb = smem_u32(smem);
    const int tid = threadIdx.x;
    const int cta = blockIdx.x;           // 0..127
    const int gm = (cta & 7) * 128;       // gate gemm tile map (8 x 16)
    const int gn = (cta >> 3) * 128;
    const int o1slice = cta & 3;          // out1: 8M x 4N x 4 K-slices
    const int o1n = ((cta >> 2) & 3) * 128;
    const int o1m = (cta >> 4) * 128;

    // phase -1 (once): embW0 = emb @ Wih0[9:,:]  (grid matches exactly)
    gemm_phase<0>(smem, sb, tid, gm, gn,
        g_zchi + ZZ, g_zclo + ZZ, ZH, HH, 0, 8, g_w0b_h, g_w0b_l,
        nullptr, nullptr, 0, 0, 0, nullptr, nullptr,
        g_embW0, G4, nullptr, nullptr, nullptr, nullptr, nullptr);
    gridbar(tid);

    for (int t = 0; t < TT; t++) {
        const int p = t & 1, q = p ^ 1;
        const bf16 *hip = g_hhi + p*(LL*BH), *lop = g_hlo + p*(LL*BH);
        bf16 *hiq = g_hhi + q*(LL*BH), *loq = g_hlo + q*(LL*BH);

        // L0: h0(p)@Whh0 (K=512) + prev@W0t (K=64), fused cell -> h0(q)
        gemm_phase<3>(smem, sb, tid, gm, gn,
            hip, lop, HH, HH, 0, 8, g_whh_h, g_whh_l,
            g_prevh, g_prevl, 64, 64, 1, g_w0t_h, g_w0t_l,
            nullptr, 0, g_bias, g_embW0, g_c, hiq, loq);
        gridbar(tid);
        // L1: h0(q)@Wih1 + h1(p)@Whh1
        gemm_phase<3>(smem, sb, tid, gm, gn,
            hiq, loq, HH, HH, 0, 8, g_wih_h, g_wih_l,
            hip + BH, lop + BH, HH, HH, 8, g_whh_h + G4*HH, g_whh_l + G4*HH,
            nullptr, 0, g_bias + G4, nullptr, g_c + BH, hiq + BH, loq + BH);
        gridbar(tid);
        // L2
        gemm_phase<3>(smem, sb, tid, gm, gn,
            hiq + BH, loq + BH, HH, HH, 0, 8, g_wih_h + G4*HH, g_wih_l + G4*HH,
            hip + 2*BH, lop + 2*BH, HH, HH, 8, g_whh_h + 2*G4*HH, g_whh_l + 2*G4*HH,
            nullptr, 0, g_bias + 2*G4, nullptr, g_c + 2*BH, hiq + 2*BH, loq + 2*BH);
        gridbar(tid);
        // out1 split-K partial (no bias/leaky yet)
        gemm_phase<0>(smem, sb, tid, o1m, o1n,
            hiq + 2*BH, loq + 2*BH, HH, HH, o1slice*128, 2, g_o1_h, g_o1_l,
            nullptr, nullptr, 0, 0, 0, nullptr, nullptr,
            g_part + o1slice*(BB*HH), HH, nullptr, nullptr, nullptr, nullptr, nullptr);
        gridbar(tid);
        // out2: combine partials + bias + leaky, dot with W2, add trend, emit prev
        {
            float* hid = reinterpret_cast<float*>(smem);   // 8 rows x 512 = 16KB
            const int rbase = cta * 8;
            #pragma unroll
            for (int i = 0; i < 8; i++) {
                const int e = tid + i*512;
                const int rl = e >> 9, k = e & 511;
                const int gi = (rbase + rl)*HH + k;
                float v = g_part[gi] + g_part[BB*HH + gi]
                        + g_part[2*BB*HH + gi] + g_part[3*BB*HH + gi] + out1_b[k];
                hid[e] = (v > 0.0f) ? v : 0.2f*v;
            }
            __syncthreads();
            const int wid = tid >> 5, lane = tid & 31;
            for (int task = wid; task < 72; task += 16) {
                const int rl = task / 9, w = task - rl*9;
                const float* hrow = hid + rl*512;
                float s = 0.0f;
                #pragma unroll
                for (int k = lane; k < HH; k += 32) s += hrow[k]*W2[k*VV + w];
                #pragma unroll
                for (int off = 16; off; off >>= 1) s += __shfl_down_sync(0xffffffffu, s, off);
                if (lane == 0) {
                    const int b = rbase + rl;
                    const float o = s + b2[w] + g_trend[b*(TT*VV) + t*VV + w];
                    out[b*(TT*VV) + t*VV + w] = o;
                    const bf16 h = __float2bfloat16(o);
                    g_prevh[b*64 + w] = h;
                    g_prevl[b*64 + w] = __float2bfloat16(o - __bfloat162float(h));
                }
            }
        }
        gridbar(tid);
    }
}

// ---- one-time init GEMM (HMMA, EPI: 1 bias+leaky, 2 init-scatter) ----
template<int EPI>
__global__ void __launch_bounds__(512)
gemm_init(const bf16* __restrict__ Ah0, const bf16* __restrict__ Al0, int lda0, int k0len,
          const bf16* __restrict__ Bh0, const bf16* __restrict__ Bl0,
          float* __restrict__ C, int ldc, const float* __restrict__ bias)
{
    extern __shared__ __align__(128) uint8_t smem[];
    const uint32_t sb = smem_u32(smem);
    const int tid = threadIdx.x, wid = tid >> 5, lane = tid & 31;
    const int m0 = blockIdx.x * 128, n0 = blockIdx.y * 128;
    const int kb0 = k0len >> 6, total = 3*kb0;

    float acc[2][4][4];
    #pragma unroll
    for (int mt = 0; mt < 2; mt++)
        #pragma unroll
        for (int nt = 0; nt < 4; nt++)
            #pragma unroll
            for (int i = 0; i < 4; i++) acc[mt][nt][i] = 0.0f;

    const int warpM = (wid & 3) * 32, warpN = (wid >> 2) * 32;
    const uint32_t aoff = (uint32_t)((lane & 15)*144 + (lane >> 4)*16);
    const uint32_t boff = (uint32_t)((lane & 7)*144 + ((lane >> 3) & 1)*16 + (lane >> 4)*1152);

    auto issue = [&](int c, int s){
        const int term = c / kb0, koff = (c - term*kb0) << 6;
        const bf16* Ap = (term == 2) ? Al0 : Ah0;
        const bf16* Bp = (term == 1) ? Bl0 : Bh0;
        const uint32_t sA = sb + s*STAGE_B, sB = sA + 18432;
        #pragma unroll
        for (int i = 0; i < 2; i++) {
            const int li = tid + i*512, r = li >> 3, c16 = li & 7;
            cp16(sA + r*144 + c16*16, Ap + (m0 + r)*lda0 + koff + c16*8);
            cp16(sB + r*144 + c16*16, Bp + (n0 + r)*k0len + koff + c16*8);
        }
        asm volatile("cp.async.commit_group;" ::: "memory");
    };
    issue(0, 0);
    issue(1, 1);
    for (int c = 0; c < total; c++) {
        if (c + 1 < total) asm volatile("cp.async.wait_group 1;" ::: "memory");
        else               asm volatile("cp.async.wait_group 0;" ::: "memory");
        __syncthreads();
        {
            const int s = c % 3;
            const uint32_t sA = sb + s*STAGE_B + warpM*144;
            const uint32_t sB = sb + s*STAGE_B + 18432 + warpN*144;
            #pragma unroll
            for (int ks = 0; ks < 4; ks++) {
                uint32_t af[2][4], bfr[2][4];
                #pragma unroll
                for (int mt = 0; mt < 2; mt++) ldsm4(af[mt], sA + mt*2304 + ks*32 + aoff);
                #pragma unroll
                for (int np = 0; np < 2; np++) ldsm4(bfr[np], sB + np*2304 + ks*32 + boff);
                #pragma unroll
                for (int mt = 0; mt < 2; mt++)
                    #pragma unroll
                    for (int nt = 0; nt < 4; nt++)
                        mma16816(acc[mt][nt], af[mt], bfr[nt>>1][(nt&1)*2], bfr[nt>>1][(nt&1)*2+1]);
            }
        }
        if (c + 2 < total) issue(c + 2, (c + 2) % 3);
    }

    #pragma unroll
    for (int mt = 0; mt < 2; mt++) {
        #pragma unroll
        for (int nt = 0; nt < 4; nt++) {
            const int row = m0 + warpM + mt*16 + (lane >> 2);
            const int col = n0 + warpN + nt*8 + (lane & 3)*2;
            #pragma unroll
            for (int hrow = 0; hrow < 2; hrow++) {
                const int r = row + hrow*8;
                float a = hrow ? acc[mt][nt][2] : acc[mt][nt][0];
                float b = hrow ? acc[mt][nt][3] : acc[mt][nt][1];
                if (EPI == 1) {
                    a += bias[col];   a = (a > 0.0f) ? a : 0.2f*a;
                    b += bias[col+1]; b = (b > 0.0f) ? b : 0.2f*b;
                    *reinterpret_cast<float2*>(&C[r*ldc + col]) = make_float2(a, b);
                } else {
                    a += bias[col]; b += bias[col+1];
                    const int l = col >> 10, rem = col & 1023, sel = rem >> 9, hh2 = rem & 511;
                    const int di = l*BH + r*HH + hh2;
                    if (sel) {
                        *reinterpret_cast<float2*>(&g_c[di]) = make_float2(a, b);
                    } else {
                        const bf16 ah = __float2bfloat16(a);
                        const bf16 bh = __float2bfloat16(b);
                        g_hhi[di]   = ah;  g_hhi[di+1] = bh;
                        g_hlo[di]   = __float2bfloat16(a - __bfloat162float(ah));
                        g_hlo[di+1] = __float2bfloat16(b - __bfloat162float(bh));
                    }
                }
            }
        }
    }
}

// ---- merged transpose+split: one launch, job table ----
struct CsJob { const float* W; bf16* Th; bf16* Tl; int K, Kpad, N, gx, blk0, perm; };
struct CsJobs { CsJob j[10]; };

__global__ void convsplit_all(CsJobs jobs)
{
    __shared__ float tile[32][33];
    const int b = blockIdx.x;
    int ji = 0;
    #pragma unroll
    for (int i = 1; i < 10; i++) if (b >= jobs.j[i].blk0) ji = i;
    const CsJob jb = jobs.j[ji];
    const int local = b - jb.blk0;
    const int k0 = (local % jb.gx) * 32;
    const int n0 = (local / jb.gx) * 32;
    const int tx = threadIdx.x, ty = threadIdx.y;
    for (int i = ty; i < 32; i += 8) {
        const int k = k0+i, n = n0+tx;
        tile[i][tx] = (k < jb.K && n < jb.N) ? jb.W[k*jb.N + n] : 0.0f;
    }
    __syncthreads();
    for (int i = ty; i < 32; i += 8) {
        const int n = n0+i, k = k0+tx;
        if (n < jb.N && k < jb.Kpad) {
            const float v = tile[tx][i];
            const int np = jb.perm ? ((n & 511)*4 + (n >> 9)) : n;
            const bf16 h = __float2bfloat16(v);
            jb.Th[np*jb.Kpad + k] = h;
            jb.Tl[np*jb.Kpad + k] = __float2bfloat16(v - __bfloat162float(h));
        }
    }
}

// ---- prep: z_cond split, prev zero, permuted bias sums ----
__global__ void prep_kernel(const float* __restrict__ z, const int* __restrict__ scen,
                            const float* __restrict__ embed,
                            const float* b0a, const float* b0b,
                            const float* b1a, const float* b1b,
                            const float* b2a, const float* b2b)
{
    const int idx = blockIdx.x*blockDim.x + threadIdx.x;
    if (idx < BB*ZH) {
        const int b = idx / ZH, j = idx - b*ZH;
        const float v = (j < ZZ) ? z[b*ZZ + j] : embed[scen[b]*HH + (j - ZZ)];
        const bf16 h = __float2bfloat16(v);
        g_zchi[idx] = h;
        g_zclo[idx] = __float2bfloat16(v - __bfloat162float(h));
    }
    if (idx < BB*64) { g_prevh[idx] = __float2bfloat16(0.0f); g_prevl[idx] = __float2bfloat16(0.0f); }
    if (idx < LL*G4) {
        const int l = idx >> 11, n = idx & 2047;
        const float s = (l == 0) ? b0a[n]+b0b[n] : (l == 1) ? b1a[n]+b1b[n] : b2a[n]+b2b[n];
        const int np = (n & 511)*4 + (n >> 9);
        g_bias[l*G4 + np] = s;
    }
}

// ---- one-time fp32 GEMM (trend2, N=540) ----
__global__ void __launch_bounds__(256)
gemm32_kernel(const float* __restrict__ A, const float* __restrict__ W,
              int N, int K, const float* __restrict__ bias, float* __restrict__ C)
{
    __shared__ float As[16][65];
    __shared__ float Ws[16][64];
    const int tid = threadIdx.x, tx = tid & 15, ty = tid >> 4;
    const int row0 = blockIdx.x*64, col0 = blockIdx.y*64;
    const int ar = tid >> 2, ak = (tid & 3)*4, wk = tid >> 4, wn = (tid & 15)*4;
    float acc[4][4];
    #pragma unroll
    for (int m = 0; m < 4; m++) { acc[m][0]=acc[m][1]=acc[m][2]=acc[m][3]=0.0f; }
    for (int k0 = 0; k0 < K; k0 += 16) {
        float4 av = *reinterpret_cast<const float4*>(&A[(row0+ar)*K + k0 + ak]);
        As[ak+0][ar]=av.x; As[ak+1][ar]=av.y; As[ak+2][ar]=av.z; As[ak+3][ar]=av.w;
        const int wcol = col0 + wn;
        #pragma unroll
        for (int j = 0; j < 4; j++)
            Ws[wk][wn+j] = (wcol+j < N) ? W[(k0+wk)*N + wcol + j] : 0.0f;
        __syncthreads();
        #pragma unroll
        for (int kk = 0; kk < 16; kk++) {
            float a[4];
            #pragma unroll
            for (int m = 0; m < 4; m++) a[m] = As[kk][ty*4+m];
            #pragma unroll
            for (int m = 0; m < 4; m++)
                #pragma unroll
                for (int n = 0; n < 4; n++) acc[m][n] += a[m]*Ws[kk][tx*4+n];
        }
        __syncthreads();
    }
    #pragma unroll
    for (int m = 0; m < 4; m++) {
        const int row = row0 + ty*4 + m;
        #pragma unroll
        for (int n = 0; n < 4; n++) {
            const int col = col0 + tx*4 + n;
            if (col < N) C[row*N + col] = acc[m][n] + bias[col];
        }
    }
}

extern "C" void kernel_launch(void* const* d_in, const int* in_sizes, int n_in,
                              void* d_out, int out_size)
{
    (void)in_sizes; (void)n_in; (void)out_size;
    const float* z     = (const float*)d_in[0];
    const int*   scen  = (const int*)  d_in[1];
    const float* embed = (const float*)d_in[2];
    const float* fcW   = (const float*)d_in[3];
    const float* fcb   = (const float*)d_in[4];
    const float* Wih[LL], *Whh[LL], *bih[LL], *bhh[LL];
    for (int l = 0; l < LL; l++) {
        Wih[l] = (const float*)d_in[5+4*l];  Whh[l] = (const float*)d_in[6+4*l];
        bih[l] = (const float*)d_in[7+4*l];  bhh[l] = (const float*)d_in[8+4*l];
    }
    const float* out1_W = (const float*)d_in[17];
    const float* out1_b = (const float*)d_in[18];
    const float* out2_W = (const float*)d_in[19];
    const float* out2_b = (const float*)d_in[20];
    const float* tr1_W  = (const float*)d_in[21];
    const float* tr1_b  = (const float*)d_in[22];
    const float* tr2_W  = (const float*)d_in[23];
    const float* tr2_b  = (const float*)d_in[24];
    float* out = (float*)d_out;

    cudaFuncSetAttribute(gemm_init<1>, cudaFuncAttributeMaxDynamicSharedMemorySize, SMEM_TOTAL);
    cudaFuncSetAttribute(gemm_init<2>, cudaFuncAttributeMaxDynamicSharedMemorySize, SMEM_TOTAL);
    cudaFuncSetAttribute(step_kernel,  cudaFuncAttributeMaxDynamicSharedMemorySize, SMEM_TOTAL);

    bf16 *p_zchi,*p_zclo,*p_fcWh,*p_fcWl,*p_tr1h,*p_tr1l,*p_w0bh,*p_w0bl,*p_w0th,*p_w0tl;
    bf16 *p_whhh,*p_whhl,*p_wihh,*p_wihl,*p_o1h,*p_o1l;
    float *p_trendh,*p_trend;
    cudaGetSymbolAddress((void**)&p_zchi, g_zchi);   cudaGetSymbolAddress((void**)&p_zclo, g_zclo);
    cudaGetSymbolAddress((void**)&p_fcWh, g_fcW_h);  cudaGetSymbolAddress((void**)&p_fcWl, g_fcW_l);
    cudaGetSymbolAddress((void**)&p_tr1h, g_tr1_h);  cudaGetSymbolAddress((void**)&p_tr1l, g_tr1_l);
    cudaGetSymbolAddress((void**)&p_w0bh, g_w0b_h);  cudaGetSymbolAddress((void**)&p_w0bl, g_w0b_l);
    cudaGetSymbolAddress((void**)&p_w0th, g_w0t_h);  cudaGetSymbolAddress((void**)&p_w0tl, g_w0t_l);
    cudaGetSymbolAddress((void**)&p_whhh, g_whh_h);  cudaGetSymbolAddress((void**)&p_whhl, g_whh_l);
    cudaGetSymbolAddress((void**)&p_wihh, g_wih_h);  cudaGetSymbolAddress((void**)&p_wihl, g_wih_l);
    cudaGetSymbolAddress((void**)&p_o1h,  g_o1_h);   cudaGetSymbolAddress((void**)&p_o1l,  g_o1_l);
    cudaGetSymbolAddress((void**)&p_trendh,g_trendh); cudaGetSymbolAddress((void**)&p_trend, g_trend);

    // job table for merged transpose/split (blk0 cumulative)
    CsJobs jobs;
    int blk = 0;
    auto addjob = [&](int i, const float* W, bf16* Th, bf16* Tl, int K, int Kpad, int N, int perm){
        const int gx = (Kpad + 31)/32, gy = (N + 31)/32;
        jobs.j[i] = CsJob{W, Th, Tl, K, Kpad, N, gx, blk, perm};
        blk += gx*gy;
    };
    addjob(0, fcW,            p_fcWh, p_fcWl, ZH, ZH, 3072, 0);
    addjob(1, tr1_W,          p_tr1h, p_tr1l, ZH, ZH, HH,   0);
    addjob(2, Wih[0] + VV*G4, p_w0bh, p_w0bl, HH, HH, G4,   1);
    addjob(3, Wih[0],         p_w0th, p_w0tl, VV, 64, G4,   1);
    addjob(4, Whh[0],         p_whhh,            p_whhl,            HH, HH, G4, 1);
    addjob(5, Whh[1],         p_whhh + G4*HH,    p_whhl + G4*HH,    HH, HH, G4, 1);
    addjob(6, Whh[2],         p_whhh + 2*G4*HH,  p_whhl + 2*G4*HH,  HH, HH, G4, 1);
    addjob(7, Wih[1],         p_wihh,            p_wihl,            HH, HH, G4, 1);
    addjob(8, Wih[2],         p_wihh + G4*HH,    p_wihl + G4*HH,    HH, HH, G4, 1);
    addjob(9, out1_W,         p_o1h,  p_o1l,  HH, HH, HH,   0);

    // launch 1: all weight transposes/splits
    convsplit_all<<<blk, dim3(32, 8)>>>(jobs);
    // launch 2: prep
    prep_kernel<<<(BB*ZH + 255)/256, 256>>>(z, scen, embed,
        bih[0], bhh[0], bih[1], bhh[1], bih[2], bhh[2]);
    // launch 3: h0/c0 init scatter (N=3072)
    gemm_init<2><<<dim3(8,24), 512, SMEM_TOTAL>>>(
        p_zchi, p_zclo, ZH, ZH, p_fcWh, p_fcWl, nullptr, 0, fcb);
    // launch 4: trend hidden (leaky, N=512)
    gemm_init<1><<<dim3(8,4), 512, SMEM_TOTAL>>>(
        p_zchi, p_zclo, ZH, ZH, p_tr1h, p_tr1l, p_trendh, HH, tr1_b);
    // launch 5: trend2 (fp32)
    gemm32_kernel<<<dim3(16,9), 256>>>(p_trendh, tr2_W, TT*VV, HH, tr2_b, p_trend);
    // launch 6 (ncu -s 5 captures this): persistent embW0 + 60-step loop
    step_kernel<<<128, 512, SMEM_TOTAL>>>(out1_b, out2_W, out2_b, out);
}

// round 16
// speedup vs baseline: 2.5821x; 1.3669x over previous
#include <cuda_runtime.h>
#include <cuda_bf16.h>
#include <cuda_fp16.h>
#include <cstdint>
typedef __nv_bfloat16 bf16;
typedef __half f16;

#define BB 1024
#define TT 60
#define VV 9
#define HH 512
#define LL 3
#define ZZ 128
#define ZH 640
#define G4 2048
#define BH (BB*HH)

// scratch
__device__ float g_c[LL*BH];
__device__ f16   g_hhi[2*LL*BH];
__device__ f16   g_hlo[2*LL*BH];
__device__ f16   g_prevh[BB*64];
__device__ f16   g_prevl[BB*64];
__device__ bf16  g_zchi[BB*ZH];
__device__ bf16  g_zclo[BB*ZH];
__device__ f16   g_emfh[BB*HH];
__device__ f16   g_emfl[BB*HH];
__device__ float g_embW0[BB*G4];
__device__ float g_bias[LL*G4];
__device__ float g_part[4*BB*HH];
__device__ float g_trendh[BB*HH];
__device__ float g_trend[BB*TT*VV];
__device__ unsigned g_count;
__device__ volatile unsigned g_gen;
// init-path weights (bf16 3-term split)
__device__ bf16 g_fcW_h[3072*ZH], g_fcW_l[3072*ZH];
__device__ bf16 g_tr1_h[HH*ZH],  g_tr1_l[HH*ZH];
// loop-path weights (single f16, [Nperm, Kpad])
__device__ f16 g_w0b[G4*HH];
__device__ f16 g_w0t[G4*64];
__device__ f16 g_whh[LL*G4*HH];
__device__ f16 g_wih[2*G4*HH];
__device__ f16 g_o1[HH*HH];

__device__ __forceinline__ float fsigmoid(float x){ return __fdividef(1.0f,1.0f+__expf(-x)); }
__device__ __forceinline__ float ftanh(float x){
    x = fminf(fmaxf(x,-15.0f),15.0f);
    float e = __expf(2.0f*x);
    return (e-1.0f)*__fdividef(1.0f,e+1.0f);
}
__device__ __forceinline__ uint32_t smem_u32(const void* p){
    uint32_t r;
    asm("{ .reg .u64 t; cvta.to.shared.u64 t, %1; cvt.u32.u64 %0, t; }" : "=r"(r) : "l"(p));
    return r;
}
__device__ __forceinline__ void cp16(uint32_t s, const void* g){
    asm volatile("cp.async.cg.shared.global [%0], [%1], 16;" :: "r"(s), "l"(g) : "memory");
}
__device__ __forceinline__ void ldsm4(uint32_t* r, uint32_t a){
    asm volatile("ldmatrix.sync.aligned.m8n8.x4.shared.b16 {%0,%1,%2,%3}, [%4];"
        : "=r"(r[0]),"=r"(r[1]),"=r"(r[2]),"=r"(r[3]) : "r"(a));
}
__device__ __forceinline__ void mma_bf(float* d, const uint32_t* a, uint32_t b0, uint32_t b1){
    asm volatile("mma.sync.aligned.m16n8k16.row.col.f32.bf16.bf16.f32 "
        "{%0,%1,%2,%3}, {%4,%5,%6,%7}, {%8,%9}, {%0,%1,%2,%3};"
        : "+f"(d[0]),"+f"(d[1]),"+f"(d[2]),"+f"(d[3])
        : "r"(a[0]),"r"(a[1]),"r"(a[2]),"r"(a[3]), "r"(b0),"r"(b1));
}
__device__ __forceinline__ void mma_hf(float* d, const uint32_t* a, uint32_t b0, uint32_t b1){
    asm volatile("mma.sync.aligned.m16n8k16.row.col.f32.f16.f16.f32 "
        "{%0,%1,%2,%3}, {%4,%5,%6,%7}, {%8,%9}, {%0,%1,%2,%3};"
        : "+f"(d[0]),"+f"(d[1]),"+f"(d[2]),"+f"(d[3])
        : "r"(a[0]),"r"(a[1]),"r"(a[2]),"r"(a[3]), "r"(b0),"r"(b1));
}

#define STAGE_B 36864
#define SMEM_INIT (3*STAGE_B)     // 110592 (3-term bf16 path)
#define ST2 55296                 // Ahi(18432)+Alo(18432)+B(18432)
#define SMEM2 (3*ST2)             // 165888 (2-term f16 path)

__device__ __forceinline__ void gridbar(int tid){
    __syncthreads();
    __threadfence();
    if (tid == 0){
        unsigned old = g_gen;
        if (atomicAdd(&g_count, 1u) == 127u){
            g_count = 0;
            __threadfence();
            g_gen = old + 1u;
        } else {
            while (g_gen == old) __nanosleep(64);
        }
    }
    __syncthreads();
}

// ---- 2-term f16 GEMM phase: 128x128 tile, BK=64, C=(Ahi+Alo)@B, B loaded once ----
// EPI 0: plain store. EPI 3: fused LSTM cell (gate-interleaved cols).
template<int EPI>
__device__ __noinline__ void gemm2(
    uint8_t* smem, uint32_t sb, int tid, int m0, int n0,
    const f16* Ah0, const f16* Al0, int lda0, int klen0, int koff0, int kb0, const f16* B0,
    const f16* Ah1, const f16* Al1, int lda1, int klen1, int kb1, const f16* B1,
    float* C, int ldc, const float* bias, const float* embAdd,
    float* cbase, f16* hhi_out, f16* hlo_out)
{
    const int wid = tid >> 5, lane = tid & 31;
    const int total = kb0 + kb1;

    float acc[2][4][4];
    #pragma unroll
    for (int mt = 0; mt < 2; mt++)
        #pragma unroll
        for (int nt = 0; nt < 4; nt++)
            #pragma unroll
            for (int i = 0; i < 4; i++) acc[mt][nt][i] = 0.0f;

    const int warpM = (wid & 3) * 32, warpN = (wid >> 2) * 32;
    const uint32_t aoff = (uint32_t)((lane & 15)*144 + (lane >> 4)*16);
    const uint32_t boff = (uint32_t)((lane & 7)*144 + ((lane >> 3) & 1)*16 + (lane >> 4)*1152);

    auto issue = [&](int c, int s){
        const f16 *Ah, *Al, *Bp; int lda, klen, koff;
        if (c < kb0) { koff = koff0 + (c << 6); Ah = Ah0; Al = Al0; Bp = B0; lda = lda0; klen = klen0; }
        else { const int cc = c - kb0; koff = cc << 6; Ah = Ah1; Al = Al1; Bp = B1; lda = lda1; klen = klen1; }
        const uint32_t s0 = sb + s*ST2;
        #pragma unroll
        for (int i = 0; i < 6; i++) {
            const int li = tid + i*512;     // 0..3071
            const int tile = li >> 10, w = li & 1023;
            const int r = w >> 3, c16 = w & 7;
            const f16* src = (tile == 0) ? Ah + (m0 + r)*lda + koff + c16*8
                           : (tile == 1) ? Al + (m0 + r)*lda + koff + c16*8
                           :               Bp + (n0 + r)*klen + koff + c16*8;
            cp16(s0 + tile*18432 + r*144 + c16*16, src);
        }
        asm volatile("cp.async.commit_group;" ::: "memory");
    };
    auto compute = [&](int s){
        const uint32_t sAh = sb + s*ST2 + warpM*144;
        const uint32_t sAl = sAh + 18432;
        const uint32_t sB  = sb + s*ST2 + 36864 + warpN*144;
        #pragma unroll
        for (int ks = 0; ks < 4; ks++) {
            uint32_t bfr[2][4], ah[2][4], al[2][4];
            #pragma unroll
            for (int np = 0; np < 2; np++) ldsm4(bfr[np], sB + np*2304 + ks*32 + boff);
            #pragma unroll
            for (int mt = 0; mt < 2; mt++) {
                ldsm4(ah[mt], sAh + mt*2304 + ks*32 + aoff);
                ldsm4(al[mt], sAl + mt*2304 + ks*32 + aoff);
            }
            #pragma unroll
            for (int mt = 0; mt < 2; mt++)
                #pragma unroll
                for (int nt = 0; nt < 4; nt++) {
                    mma_hf(acc[mt][nt], ah[mt], bfr[nt>>1][(nt&1)*2], bfr[nt>>1][(nt&1)*2+1]);
                    mma_hf(acc[mt][nt], al[mt], bfr[nt>>1][(nt&1)*2], bfr[nt>>1][(nt&1)*2+1]);
                }
        }
    };

    issue(0, 0);
    issue(1, 1);
    for (int c = 0; c < total; c++) {
        if (c + 1 < total) asm volatile("cp.async.wait_group 1;" ::: "memory");
        else               asm volatile("cp.async.wait_group 0;" ::: "memory");
        __syncthreads();
        compute(c % 3);
        if (c + 2 < total) issue(c + 2, (c + 2) % 3);
    }
    __syncthreads();

    if (EPI == 3) {
        #pragma unroll
        for (int mt = 0; mt < 2; mt++) {
            const int row = m0 + warpM + mt*16 + (lane >> 2) + ((lane & 1) ? 8 : 0);
            #pragma unroll
            for (int nt = 0; nt < 4; nt++) {
                const float d0 = acc[mt][nt][0], d1 = acc[mt][nt][1];
                const float d2 = acc[mt][nt][2], d3 = acc[mt][nt][3];
                const float e0 = __shfl_xor_sync(0xffffffffu, d0, 1);
                const float e1 = __shfl_xor_sync(0xffffffffu, d1, 1);
                const float e2 = __shfl_xor_sync(0xffffffffu, d2, 1);
                const float e3 = __shfl_xor_sync(0xffffffffu, d3, 1);
                float q0, q1, q2, q3;
                if (lane & 1) { q0 = e2; q1 = e3; q2 = d2; q3 = d3; }
                else          { q0 = d0; q1 = d1; q2 = e0; q3 = e1; }
                const int qb = n0 + warpN + nt*8 + ((lane & 3) >> 1)*4;
                const int nh = qb >> 2;
                float4 bb = *reinterpret_cast<const float4*>(&bias[qb]);
                float gi = q0 + bb.x, gf = q1 + bb.y, gg = q2 + bb.z, go = q3 + bb.w;
                if (embAdd) {
                    float4 e = *reinterpret_cast<const float4*>(&embAdd[row*G4 + qb]);
                    gi += e.x; gf += e.y; gg += e.z; go += e.w;
                }
                const int ci = row*HH + nh;
                const float cn = fsigmoid(gf)*cbase[ci] + fsigmoid(gi)*ftanh(gg);
                cbase[ci] = cn;
                const float h = fsigmoid(go)*ftanh(cn);
                const f16 hh = __float2half(h);
                hhi_out[ci] = hh;
                hlo_out[ci] = __float2half(h - __half2float(hh));
            }
        }
    } else {
        #pragma unroll
        for (int mt = 0; mt < 2; mt++) {
            #pragma unroll
            for (int nt = 0; nt < 4; nt++) {
                const int row = m0 + warpM + mt*16 + (lane >> 2);
                const int col = n0 + warpN + nt*8 + (lane & 3)*2;
                *reinterpret_cast<float2*>(&C[row*ldc + col]) =
                    make_float2(acc[mt][nt][0], acc[mt][nt][1]);
                *reinterpret_cast<float2*>(&C[(row+8)*ldc + col]) =
                    make_float2(acc[mt][nt][2], acc[mt][nt][3]);
            }
        }
    }
}

// ---- persistent kernel: embW0 + 60 steps, 128 CTAs ----
__global__ void __launch_bounds__(512) step_kernel(
    const float* __restrict__ out1_b, const float* __restrict__ W2,
    const float* __restrict__ b2, float* __restrict__ out)
{
    extern __shared__ __align__(128) uint8_t smem[];
    const uint32_t sb = smem_u32(smem);
    const int tid = threadIdx.x;
    const int cta = blockIdx.x;
    const int gm = (cta & 7) * 128;
    const int gn = (cta >> 3) * 128;
    const int o1slice = cta & 3;
    const int o1n = ((cta >> 2) & 3) * 128;
    const int o1m = (cta >> 4) * 128;

    // once: embW0 = emb @ Wih0[9:,:]
    gemm2<0>(smem, sb, tid, gm, gn,
        g_emfh, g_emfl, HH, HH, 0, 8, g_w0b,
        nullptr, nullptr, 0, 0, 0, nullptr,
        g_embW0, G4, nullptr, nullptr, nullptr, nullptr, nullptr);
    gridbar(tid);

    for (int t = 0; t < TT; t++) {
        const int p = t & 1, q = p ^ 1;
        const f16 *hip = g_hhi + p*(LL*BH), *lop = g_hlo + p*(LL*BH);
        f16 *hiq = g_hhi + q*(LL*BH), *loq = g_hlo + q*(LL*BH);

        // L0: h0(p)@Whh0 + prev@W0t, fused cell -> h0(q)
        gemm2<3>(smem, sb, tid, gm, gn,
            hip, lop, HH, HH, 0, 8, g_whh,
            g_prevh, g_prevl, 64, 64, 1, g_w0t,
            nullptr, 0, g_bias, g_embW0, g_c, hiq, loq);
        gridbar(tid);
        // L1
        gemm2<3>(smem, sb, tid, gm, gn,
            hiq, loq, HH, HH, 0, 8, g_wih,
            hip + BH, lop + BH, HH, HH, 8, g_whh + G4*HH,
            nullptr, 0, g_bias + G4, nullptr, g_c + BH, hiq + BH, loq + BH);
        gridbar(tid);
        // L2
        gemm2<3>(smem, sb, tid, gm, gn,
            hiq + BH, loq + BH, HH, HH, 0, 8, g_wih + G4*HH,
            hip + 2*BH, lop + 2*BH, HH, HH, 8, g_whh + 2*G4*HH,
            nullptr, 0, g_bias + 2*G4, nullptr, g_c + 2*BH, hiq + 2*BH, loq + 2*BH);
        gridbar(tid);
        // out1 split-K partial
        gemm2<0>(smem, sb, tid, o1m, o1n,
            hiq + 2*BH, loq + 2*BH, HH, HH, o1slice*128, 2, g_o1,
            nullptr, nullptr, 0, 0, 0, nullptr,
            g_part + o1slice*(BB*HH), HH, nullptr, nullptr, nullptr, nullptr, nullptr);
        gridbar(tid);
        // out2
        {
            float* hid = reinterpret_cast<float*>(smem);
            const int rbase = cta * 8;
            #pragma unroll
            for (int i = 0; i < 8; i++) {
                const int e = tid + i*512;
                const int rl = e >> 9, k = e & 511;
                const int gi = (rbase + rl)*HH + k;
                float v = g_part[gi] + g_part[BB*HH + gi]
                        + g_part[2*BB*HH + gi] + g_part[3*BB*HH + gi] + out1_b[k];
                hid[e] = (v > 0.0f) ? v : 0.2f*v;
            }
            __syncthreads();
            const int wid = tid >> 5, lane = tid & 31;
            for (int task = wid; task < 72; task += 16) {
                const int rl = task / 9, w = task - rl*9;
                const float* hrow = hid + rl*512;
                float s = 0.0f;
                #pragma unroll
                for (int k = lane; k < HH; k += 32) s += hrow[k]*W2[k*VV + w];
                #pragma unroll
                for (int off = 16; off; off >>= 1) s += __shfl_down_sync(0xffffffffu, s, off);
                if (lane == 0) {
                    const int b = rbase + rl;
                    const float o = s + b2[w] + g_trend[b*(TT*VV) + t*VV + w];
                    out[b*(TT*VV) + t*VV + w] = o;
                    const f16 h = __float2half(o);
                    g_prevh[b*64 + w] = h;
                    g_prevl[b*64 + w] = __float2half(o - __half2float(h));
                }
            }
        }
        gridbar(tid);
    }
}

// ---- one-time init GEMM (3-term bf16; EPI 1 bias+leaky, 2 init-scatter) ----
template<int EPI>
__global__ void __launch_bounds__(512)
gemm_init(const bf16* __restrict__ Ah0, const bf16* __restrict__ Al0, int lda0, int k0len,
          const bf16* __restrict__ Bh0, const bf16* __restrict__ Bl0,
          float* __restrict__ C, int ldc, const float* __restrict__ bias)
{
    extern __shared__ __align__(128) uint8_t smem[];
    const uint32_t sb = smem_u32(smem);
    const int tid = threadIdx.x, wid = tid >> 5, lane = tid & 31;
    const int m0 = blockIdx.x * 128, n0 = blockIdx.y * 128;
    const int kb0 = k0len >> 6, total = 3*kb0;

    float acc[2][4][4];
    #pragma unroll
    for (int mt = 0; mt < 2; mt++)
        #pragma unroll
        for (int nt = 0; nt < 4; nt++)
            #pragma unroll
            for (int i = 0; i < 4; i++) acc[mt][nt][i] = 0.0f;

    const int warpM = (wid & 3) * 32, warpN = (wid >> 2) * 32;
    const uint32_t aoff = (uint32_t)((lane & 15)*144 + (lane >> 4)*16);
    const uint32_t boff = (uint32_t)((lane & 7)*144 + ((lane >> 3) & 1)*16 + (lane >> 4)*1152);

    auto issue = [&](int c, int s){
        const int term = c / kb0, koff = (c - term*kb0) << 6;
        const bf16* Ap = (term == 2) ? Al0 : Ah0;
        const bf16* Bp = (term == 1) ? Bl0 : Bh0;
        const uint32_t sA = sb + s*STAGE_B, sB = sA + 18432;
        #pragma unroll
        for (int i = 0; i < 2; i++) {
            const int li = tid + i*512, r = li >> 3, c16 = li & 7;
            cp16(sA + r*144 + c16*16, Ap + (m0 + r)*lda0 + koff + c16*8);
            cp16(sB + r*144 + c16*16, Bp + (n0 + r)*k0len + koff + c16*8);
        }
        asm volatile("cp.async.commit_group;" ::: "memory");
    };
    issue(0, 0);
    issue(1, 1);
    for (int c = 0; c < total; c++) {
        if (c + 1 < total) asm volatile("cp.async.wait_group 1;" ::: "memory");
        else               asm volatile("cp.async.wait_group 0;" ::: "memory");
        __syncthreads();
        {
            const int s = c % 3;
            const uint32_t sA = sb + s*STAGE_B + warpM*144;
            const uint32_t sB = sb + s*STAGE_B + 18432 + warpN*144;
            #pragma unroll
            for (int ks = 0; ks < 4; ks++) {
                uint32_t af[2][4], bfr[2][4];
                #pragma unroll
                for (int mt = 0; mt < 2; mt++) ldsm4(af[mt], sA + mt*2304 + ks*32 + aoff);
                #pragma unroll
                for (int np = 0; np < 2; np++) ldsm4(bfr[np], sB + np*2304 + ks*32 + boff);
                #pragma unroll
                for (int mt = 0; mt < 2; mt++)
                    #pragma unroll
                    for (int nt = 0; nt < 4; nt++)
                        mma_bf(acc[mt][nt], af[mt], bfr[nt>>1][(nt&1)*2], bfr[nt>>1][(nt&1)*2+1]);
            }
        }
        if (c + 2 < total) issue(c + 2, (c + 2) % 3);
    }

    #pragma unroll
    for (int mt = 0; mt < 2; mt++) {
        #pragma unroll
        for (int nt = 0; nt < 4; nt++) {
            const int row = m0 + warpM + mt*16 + (lane >> 2);
            const int col = n0 + warpN + nt*8 + (lane & 3)*2;
            #pragma unroll
            for (int hrow = 0; hrow < 2; hrow++) {
                const int r = row + hrow*8;
                float a = hrow ? acc[mt][nt][2] : acc[mt][nt][0];
                float b = hrow ? acc[mt][nt][3] : acc[mt][nt][1];
                if (EPI == 1) {
                    a += bias[col];   a = (a > 0.0f) ? a : 0.2f*a;
                    b += bias[col+1]; b = (b > 0.0f) ? b : 0.2f*b;
                    *reinterpret_cast<float2*>(&C[r*ldc + col]) = make_float2(a, b);
                } else {
                    a += bias[col]; b += bias[col+1];
                    const int l = col >> 10, rem = col & 1023, sel = rem >> 9, hh2 = rem & 511;
                    const int di = l*BH + r*HH + hh2;
                    if (sel) {
                        *reinterpret_cast<float2*>(&g_c[di]) = make_float2(a, b);
                    } else {
                        const f16 ah = __float2half(a);
                        const f16 bh = __float2half(b);
                        g_hhi[di]   = ah;  g_hhi[di+1] = bh;
                        g_hlo[di]   = __float2half(a - __half2float(ah));
                        g_hlo[di+1] = __float2half(b - __half2float(bh));
                    }
                }
            }
        }
    }
}

// ---- merged transpose+split: fmt 0 = bf16 hi/lo pair, 1 = single f16 ----
struct CsJob { const float* W; void* Th; void* Tl; int K, Kpad, N, gx, blk0, perm, fmt; };
struct CsJobs { CsJob j[10]; };

__global__ void convsplit_all(CsJobs jobs)
{
    __shared__ float tile[32][33];
    const int b = blockIdx.x;
    int ji = 0;
    #pragma unroll
    for (int i = 1; i < 10; i++) if (b >= jobs.j[i].blk0) ji = i;
    const CsJob jb = jobs.j[ji];
    const int local = b - jb.blk0;
    const int k0 = (local % jb.gx) * 32;
    const int n0 = (local / jb.gx) * 32;
    const int tx = threadIdx.x, ty = threadIdx.y;
    for (int i = ty; i < 32; i += 8) {
        const int k = k0+i, n = n0+tx;
        tile[i][tx] = (k < jb.K && n < jb.N) ? jb.W[k*jb.N + n] : 0.0f;
    }
    __syncthreads();
    for (int i = ty; i < 32; i += 8) {
        const int n = n0+i, k = k0+tx;
        if (n < jb.N && k < jb.Kpad) {
            const float v = tile[tx][i];
            const int np = jb.perm ? ((n & 511)*4 + (n >> 9)) : n;
            if (jb.fmt == 0) {
                const bf16 h = __float2bfloat16(v);
                ((bf16*)jb.Th)[np*jb.Kpad + k] = h;
                ((bf16*)jb.Tl)[np*jb.Kpad + k] = __float2bfloat16(v - __bfloat162float(h));
            } else {
                ((f16*)jb.Th)[np*jb.Kpad + k] = __float2half(v);
            }
        }
    }
}

// ---- prep ----
__global__ void prep_kernel(const float* __restrict__ z, const int* __restrict__ scen,
                            const float* __restrict__ embed,
                            const float* b0a, const float* b0b,
                            const float* b1a, const float* b1b,
                            const float* b2a, const float* b2b)
{
    const int idx = blockIdx.x*blockDim.x + threadIdx.x;
    if (idx < BB*ZH) {
        const int b = idx / ZH, j = idx - b*ZH;
        const float v = (j < ZZ) ? z[b*ZZ + j] : embed[scen[b]*HH + (j - ZZ)];
        const bf16 h = __float2bfloat16(v);
        g_zchi[idx] = h;
        g_zclo[idx] = __float2bfloat16(v - __bfloat162float(h));
        if (j >= ZZ) {
            const int ei = b*HH + (j - ZZ);
            const f16 fh = __float2half(v);
            g_emfh[ei] = fh;
            g_emfl[ei] = __float2half(v - __half2float(fh));
        }
    }
    if (idx < BB*64) { g_prevh[idx] = __float2half(0.0f); g_prevl[idx] = __float2half(0.0f); }
    if (idx < LL*G4) {
        const int l = idx >> 11, n = idx & 2047;
        const float s = (l == 0) ? b0a[n]+b0b[n] : (l == 1) ? b1a[n]+b1b[n] : b2a[n]+b2b[n];
        const int np = (n & 511)*4 + (n >> 9);
        g_bias[l*G4 + np] = s;
    }
}

// ---- one-time fp32 GEMM (trend2) ----
__global__ void __launch_bounds__(256)
gemm32_kernel(const float* __restrict__ A, const float* __restrict__ W,
              int N, int K, const float* __restrict__ bias, float* __restrict__ C)
{
    __shared__ float As[16][65];
    __shared__ float Ws[16][64];
    const int tid = threadIdx.x, tx = tid & 15, ty = tid >> 4;
    const int row0 = blockIdx.x*64, col0 = blockIdx.y*64;
    const int ar = tid >> 2, ak = (tid & 3)*4, wk = tid >> 4, wn = (tid & 15)*4;
    float acc[4][4];
    #pragma unroll
    for (int m = 0; m < 4; m++) { acc[m][0]=acc[m][1]=acc[m][2]=acc[m][3]=0.0f; }
    for (int k0 = 0; k0 < K; k0 += 16) {
        float4 av = *reinterpret_cast<const float4*>(&A[(row0+ar)*K + k0 + ak]);
        As[ak+0][ar]=av.x; As[ak+1][ar]=av.y; As[ak+2][ar]=av.z; As[ak+3][ar]=av.w;
        const int wcol = col0 + wn;
        #pragma unroll
        for (int j = 0; j < 4; j++)
            Ws[wk][wn+j] = (wcol+j < N) ? W[(k0+wk)*N + wcol + j] : 0.0f;
        __syncthreads();
        #pragma unroll
        for (int kk = 0; kk < 16; kk++) {
            float a[4];
            #pragma unroll
            for (int m = 0; m < 4; m++) a[m] = As[kk][ty*4+m];
            #pragma unroll
            for (int m = 0; m < 4; m++)
                #pragma unroll
                for (int n = 0; n < 4; n++) acc[m][n] += a[m]*Ws[kk][tx*4+n];
        }
        __syncthreads();
    }
    #pragma unroll
    for (int m = 0; m < 4; m++) {
        const int row = row0 + ty*4 + m;
        #pragma unroll
        for (int n = 0; n < 4; n++) {
            const int col = col0 + tx*4 + n;
            if (col < N) C[row*N + col] = acc[m][n] + bias[col];
        }
    }
}

extern "C" void kernel_launch(void* const* d_in, const int* in_sizes, int n_in,
                              void* d_out, int out_size)
{
    (void)in_sizes; (void)n_in; (void)out_size;
    const float* z     = (const float*)d_in[0];
    const int*   scen  = (const int*)  d_in[1];
    const float* embed = (const float*)d_in[2];
    const float* fcW   = (const float*)d_in[3];
    const float* fcb   = (const float*)d_in[4];
    const float* Wih[LL], *Whh[LL], *bih[LL], *bhh[LL];
    for (int l = 0; l < LL; l++) {
        Wih[l] = (const float*)d_in[5+4*l];  Whh[l] = (const float*)d_in[6+4*l];
        bih[l] = (const float*)d_in[7+4*l];  bhh[l] = (const float*)d_in[8+4*l];
    }
    const float* out1_W = (const float*)d_in[17];
    const float* out1_b = (const float*)d_in[18];
    const float* out2_W = (const float*)d_in[19];
    const float* out2_b = (const float*)d_in[20];
    const float* tr1_W  = (const float*)d_in[21];
    const float* tr1_b  = (const float*)d_in[22];
    const float* tr2_W  = (const float*)d_in[23];
    const float* tr2_b  = (const float*)d_in[24];
    float* out = (float*)d_out;

    cudaFuncSetAttribute(gemm_init<1>, cudaFuncAttributeMaxDynamicSharedMemorySize, SMEM_INIT);
    cudaFuncSetAttribute(gemm_init<2>, cudaFuncAttributeMaxDynamicSharedMemorySize, SMEM_INIT);
    cudaFuncSetAttribute(step_kernel,  cudaFuncAttributeMaxDynamicSharedMemorySize, SMEM2);

    bf16 *p_zchi,*p_zclo,*p_fcWh,*p_fcWl,*p_tr1h,*p_tr1l;
    f16  *p_w0b,*p_w0t,*p_whh,*p_wih,*p_o1;
    float *p_trendh,*p_trend;
    cudaGetSymbolAddress((void**)&p_zchi, g_zchi);   cudaGetSymbolAddress((void**)&p_zclo, g_zclo);
    cudaGetSymbolAddress((void**)&p_fcWh, g_fcW_h);  cudaGetSymbolAddress((void**)&p_fcWl, g_fcW_l);
    cudaGetSymbolAddress((void**)&p_tr1h, g_tr1_h);  cudaGetSymbolAddress((void**)&p_tr1l, g_tr1_l);
    cudaGetSymbolAddress((void**)&p_w0b,  g_w0b);    cudaGetSymbolAddress((void**)&p_w0t,  g_w0t);
    cudaGetSymbolAddress((void**)&p_whh,  g_whh);    cudaGetSymbolAddress((void**)&p_wih,  g_wih);
    cudaGetSymbolAddress((void**)&p_o1,   g_o1);
    cudaGetSymbolAddress((void**)&p_trendh,g_trendh); cudaGetSymbolAddress((void**)&p_trend, g_trend);

    CsJobs jobs;
    int blk = 0;
    auto addjob = [&](int i, const float* W, void* Th, void* Tl, int K, int Kpad, int N, int perm, int fmt){
        const int gx = (Kpad + 31)/32, gy = (N + 31)/32;
        jobs.j[i] = CsJob{W, Th, Tl, K, Kpad, N, gx, blk, perm, fmt};
        blk += gx*gy;
    };
    addjob(0, fcW,            p_fcWh, p_fcWl, ZH, ZH, 3072, 0, 0);
    addjob(1, tr1_W,          p_tr1h, p_tr1l, ZH, ZH, HH,   0, 0);
    addjob(2, Wih[0] + VV*G4, p_w0b,  nullptr, HH, HH, G4,  1, 1);
    addjob(3, Wih[0],         p_w0t,  nullptr, VV, 64, G4,  1, 1);
    addjob(4, Whh[0],         p_whh,             nullptr, HH, HH, G4, 1, 1);
    addjob(5, Whh[1],         p_whh + G4*HH,     nullptr, HH, HH, G4, 1, 1);
    addjob(6, Whh[2],         p_whh + 2*G4*HH,   nullptr, HH, HH, G4, 1, 1);
    addjob(7, Wih[1],         p_wih,             nullptr, HH, HH, G4, 1, 1);
    addjob(8, Wih[2],         p_wih + G4*HH,     nullptr, HH, HH, G4, 1, 1);
    addjob(9, out1_W,         p_o1,   nullptr, HH, HH, HH,  0, 1);

    convsplit_all<<<blk, dim3(32, 8)>>>(jobs);
    prep_kernel<<<(BB*ZH + 255)/256, 256>>>(z, scen, embed,
        bih[0], bhh[0], bih[1], bhh[1], bih[2], bhh[2]);
    gemm_init<2><<<dim3(8,24), 512, SMEM_INIT>>>(
        p_zchi, p_zclo, ZH, ZH, p_fcWh, p_fcWl, nullptr, 0, fcb);
    gemm_init<1><<<dim3(8,4), 512, SMEM_INIT>>>(
        p_zchi, p_zclo, ZH, ZH, p_tr1h, p_tr1l, p_trendh, HH, tr1_b);
    gemm32_kernel<<<dim3(16,9), 256>>>(p_trendh, tr2_W, TT*VV, HH, tr2_b, p_trend);
    step_kernel<<<128, 512, SMEM2>>>(out1_b, out2_W, out2_b, out);
}

// round 17
// speedup vs baseline: 3.1867x; 1.2341x over previous
#include <cuda_runtime.h>
#include <cuda_bf16.h>
#include <cuda_fp16.h>
#include <cstdint>
typedef __nv_bfloat16 bf16;
typedef __half f16;

#define BB 1024
#define TT 60
#define VV 9
#define HH 512
#define LL 3
#define ZZ 128
#define ZH 640
#define G4 2048
#define BH (BB*HH)

// scratch
__device__ float g_c[LL*BH];
__device__ f16   g_h[2*LL*BH];          // ping-pong h, single f16
__device__ f16   g_prev[BB*64];
__device__ bf16  g_zchi[BB*ZH];
__device__ bf16  g_zclo[BB*ZH];
__device__ f16   g_emfh[BB*HH];
__device__ f16   g_emfl[BB*HH];
__device__ float g_embW0[BB*G4];
__device__ float g_bias[LL*G4];
__device__ float g_part[4*BB*HH];
__device__ float g_trendh[BB*HH];
__device__ float g_trend[BB*TT*VV];
__device__ unsigned g_count;
__device__ volatile unsigned g_gen;
// init-path weights (bf16 3-term split)
__device__ bf16 g_fcW_h[3072*ZH], g_fcW_l[3072*ZH];
__device__ bf16 g_tr1_h[HH*ZH],  g_tr1_l[HH*ZH];
// loop-path weights (single f16, [Nperm, Kpad])
__device__ f16 g_w0b[G4*HH];
__device__ f16 g_w0t[G4*64];
__device__ f16 g_whh[LL*G4*HH];
__device__ f16 g_wih[2*G4*HH];
__device__ f16 g_o1[HH*HH];

__device__ __forceinline__ float fsigmoid(float x){ return __fdividef(1.0f,1.0f+__expf(-x)); }
__device__ __forceinline__ float ftanh(float x){
    x = fminf(fmaxf(x,-15.0f),15.0f);
    float e = __expf(2.0f*x);
    return (e-1.0f)*__fdividef(1.0f,e+1.0f);
}
__device__ __forceinline__ uint32_t smem_u32(const void* p){
    uint32_t r;
    asm("{ .reg .u64 t; cvta.to.shared.u64 t, %1; cvt.u32.u64 %0, t; }" : "=r"(r) : "l"(p));
    return r;
}
__device__ __forceinline__ void cp16(uint32_t s, const void* g){
    asm volatile("cp.async.cg.shared.global [%0], [%1], 16;" :: "r"(s), "l"(g) : "memory");
}
__device__ __forceinline__ void ldsm4(uint32_t* r, uint32_t a){
    asm volatile("ldmatrix.sync.aligned.m8n8.x4.shared.b16 {%0,%1,%2,%3}, [%4];"
        : "=r"(r[0]),"=r"(r[1]),"=r"(r[2]),"=r"(r[3]) : "r"(a));
}
__device__ __forceinline__ void mma_bf(float* d, const uint32_t* a, uint32_t b0, uint32_t b1){
    asm volatile("mma.sync.aligned.m16n8k16.row.col.f32.bf16.bf16.f32 "
        "{%0,%1,%2,%3}, {%4,%5,%6,%7}, {%8,%9}, {%0,%1,%2,%3};"
        : "+f"(d[0]),"+f"(d[1]),"+f"(d[2]),"+f"(d[3])
        : "r"(a[0]),"r"(a[1]),"r"(a[2]),"r"(a[3]), "r"(b0),"r"(b1));
}
__device__ __forceinline__ void mma_hf(float* d, const uint32_t* a, uint32_t b0, uint32_t b1){
    asm volatile("mma.sync.aligned.m16n8k16.row.col.f32.f16.f16.f32 "
        "{%0,%1,%2,%3}, {%4,%5,%6,%7}, {%8,%9}, {%0,%1,%2,%3};"
        : "+f"(d[0]),"+f"(d[1]),"+f"(d[2]),"+f"(d[3])
        : "r"(a[0]),"r"(a[1]),"r"(a[2]),"r"(a[3]), "r"(b0),"r"(b1));
}

#define STAGE_B 36864
#define SMEM_INIT (3*STAGE_B)     // init path (3-term bf16)
#define SMEM_STEP (3*55296)       // step kernel (covers TERMS=2 embW0 phase)

__device__ __forceinline__ void gridbar(int tid){
    __syncthreads();
    __threadfence();
    if (tid == 0){
        unsigned old = g_gen;
        if (atomicAdd(&g_count, 1u) == 127u){
            g_count = 0;
            __threadfence();
            g_gen = old + 1u;
        } else {
            while (g_gen == old) __nanosleep(64);
        }
    }
    __syncthreads();
}

// ---- f16 GEMM phase: 128x128 tile, BK=64, TERMS = activation terms (1 or 2) ----
// EPI 0: plain store. EPI 3: fused LSTM cell (gate-interleaved cols).
template<int EPI, int TERMS>
__device__ __noinline__ void gemmT(
    uint8_t* smem, uint32_t sb, int tid, int m0, int n0,
    const f16* Ah0, const f16* Al0, int lda0, int klen0, int koff0, int kb0, const f16* B0,
    const f16* Ah1, const f16* Al1, int lda1, int klen1, int kb1, const f16* B1,
    float* C, int ldc, const float* bias, const float* embAdd,
    float* cbase, f16* h_out)
{
    constexpr int ST = (TERMS == 2) ? 55296 : 36864;
    constexpr int BOFF = (TERMS == 2) ? 36864 : 18432;
    const int wid = tid >> 5, lane = tid & 31;
    const int total = kb0 + kb1;

    float acc[2][4][4];
    #pragma unroll
    for (int mt = 0; mt < 2; mt++)
        #pragma unroll
        for (int nt = 0; nt < 4; nt++)
            #pragma unroll
            for (int i = 0; i < 4; i++) acc[mt][nt][i] = 0.0f;

    const int warpM = (wid & 3) * 32, warpN = (wid >> 2) * 32;
    const uint32_t aoff = (uint32_t)((lane & 15)*144 + (lane >> 4)*16);
    const uint32_t boff = (uint32_t)((lane & 7)*144 + ((lane >> 3) & 1)*16 + (lane >> 4)*1152);

    auto issue = [&](int c, int s){
        const f16 *Ah, *Al, *Bp; int lda, klen, koff;
        if (c < kb0) { koff = koff0 + (c << 6); Ah = Ah0; Al = Al0; Bp = B0; lda = lda0; klen = klen0; }
        else { const int cc = c - kb0; koff = cc << 6; Ah = Ah1; Al = Al1; Bp = B1; lda = lda1; klen = klen1; }
        const uint32_t s0 = sb + s*ST;
        #pragma unroll
        for (int i = 0; i < 2*(TERMS + 1); i++) {
            const int li = tid + i*512;
            const int tile = li >> 10, w = li & 1023;
            const int r = w >> 3, c16 = w & 7;
            const f16* src;
            if (tile == 0)                      src = Ah + (m0 + r)*lda + koff + c16*8;
            else if (TERMS == 2 && tile == 1)   src = Al + (m0 + r)*lda + koff + c16*8;
            else                                src = Bp + (n0 + r)*klen + koff + c16*8;
            cp16(s0 + tile*18432 + r*144 + c16*16, src);
        }
        asm volatile("cp.async.commit_group;" ::: "memory");
    };
    auto compute = [&](int s){
        const uint32_t sAh = sb + s*ST + warpM*144;
        const uint32_t sAl = sAh + 18432;
        const uint32_t sB  = sb + s*ST + BOFF + warpN*144;
        #pragma unroll
        for (int ks = 0; ks < 4; ks++) {
            uint32_t bfr[2][4], ah[2][4], al[2][4];
            #pragma unroll
            for (int np = 0; np < 2; np++) ldsm4(bfr[np], sB + np*2304 + ks*32 + boff);
            #pragma unroll
            for (int mt = 0; mt < 2; mt++) {
                ldsm4(ah[mt], sAh + mt*2304 + ks*32 + aoff);
                if (TERMS == 2) ldsm4(al[mt], sAl + mt*2304 + ks*32 + aoff);
            }
            #pragma unroll
            for (int mt = 0; mt < 2; mt++)
                #pragma unroll
                for (int nt = 0; nt < 4; nt++) {
                    mma_hf(acc[mt][nt], ah[mt], bfr[nt>>1][(nt&1)*2], bfr[nt>>1][(nt&1)*2+1]);
                    if (TERMS == 2)
                        mma_hf(acc[mt][nt], al[mt], bfr[nt>>1][(nt&1)*2], bfr[nt>>1][(nt&1)*2+1]);
                }
        }
    };

    issue(0, 0);
    issue(1, 1);
    for (int c = 0; c < total; c++) {
        if (c + 1 < total) asm volatile("cp.async.wait_group 1;" ::: "memory");
        else               asm volatile("cp.async.wait_group 0;" ::: "memory");
        __syncthreads();
        compute(c % 3);
        if (c + 2 < total) issue(c + 2, (c + 2) % 3);
    }
    __syncthreads();

    if (EPI == 3) {
        #pragma unroll
        for (int mt = 0; mt < 2; mt++) {
            const int row = m0 + warpM + mt*16 + (lane >> 2) + ((lane & 1) ? 8 : 0);
            #pragma unroll
            for (int nt = 0; nt < 4; nt++) {
                const float d0 = acc[mt][nt][0], d1 = acc[mt][nt][1];
                const float d2 = acc[mt][nt][2], d3 = acc[mt][nt][3];
                const float e0 = __shfl_xor_sync(0xffffffffu, d0, 1);
                const float e1 = __shfl_xor_sync(0xffffffffu, d1, 1);
                const float e2 = __shfl_xor_sync(0xffffffffu, d2, 1);
                const float e3 = __shfl_xor_sync(0xffffffffu, d3, 1);
                float q0, q1, q2, q3;
                if (lane & 1) { q0 = e2; q1 = e3; q2 = d2; q3 = d3; }
                else          { q0 = d0; q1 = d1; q2 = e0; q3 = e1; }
                const int qb = n0 + warpN + nt*8 + ((lane & 3) >> 1)*4;
                const int nh = qb >> 2;
                float4 bb = *reinterpret_cast<const float4*>(&bias[qb]);
                float gi = q0 + bb.x, gf = q1 + bb.y, gg = q2 + bb.z, go = q3 + bb.w;
                if (embAdd) {
                    float4 e = *reinterpret_cast<const float4*>(&embAdd[row*G4 + qb]);
                    gi += e.x; gf += e.y; gg += e.z; go += e.w;
                }
                const int ci = row*HH + nh;
                const float cn = fsigmoid(gf)*cbase[ci] + fsigmoid(gi)*ftanh(gg);
                cbase[ci] = cn;
                h_out[ci] = __float2half(fsigmoid(go)*ftanh(cn));
            }
        }
    } else {
        #pragma unroll
        for (int mt = 0; mt < 2; mt++) {
            #pragma unroll
            for (int nt = 0; nt < 4; nt++) {
                const int row = m0 + warpM + mt*16 + (lane >> 2);
                const int col = n0 + warpN + nt*8 + (lane & 3)*2;
                *reinterpret_cast<float2*>(&C[row*ldc + col]) =
                    make_float2(acc[mt][nt][0], acc[mt][nt][1]);
                *reinterpret_cast<float2*>(&C[(row+8)*ldc + col]) =
                    make_float2(acc[mt][nt][2], acc[mt][nt][3]);
            }
        }
    }
}

// ---- persistent kernel: embW0 + 60 steps, 128 CTAs ----
__global__ void __launch_bounds__(512) step_kernel(
    const float* __restrict__ out1_b, const float* __restrict__ W2,
    const float* __restrict__ b2, float* __restrict__ out)
{
    extern __shared__ __align__(128) uint8_t smem[];
    const uint32_t sb = smem_u32(smem);
    const int tid = threadIdx.x;
    const int cta = blockIdx.x;
    const int gm = (cta & 7) * 128;
    const int gn = (cta >> 3) * 128;
    const int o1slice = cta & 3;
    const int o1n = ((cta >> 2) & 3) * 128;
    const int o1m = (cta >> 4) * 128;

    // once: embW0 = emb @ Wih0[9:,:]  (2-term for accuracy; one-time cost)
    gemmT<0, 2>(smem, sb, tid, gm, gn,
        g_emfh, g_emfl, HH, HH, 0, 8, g_w0b,
        nullptr, nullptr, 0, 0, 0, nullptr,
        g_embW0, G4, nullptr, nullptr, nullptr, nullptr);
    gridbar(tid);

    for (int t = 0; t < TT; t++) {
        const int p = t & 1, q = p ^ 1;
        const f16* hp = g_h + p*(LL*BH);
        f16* hq = g_h + q*(LL*BH);

        // L0: h0(p)@Whh0 + prev@W0t, fused cell -> h0(q)
        gemmT<3, 1>(smem, sb, tid, gm, gn,
            hp, nullptr, HH, HH, 0, 8, g_whh,
            g_prev, nullptr, 64, 64, 1, g_w0t,
            nullptr, 0, g_bias, g_embW0, g_c, hq);
        gridbar(tid);
        // L1
        gemmT<3, 1>(smem, sb, tid, gm, gn,
            hq, nullptr, HH, HH, 0, 8, g_wih,
            hp + BH, nullptr, HH, HH, 8, g_whh + G4*HH,
            nullptr, 0, g_bias + G4, nullptr, g_c + BH, hq + BH);
        gridbar(tid);
        // L2
        gemmT<3, 1>(smem, sb, tid, gm, gn,
            hq + BH, nullptr, HH, HH, 0, 8, g_wih + G4*HH,
            hp + 2*BH, nullptr, HH, HH, 8, g_whh + 2*G4*HH,
            nullptr, 0, g_bias + 2*G4, nullptr, g_c + 2*BH, hq + 2*BH);
        gridbar(tid);
        // out1 split-K partial
        gemmT<0, 1>(smem, sb, tid, o1m, o1n,
            hq + 2*BH, nullptr, HH, HH, o1slice*128, 2, g_o1,
            nullptr, nullptr, 0, 0, 0, nullptr,
            g_part + o1slice*(BB*HH), HH, nullptr, nullptr, nullptr, nullptr);
        gridbar(tid);
        // out2
        {
            float* hid = reinterpret_cast<float*>(smem);
            const int rbase = cta * 8;
            #pragma unroll
            for (int i = 0; i < 8; i++) {
                const int e = tid + i*512;
                const int rl = e >> 9, k = e & 511;
                const int gi = (rbase + rl)*HH + k;
                float v = g_part[gi] + g_part[BB*HH + gi]
                        + g_part[2*BB*HH + gi] + g_part[3*BB*HH + gi] + out1_b[k];
                hid[e] = (v > 0.0f) ? v : 0.2f*v;
            }
            __syncthreads();
            const int wid = tid >> 5, lane = tid & 31;
            for (int task = wid; task < 72; task += 16) {
                const int rl = task / 9, w = task - rl*9;
                const float* hrow = hid + rl*512;
                float s = 0.0f;
                #pragma unroll
                for (int k = lane; k < HH; k += 32) s += hrow[k]*W2[k*VV + w];
                #pragma unroll
                for (int off = 16; off; off >>= 1) s += __shfl_down_sync(0xffffffffu, s, off);
                if (lane == 0) {
                    const int b = rbase + rl;
                    const float o = s + b2[w] + g_trend[b*(TT*VV) + t*VV + w];
                    out[b*(TT*VV) + t*VV + w] = o;
                    g_prev[b*64 + w] = __float2half(o);
                }
            }
        }
        gridbar(tid);
    }
}

// ---- one-time init GEMM (3-term bf16; EPI 1 bias+leaky, 2 init-scatter) ----
template<int EPI>
__global__ void __launch_bounds__(512)
gemm_init(const bf16* __restrict__ Ah0, const bf16* __restrict__ Al0, int lda0, int k0len,
          const bf16* __restrict__ Bh0, const bf16* __restrict__ Bl0,
          float* __restrict__ C, int ldc, const float* __restrict__ bias)
{
    extern __shared__ __align__(128) uint8_t smem[];
    const uint32_t sb = smem_u32(smem);
    const int tid = threadIdx.x, wid = tid >> 5, lane = tid & 31;
    const int m0 = blockIdx.x * 128, n0 = blockIdx.y * 128;
    const int kb0 = k0len >> 6, total = 3*kb0;

    float acc[2][4][4];
    #pragma unroll
    for (int mt = 0; mt < 2; mt++)
        #pragma unroll
        for (int nt = 0; nt < 4; nt++)
            #pragma unroll
            for (int i = 0; i < 4; i++) acc[mt][nt][i] = 0.0f;

    const int warpM = (wid & 3) * 32, warpN = (wid >> 2) * 32;
    const uint32_t aoff = (uint32_t)((lane & 15)*144 + (lane >> 4)*16);
    const uint32_t boff = (uint32_t)((lane & 7)*144 + ((lane >> 3) & 1)*16 + (lane >> 4)*1152);

    auto issue = [&](int c, int s){
        const int term = c / kb0, koff = (c - term*kb0) << 6;
        const bf16* Ap = (term == 2) ? Al0 : Ah0;
        const bf16* Bp = (term == 1) ? Bl0 : Bh0;
        const uint32_t sA = sb + s*STAGE_B, sB = sA + 18432;
        #pragma unroll
        for (int i = 0; i < 2; i++) {
            const int li = tid + i*512, r = li >> 3, c16 = li & 7;
            cp16(sA + r*144 + c16*16, Ap + (m0 + r)*lda0 + koff + c16*8);
            cp16(sB + r*144 + c16*16, Bp + (n0 + r)*k0len + koff + c16*8);
        }
        asm volatile("cp.async.commit_group;" ::: "memory");
    };
    issue(0, 0);
    issue(1, 1);
    for (int c = 0; c < total; c++) {
        if (c + 1 < total) asm volatile("cp.async.wait_group 1;" ::: "memory");
        else               asm volatile("cp.async.wait_group 0;" ::: "memory");
        __syncthreads();
        {
            const int s = c % 3;
            const uint32_t sA = sb + s*STAGE_B + warpM*144;
            const uint32_t sB = sb + s*STAGE_B + 18432 + warpN*144;
            #pragma unroll
            for (int ks = 0; ks < 4; ks++) {
                uint32_t af[2][4], bfr[2][4];
                #pragma unroll
                for (int mt = 0; mt < 2; mt++) ldsm4(af[mt], sA + mt*2304 + ks*32 + aoff);
                #pragma unroll
                for (int np = 0; np < 2; np++) ldsm4(bfr[np], sB + np*2304 + ks*32 + boff);
                #pragma unroll
                for (int mt = 0; mt < 2; mt++)
                    #pragma unroll
                    for (int nt = 0; nt < 4; nt++)
                        mma_bf(acc[mt][nt], af[mt], bfr[nt>>1][(nt&1)*2], bfr[nt>>1][(nt&1)*2+1]);
            }
        }
        if (c + 2 < total) issue(c + 2, (c + 2) % 3);
    }

    #pragma unroll
    for (int mt = 0; mt < 2; mt++) {
        #pragma unroll
        for (int nt = 0; nt < 4; nt++) {
            const int row = m0 + warpM + mt*16 + (lane >> 2);
            const int col = n0 + warpN + nt*8 + (lane & 3)*2;
            #pragma unroll
            for (int hrow = 0; hrow < 2; hrow++) {
                const int r = row + hrow*8;
                float a = hrow ? acc[mt][nt][2] : acc[mt][nt][0];
                float b = hrow ? acc[mt][nt][3] : acc[mt][nt][1];
                if (EPI == 1) {
                    a += bias[col];   a = (a > 0.0f) ? a : 0.2f*a;
                    b += bias[col+1]; b = (b > 0.0f) ? b : 0.2f*b;
                    *reinterpret_cast<float2*>(&C[r*ldc + col]) = make_float2(a, b);
                } else {
                    a += bias[col]; b += bias[col+1];
                    const int l = col >> 10, rem = col & 1023, sel = rem >> 9, hh2 = rem & 511;
                    const int di = l*BH + r*HH + hh2;
                    if (sel) {
                        *reinterpret_cast<float2*>(&g_c[di]) = make_float2(a, b);
                    } else {
                        g_h[di]   = __float2half(a);
                        g_h[di+1] = __float2half(b);
                    }
                }
            }
        }
    }
}

// ---- merged transpose+split: fmt 0 = bf16 hi/lo pair, 1 = single f16 ----
struct CsJob { const float* W; void* Th; void* Tl; int K, Kpad, N, gx, blk0, perm, fmt; };
struct CsJobs { CsJob j[10]; };

__global__ void convsplit_all(CsJobs jobs)
{
    __shared__ float tile[32][33];
    const int b = blockIdx.x;
    int ji = 0;
    #pragma unroll
    for (int i = 1; i < 10; i++) if (b >= jobs.j[i].blk0) ji = i;
    const CsJob jb = jobs.j[ji];
    const int local = b - jb.blk0;
    const int k0 = (local % jb.gx) * 32;
    const int n0 = (local / jb.gx) * 32;
    const int tx = threadIdx.x, ty = threadIdx.y;
    for (int i = ty; i < 32; i += 8) {
        const int k = k0+i, n = n0+tx;
        tile[i][tx] = (k < jb.K && n < jb.N) ? jb.W[k*jb.N + n] : 0.0f;
    }
    __syncthreads();
    for (int i = ty; i < 32; i += 8) {
        const int n = n0+i, k = k0+tx;
        if (n < jb.N && k < jb.Kpad) {
            const float v = tile[tx][i];
            const int np = jb.perm ? ((n & 511)*4 + (n >> 9)) : n;
            if (jb.fmt == 0) {
                const bf16 h = __float2bfloat16(v);
                ((bf16*)jb.Th)[np*jb.Kpad + k] = h;
                ((bf16*)jb.Tl)[np*jb.Kpad + k] = __float2bfloat16(v - __bfloat162float(h));
            } else {
                ((f16*)jb.Th)[np*jb.Kpad + k] = __float2half(v);
            }
        }
    }
}

// ---- prep ----
__global__ void prep_kernel(const float* __restrict__ z, const int* __restrict__ scen,
                            const float* __restrict__ embed,
                            const float* b0a, const float* b0b,
                            const float* b1a, const float* b1b,
                            const float* b2a, const float* b2b)
{
    const int idx = blockIdx.x*blockDim.x + threadIdx.x;
    if (idx < BB*ZH) {
        const int b = idx / ZH, j = idx - b*ZH;
        const float v = (j < ZZ) ? z[b*ZZ + j] : embed[scen[b]*HH + (j - ZZ)];
        const bf16 h = __float2bfloat16(v);
        g_zchi[idx] = h;
        g_zclo[idx] = __float2bfloat16(v - __bfloat162float(h));
        if (j >= ZZ) {
            const int ei = b*HH + (j - ZZ);
            const f16 fh = __float2half(v);
            g_emfh[ei] = fh;
            g_emfl[ei] = __float2half(v - __half2float(fh));
        }
    }
    if (idx < BB*64) g_prev[idx] = __float2half(0.0f);
    if (idx < LL*G4) {
        const int l = idx >> 11, n = idx & 2047;
        const float s = (l == 0) ? b0a[n]+b0b[n] : (l == 1) ? b1a[n]+b1b[n] : b2a[n]+b2b[n];
        const int np = (n & 511)*4 + (n >> 9);
        g_bias[l*G4 + np] = s;
    }
}

// ---- one-time fp32 GEMM (trend2) ----
__global__ void __launch_bounds__(256)
gemm32_kernel(const float* __restrict__ A, const float* __restrict__ W,
              int N, int K, const float* __restrict__ bias, float* __restrict__ C)
{
    __shared__ float As[16][65];
    __shared__ float Ws[16][64];
    const int tid = threadIdx.x, tx = tid & 15, ty = tid >> 4;
    const int row0 = blockIdx.x*64, col0 = blockIdx.y*64;
    const int ar = tid >> 2, ak = (tid & 3)*4, wk = tid >> 4, wn = (tid & 15)*4;
    float acc[4][4];
    #pragma unroll
    for (int m = 0; m < 4; m++) { acc[m][0]=acc[m][1]=acc[m][2]=acc[m][3]=0.0f; }
    for (int k0 = 0; k0 < K; k0 += 16) {
        float4 av = *reinterpret_cast<const float4*>(&A[(row0+ar)*K + k0 + ak]);
        As[ak+0][ar]=av.x; As[ak+1][ar]=av.y; As[ak+2][ar]=av.z; As[ak+3][ar]=av.w;
        const int wcol = col0 + wn;
        #pragma unroll
        for (int j = 0; j < 4; j++)
            Ws[wk][wn+j] = (wcol+j < N) ? W[(k0+wk)*N + wcol + j] : 0.0f;
        __syncthreads();
        #pragma unroll
        for (int kk = 0; kk < 16; kk++) {
            float a[4];
            #pragma unroll
            for (int m = 0; m < 4; m++) a[m] = As[kk][ty*4+m];
            #pragma unroll
            for (int m = 0; m < 4; m++)
                #pragma unroll
                for (int n = 0; n < 4; n++) acc[m][n] += a[m]*Ws[kk][tx*4+n];
        }
        __syncthreads();
    }
    #pragma unroll
    for (int m = 0; m < 4; m++) {
        const int row = row0 + ty*4 + m;
        #pragma unroll
        for (int n = 0; n < 4; n++) {
            const int col = col0 + tx*4 + n;
            if (col < N) C[row*N + col] = acc[m][n] + bias[col];
        }
    }
}

extern "C" void kernel_launch(void* const* d_in, const int* in_sizes, int n_in,
                              void* d_out, int out_size)
{
    (void)in_sizes; (void)n_in; (void)out_size;
    const float* z     = (const float*)d_in[0];
    const int*   scen  = (const int*)  d_in[1];
    const float* embed = (const float*)d_in[2];
    const float* fcW   = (const float*)d_in[3];
    const float* fcb   = (const float*)d_in[4];
    const float* Wih[LL], *Whh[LL], *bih[LL], *bhh[LL];
    for (int l = 0; l < LL; l++) {
        Wih[l] = (const float*)d_in[5+4*l];  Whh[l] = (const float*)d_in[6+4*l];
        bih[l] = (const float*)d_in[7+4*l];  bhh[l] = (const float*)d_in[8+4*l];
    }
    const float* out1_W = (const float*)d_in[17];
    const float* out1_b = (const float*)d_in[18];
    const float* out2_W = (const float*)d_in[19];
    const float* out2_b = (const float*)d_in[20];
    const float* tr1_W  = (const float*)d_in[21];
    const float* tr1_b  = (const float*)d_in[22];
    const float* tr2_W  = (const float*)d_in[23];
    const float* tr2_b  = (const float*)d_in[24];
    float* out = (float*)d_out;

    cudaFuncSetAttribute(gemm_init<1>, cudaFuncAttributeMaxDynamicSharedMemorySize, SMEM_INIT);
    cudaFuncSetAttribute(gemm_init<2>, cudaFuncAttributeMaxDynamicSharedMemorySize, SMEM_INIT);
    cudaFuncSetAttribute(step_kernel,  cudaFuncAttributeMaxDynamicSharedMemorySize, SMEM_STEP);

    bf16 *p_zchi,*p_zclo,*p_fcWh,*p_fcWl,*p_tr1h,*p_tr1l;
    f16  *p_w0b,*p_w0t,*p_whh,*p_wih,*p_o1;
    float *p_trendh,*p_trend;
    cudaGetSymbolAddress((void**)&p_zchi, g_zchi);   cudaGetSymbolAddress((void**)&p_zclo, g_zclo);
    cudaGetSymbolAddress((void**)&p_fcWh, g_fcW_h);  cudaGetSymbolAddress((void**)&p_fcWl, g_fcW_l);
    cudaGetSymbolAddress((void**)&p_tr1h, g_tr1_h);  cudaGetSymbolAddress((void**)&p_tr1l, g_tr1_l);
    cudaGetSymbolAddress((void**)&p_w0b,  g_w0b);    cudaGetSymbolAddress((void**)&p_w0t,  g_w0t);
    cudaGetSymbolAddress((void**)&p_whh,  g_whh);    cudaGetSymbolAddress((void**)&p_wih,  g_wih);
    cudaGetSymbolAddress((void**)&p_o1,   g_o1);
    cudaGetSymbolAddress((void**)&p_trendh,g_trendh); cudaGetSymbolAddress((void**)&p_trend, g_trend);

    CsJobs jobs;
    int blk = 0;
    auto addjob = [&](int i, const float* W, void* Th, void* Tl, int K, int Kpad, int N, int perm, int fmt){
        const int gx = (Kpad + 31)/32, gy = (N + 31)/32;
        jobs.j[i] = CsJob{W, Th, Tl, K, Kpad, N, gx, blk, perm, fmt};
        blk += gx*gy;
    };
    addjob(0, fcW,            p_fcWh, p_fcWl, ZH, ZH, 3072, 0, 0);
    addjob(1, tr1_W,          p_tr1h, p_tr1l, ZH, ZH, HH,   0, 0);
    addjob(2, Wih[0] + VV*G4, p_w0b,  nullptr, HH, HH, G4,  1, 1);
    addjob(3, Wih[0],         p_w0t,  nullptr, VV, 64, G4,  1, 1);
    addjob(4, Whh[0],         p_whh,             nullptr, HH, HH, G4, 1, 1);
    addjob(5, Whh[1],         p_whh + G4*HH,     nullptr, HH, HH, G4, 1, 1);
    addjob(6, Whh[2],         p_whh + 2*G4*HH,   nullptr, HH, HH, G4, 1, 1);
    addjob(7, Wih[1],         p_wih,             nullptr, HH, HH, G4, 1, 1);
    addjob(8, Wih[2],         p_wih + G4*HH,     nullptr, HH, HH, G4, 1, 1);
    addjob(9, out1_W,         p_o1,   nullptr, HH, HH, HH,  0, 1);

    convsplit_all<<<blk, dim3(32, 8)>>>(jobs);
    prep_kernel<<<(BB*ZH + 255)/256, 256>>>(z, scen, embed,
        bih[0], bhh[0], bih[1], bhh[1], bih[2], bhh[2]);
    gemm_init<2><<<dim3(8,24), 512, SMEM_INIT>>>(
        p_zchi, p_zclo, ZH, ZH, p_fcWh, p_fcWl, nullptr, 0, fcb);
    gemm_init<1><<<dim3(8,4), 512, SMEM_INIT>>>(
        p_zchi, p_zclo, ZH, ZH, p_tr1h, p_tr1l, p_trendh, HH, tr1_b);
    gemm32_kernel<<<dim3(16,9), 256>>>(p_trendh, tr2_W, TT*VV, HH, tr2_b, p_trend);
    step_kernel<<<128, 512, SMEM_STEP>>>(out1_b, out2_W, out2_b, out);
}